// round 6
// baseline (speedup 1.0000x reference)
#include <cuda_runtime.h>
#include <math.h>
#include <stdint.h>

#define NN   50000
#define NE   800000
#define ET   (NE + NN)     // edges + self loops
#define FIN  42
#define HIDD 128
#define SCB  ((NN + 255) / 256)   // 196 scan blocks

// ---------------- scratch (device globals; no allocation allowed) -------------
__device__ float g_xn [NN * FIN];
__device__ float g_h  [NN * HIDD];
__device__ float g_cur[NN * HIDD];
__device__ float g_hs [NN];
__device__ float g_hd [NN];
__device__ int   g_deg [NN];      // zero at start of every launch (BSS init + k_off reset)
__device__ int   g_off [NN + 1];
__device__ int   g_fill[NN];
__device__ int   g_csr [ET];
__device__ int   g_boff[256];

// ---------------- L1 normalize input ----------------
__global__ void k_xn(const float* __restrict__ x) {
    int w = (blockIdx.x * blockDim.x + threadIdx.x) >> 5;
    int lane = threadIdx.x & 31;
    if (w >= NN) return;
    float s = 0.f;
    for (int j = lane; j < FIN; j += 32) s += fabsf(x[w * FIN + j]);
    #pragma unroll
    for (int o = 16; o; o >>= 1) s += __shfl_xor_sync(0xffffffff, s, o);
    float inv = 1.f / fmaxf(s, 1e-12f);
    for (int j = lane; j < FIN; j += 32) g_xn[w * FIN + j] = x[w * FIN + j] * inv;
}

// ---------------- CSR build (by destination) ----------------
__global__ void k_count(const int* __restrict__ ei) {
    int e = blockIdx.x * blockDim.x + threadIdx.x;
    if (e >= ET) return;
    int dst = (e < NE) ? ei[NE + e] : (e - NE);
    atomicAdd(&g_deg[dst], 1);
}

__global__ void k_part() {
    __shared__ int wsum[8];
    int t = threadIdx.x, b = blockIdx.x;
    int node = b * 256 + t;
    int v = (node < NN) ? g_deg[node] : 0;
    #pragma unroll
    for (int o = 16; o; o >>= 1) v += __shfl_xor_sync(0xffffffff, v, o);
    if ((t & 31) == 0) wsum[t >> 5] = v;
    __syncthreads();
    if (t == 0) {
        int s = 0;
        #pragma unroll
        for (int i = 0; i < 8; i++) s += wsum[i];
        g_boff[b] = s;
    }
}

__global__ void k_scanb() {
    __shared__ int sh[256];
    int t = threadIdx.x;
    int v = (t < SCB) ? g_boff[t] : 0;
    sh[t] = v;
    __syncthreads();
    #pragma unroll
    for (int o = 1; o < 256; o <<= 1) {
        int u = (t >= o) ? sh[t - o] : 0;
        __syncthreads();
        sh[t] += u;
        __syncthreads();
    }
    if (t < SCB) g_boff[t] = sh[t] - v;
    if (t == 255) g_off[NN] = sh[255];
}

__global__ void k_off() {
    __shared__ int sh[256];
    int t = threadIdx.x, b = blockIdx.x;
    int node = b * 256 + t;
    int d = (node < NN) ? g_deg[node] : 0;
    sh[t] = d;
    __syncthreads();
    #pragma unroll
    for (int o = 1; o < 256; o <<= 1) {
        int u = (t >= o) ? sh[t - o] : 0;
        __syncthreads();
        sh[t] += u;
        __syncthreads();
    }
    if (node < NN) {
        int off = g_boff[b] + sh[t] - d;
        g_off[node] = off;
        g_fill[node] = off;
        g_deg[node] = 0;          // reset for the next kernel_launch call
    }
}

__global__ void k_scatter(const int* __restrict__ ei) {
    int e = blockIdx.x * blockDim.x + threadIdx.x;
    if (e >= ET) return;
    int src, dst;
    if (e < NE) { src = ei[e]; dst = ei[NE + e]; }
    else        { src = e - NE; dst = e - NE; }
    int pos = atomicAdd(&g_fill[dst], 1);
    g_csr[pos] = src;
}

// ---------------- tf32 tensor-core GEMM with fused dot epilogue ---------------
__device__ __forceinline__ uint32_t f2tf(float f) {
    uint32_t u; asm("cvt.rna.tf32.f32 %0, %1;" : "=r"(u) : "f"(f)); return u;
}
__device__ __forceinline__ void mma_tf32(float c[4],
    uint32_t a0, uint32_t a1, uint32_t a2, uint32_t a3,
    uint32_t b0, uint32_t b1)
{
    asm volatile(
        "mma.sync.aligned.m16n8k8.row.col.f32.tf32.tf32.f32 "
        "{%0,%1,%2,%3}, {%4,%5,%6,%7}, {%8,%9}, {%0,%1,%2,%3};"
        : "+f"(c[0]), "+f"(c[1]), "+f"(c[2]), "+f"(c[3])
        : "r"(a0), "r"(a1), "r"(a2), "r"(a3), "r"(b0), "r"(b1));
}

#define ASTR 36
#define BSTR 136
__global__ void __launch_bounds__(256) k_tgemm(
    const float* __restrict__ A, const float* __restrict__ B,
    float* __restrict__ C,
    const float* __restrict__ as_, const float* __restrict__ ad_,
    int M, int N, int K)
{
    __shared__ uint32_t As[128 * ASTR];
    __shared__ uint32_t Bs[32 * BSTR];
    __shared__ float sa[128], sd[128], sdot[128], ddot[128];
    int tid = threadIdx.x;
    int lane = tid & 31, wid = tid >> 5;
    int wm = wid & 3, wn = wid >> 2;     // warp tile: rows wm*32, cols wn*64
    int row0 = blockIdx.x * 128;
    if (tid < 128) {
        sa[tid] = (tid < N) ? as_[tid] : 0.f;
        sd[tid] = (tid < N) ? ad_[tid] : 0.f;
        sdot[tid] = 0.f; ddot[tid] = 0.f;
    }
    float acc[2][8][4];
    #pragma unroll
    for (int i = 0; i < 2; i++)
        #pragma unroll
        for (int j = 0; j < 8; j++)
            #pragma unroll
            for (int r = 0; r < 4; r++) acc[i][j][r] = 0.f;

    for (int k0 = 0; k0 < K; k0 += 32) {
        // ---- stage A chunk [128 x 32] ----
        if ((K & 3) == 0) {
            #pragma unroll
            for (int l = 0; l < 4; l++) {
                int slot = tid + l * 256;         // 0..1023
                int r = slot >> 3, kg = slot & 7;
                int gr = row0 + r;
                float4 v = make_float4(0.f, 0.f, 0.f, 0.f);
                if (gr < M) v = *(const float4*)&A[(long)gr * K + k0 + kg * 4];
                uint32_t* dst = &As[r * ASTR + kg * 4];
                dst[0] = f2tf(v.x); dst[1] = f2tf(v.y);
                dst[2] = f2tf(v.z); dst[3] = f2tf(v.w);
            }
        } else {
            #pragma unroll
            for (int l = 0; l < 16; l++) {
                int slot = tid + l * 256;         // 0..4095
                int r = slot >> 5, k = slot & 31;
                int gr = row0 + r, gk = k0 + k;
                float v = (gr < M && gk < K) ? A[(long)gr * K + gk] : 0.f;
                As[r * ASTR + k] = f2tf(v);
            }
        }
        // ---- stage B chunk [32 x 128] (zero-padded to 128 cols) ----
        if ((N & 3) == 0) {
            #pragma unroll
            for (int l = 0; l < 4; l++) {
                int slot = tid + l * 256;
                int k = slot >> 5, ng = slot & 31;
                int gk = k0 + k;
                float4 v = make_float4(0.f, 0.f, 0.f, 0.f);
                if (gk < K) v = *(const float4*)&B[(long)gk * N + ng * 4];
                uint32_t* dst = &Bs[k * BSTR + ng * 4];
                dst[0] = f2tf(v.x); dst[1] = f2tf(v.y);
                dst[2] = f2tf(v.z); dst[3] = f2tf(v.w);
            }
        } else {
            #pragma unroll
            for (int l = 0; l < 16; l++) {
                int slot = tid + l * 256;
                int k = slot >> 7, n = slot & 127;
                int gk = k0 + k;
                float v = (gk < K && n < N) ? B[(long)gk * N + n] : 0.f;
                Bs[k * BSTR + n] = f2tf(v);
            }
        }
        __syncthreads();
        // ---- mma over 4 k8-steps ----
        #pragma unroll
        for (int ks = 0; ks < 4; ks++) {
            int kb = ks * 8;
            uint32_t a[2][4];
            #pragma unroll
            for (int fm = 0; fm < 2; fm++) {
                int r = wm * 32 + fm * 16 + (lane >> 2);
                a[fm][0] = As[r * ASTR + kb + (lane & 3)];
                a[fm][1] = As[(r + 8) * ASTR + kb + (lane & 3)];
                a[fm][2] = As[r * ASTR + kb + (lane & 3) + 4];
                a[fm][3] = As[(r + 8) * ASTR + kb + (lane & 3) + 4];
            }
            #pragma unroll
            for (int fn = 0; fn < 8; fn++) {
                int n = wn * 64 + fn * 8 + (lane >> 2);
                uint32_t b0 = Bs[(kb + (lane & 3)) * BSTR + n];
                uint32_t b1 = Bs[(kb + (lane & 3) + 4) * BSTR + n];
                mma_tf32(acc[0][fn], a[0][0], a[0][1], a[0][2], a[0][3], b0, b1);
                mma_tf32(acc[1][fn], a[1][0], a[1][1], a[1][2], a[1][3], b0, b1);
            }
        }
        __syncthreads();
    }

    // ---- epilogue: store C + fused a_s/a_d row dots ----
    #pragma unroll
    for (int fm = 0; fm < 2; fm++) {
        #pragma unroll
        for (int ro = 0; ro < 2; ro++) {
            int rl = wm * 32 + fm * 16 + (lane >> 2) + ro * 8;
            int r = row0 + rl;
            float s = 0.f, d = 0.f;
            #pragma unroll
            for (int fn = 0; fn < 8; fn++) {
                int c = wn * 64 + fn * 8 + (lane & 3) * 2;
                float v0 = acc[fm][fn][ro * 2 + 0];
                float v1 = acc[fm][fn][ro * 2 + 1];
                s += v0 * sa[c] + v1 * sa[c + 1];
                d += v0 * sd[c] + v1 * sd[c + 1];
                if (r < M) {
                    if (c + 1 < N) *(float2*)&C[(long)r * N + c] = make_float2(v0, v1);
                    else if (c < N) C[(long)r * N + c] = v0;
                }
            }
            s += __shfl_xor_sync(0xffffffff, s, 1);
            s += __shfl_xor_sync(0xffffffff, s, 2);
            d += __shfl_xor_sync(0xffffffff, d, 1);
            d += __shfl_xor_sync(0xffffffff, d, 2);
            if ((lane & 3) == 0 && r < M) {
                atomicAdd(&sdot[rl], s);
                atomicAdd(&ddot[rl], d);
            }
        }
    }
    __syncthreads();
    if (tid < 128 && row0 + tid < M) {
        g_hs[row0 + tid] = sdot[tid];
        g_hd[row0 + tid] = ddot[tid];
    }
}

// ------------- warp-per-node softmax aggregation (no barriers) ---------------
template<int F>
__global__ void __launch_bounds__(256) k_aggw(
    const float* __restrict__ h, const float* __restrict__ bias,
    float* __restrict__ out)
{
    int w = (blockIdx.x * blockDim.x + threadIdx.x) >> 5;
    int lane = threadIdx.x & 31;
    if (w >= NN) return;
    int beg = g_off[w], end = g_off[w + 1];
    int deg = end - beg;
    int nk = (deg + 31) >> 5;
    float hdv = g_hd[w];

    float cW[4]; int cS[4];
    float mymax = -INFINITY;
    for (int c = 0; c < nk; c++) {
        int i = (c << 5) + lane;
        float e = -INFINITY; int s = 0;
        if (i < deg) {
            s = g_csr[beg + i];
            float z = g_hs[s] + hdv;
            e = (z > 0.f) ? z : 0.2f * z;
        }
        if (c < 4) { cS[c] = s; cW[c] = e; }
        mymax = fmaxf(mymax, e);
    }
    #pragma unroll
    for (int o = 16; o; o >>= 1) mymax = fmaxf(mymax, __shfl_xor_sync(0xffffffff, mymax, o));
    float M = mymax;

    float myS = 0.f;
    for (int c = 0; c < nk; c++) {
        float e;
        if (c < 4) e = cW[c];
        else {
            int i = (c << 5) + lane;
            e = -INFINITY;
            if (i < deg) {
                float z = g_hs[g_csr[beg + i]] + hdv;
                e = (z > 0.f) ? z : 0.2f * z;
            }
        }
        float wgt = __expf(e - M);
        if (c < 4) cW[c] = wgt;
        myS += wgt;
    }
    #pragma unroll
    for (int o = 16; o; o >>= 1) myS += __shfl_xor_sync(0xffffffff, myS, o);
    float invS = 1.f / (myS + 1e-16f);

    if constexpr (F == 128) {
        const float4* h4 = (const float4*)h;
        float4 acc = make_float4(0.f, 0.f, 0.f, 0.f);
        for (int c = 0; c < nk; c++) {
            int cnt = min(32, deg - (c << 5));
            int s; float wgt;
            if (c < 4) { s = cS[c]; wgt = cW[c]; }
            else {
                int i = (c << 5) + lane;
                s = 0; wgt = 0.f;
                if (i < deg) {
                    s = g_csr[beg + i];
                    float z = g_hs[s] + hdv;
                    float e = (z > 0.f) ? z : 0.2f * z;
                    wgt = __expf(e - M);
                }
            }
            int k = 0;
            for (; k + 8 <= cnt; k += 8) {      // 8-way: deep L2 MLP
                int   s0 = __shfl_sync(0xffffffff, s, k);
                int   s1 = __shfl_sync(0xffffffff, s, k + 1);
                int   s2 = __shfl_sync(0xffffffff, s, k + 2);
                int   s3 = __shfl_sync(0xffffffff, s, k + 3);
                int   s4 = __shfl_sync(0xffffffff, s, k + 4);
                int   s5 = __shfl_sync(0xffffffff, s, k + 5);
                int   s6 = __shfl_sync(0xffffffff, s, k + 6);
                int   s7 = __shfl_sync(0xffffffff, s, k + 7);
                float w0 = __shfl_sync(0xffffffff, wgt, k);
                float w1 = __shfl_sync(0xffffffff, wgt, k + 1);
                float w2 = __shfl_sync(0xffffffff, wgt, k + 2);
                float w3 = __shfl_sync(0xffffffff, wgt, k + 3);
                float w4 = __shfl_sync(0xffffffff, wgt, k + 4);
                float w5 = __shfl_sync(0xffffffff, wgt, k + 5);
                float w6 = __shfl_sync(0xffffffff, wgt, k + 6);
                float w7 = __shfl_sync(0xffffffff, wgt, k + 7);
                float4 v0 = h4[s0 * 32 + lane];
                float4 v1 = h4[s1 * 32 + lane];
                float4 v2 = h4[s2 * 32 + lane];
                float4 v3 = h4[s3 * 32 + lane];
                float4 v4 = h4[s4 * 32 + lane];
                float4 v5 = h4[s5 * 32 + lane];
                float4 v6 = h4[s6 * 32 + lane];
                float4 v7 = h4[s7 * 32 + lane];
                acc.x += w0 * v0.x + w1 * v1.x + w2 * v2.x + w3 * v3.x
                       + w4 * v4.x + w5 * v5.x + w6 * v6.x + w7 * v7.x;
                acc.y += w0 * v0.y + w1 * v1.y + w2 * v2.y + w3 * v3.y
                       + w4 * v4.y + w5 * v5.y + w6 * v6.y + w7 * v7.y;
                acc.z += w0 * v0.z + w1 * v1.z + w2 * v2.z + w3 * v3.z
                       + w4 * v4.z + w5 * v5.z + w6 * v6.z + w7 * v7.z;
                acc.w += w0 * v0.w + w1 * v1.w + w2 * v2.w + w3 * v3.w
                       + w4 * v4.w + w5 * v5.w + w6 * v6.w + w7 * v7.w;
            }
            for (; k < cnt; k++) {
                int   sk = __shfl_sync(0xffffffff, s, k);
                float wk = __shfl_sync(0xffffffff, wgt, k);
                float4 v = h4[sk * 32 + lane];
                acc.x += wk * v.x; acc.y += wk * v.y;
                acc.z += wk * v.z; acc.w += wk * v.w;
            }
        }
        const float4* b4 = (const float4*)bias;
        float4 bb = b4[lane];
        float4 o;
        o.x = tanhf(acc.x * invS + bb.x);
        o.y = tanhf(acc.y * invS + bb.y);
        o.z = tanhf(acc.z * invS + bb.z);
        o.w = tanhf(acc.w * invS + bb.w);
        ((float4*)out)[w * 32 + lane] = o;
    } else {
        float a0 = 0.f, a1 = 0.f;
        int j0 = lane, j1 = lane + 32;
        for (int c = 0; c < nk; c++) {
            int cnt = min(32, deg - (c << 5));
            int s; float wgt;
            if (c < 4) { s = cS[c]; wgt = cW[c]; }
            else {
                int i = (c << 5) + lane;
                s = 0; wgt = 0.f;
                if (i < deg) {
                    s = g_csr[beg + i];
                    float z = g_hs[s] + hdv;
                    float e = (z > 0.f) ? z : 0.2f * z;
                    wgt = __expf(e - M);
                }
            }
            for (int k = 0; k < cnt; k++) {
                int   sk = __shfl_sync(0xffffffff, s, k);
                float wk = __shfl_sync(0xffffffff, wgt, k);
                const float* row = h + (long)sk * F;
                a0 += wk * row[j0];
                if (j1 < F) a1 += wk * row[j1];
            }
        }
        out[(long)w * F + j0] = tanhf(a0 * invS + bias[j0]);
        if (j1 < F) out[(long)w * F + j1] = tanhf(a1 * invS + bias[j1]);
    }
}

// ---------------- mask MLP + soft-argmax gating (32 nodes per block) ---------
__global__ void __launch_bounds__(128) k_mask(
    float* __restrict__ cur,
    const float* __restrict__ mw1, const float* __restrict__ mb1,
    const float* __restrict__ mw2, const float* __restrict__ mb2,
    const float* __restrict__ mw3, const float* __restrict__ mb3,
    const float* __restrict__ mw4, const float* __restrict__ mb4)
{
    __shared__ float w1[128 * 64];
    __shared__ float w2[64 * 16];
    __shared__ float w3[16 * 16];
    __shared__ float w4[16 * 2];
    __shared__ float bb1[64], bb2[16], bb3[16], bb4[2];
    __shared__ float lat[128], m1[64], m2[16], m3[16];
    __shared__ float sa;
    int t = threadIdx.x;
    for (int i = t; i < 128 * 64; i += 128) w1[i] = mw1[i];
    for (int i = t; i < 64 * 16;  i += 128) w2[i] = mw2[i];
    for (int i = t; i < 16 * 16;  i += 128) w3[i] = mw3[i];
    if (t < 32) w4[t] = mw4[t];
    if (t < 64) bb1[t] = mb1[t];
    if (t < 16) { bb2[t] = mb2[t]; bb3[t] = mb3[t]; }
    if (t < 2)  bb4[t] = mb4[t];
    __syncthreads();

    int n0 = blockIdx.x * 32;
    int n1 = min(n0 + 32, NN);
    for (int n = n0; n < n1; n++) {
        lat[t] = cur[n * 128 + t];
        __syncthreads();
        if (t < 64) {
            float s = bb1[t];
            #pragma unroll 8
            for (int k = 0; k < 128; k++) s += lat[k] * w1[k * 64 + t];
            m1[t] = tanhf(s);
        }
        __syncthreads();
        if (t < 16) {
            float s = bb2[t];
            #pragma unroll
            for (int k = 0; k < 64; k++) s += m1[k] * w2[k * 16 + t];
            m2[t] = tanhf(s);
        }
        __syncthreads();
        if (t < 16) {
            float s = bb3[t];
            #pragma unroll
            for (int k = 0; k < 16; k++) s += m2[k] * w3[k * 16 + t];
            m3[t] = tanhf(s);
        }
        __syncthreads();
        if (t == 0) {
            float o0 = bb4[0], o1 = bb4[1];
            #pragma unroll
            for (int k = 0; k < 16; k++) {
                o0 += m3[k] * w4[k * 2];
                o1 += m3[k] * w4[k * 2 + 1];
            }
            float mx = fmaxf(o0, o1);
            float e0 = expf(o0 - mx), e1 = expf(o1 - mx);
            sa = e1 / (e0 + e1);
        }
        __syncthreads();
        cur[n * 128 + t] = lat[t] * sa;
    }
}

// ---------------- orchestration ----------------
extern "C" void kernel_launch(void* const* d_in, const int* in_sizes, int n_in,
                              void* d_out, int out_size)
{
    const float* x   = (const float*)d_in[0];
    const int*   ei  = (const int*)  d_in[1];
    const float* W1  = (const float*)d_in[4];
    const float* a1s = (const float*)d_in[5];
    const float* a1d = (const float*)d_in[6];
    const float* b1  = (const float*)d_in[7];
    const float* Wm  = (const float*)d_in[8];
    const float* ams = (const float*)d_in[9];
    const float* amd = (const float*)d_in[10];
    const float* bm  = (const float*)d_in[11];
    const float* W8  = (const float*)d_in[12];
    const float* a8s = (const float*)d_in[13];
    const float* a8d = (const float*)d_in[14];
    const float* b8  = (const float*)d_in[15];
    const float* mw1 = (const float*)d_in[16];
    const float* mb1 = (const float*)d_in[17];
    const float* mw2 = (const float*)d_in[18];
    const float* mb2 = (const float*)d_in[19];
    const float* mw3 = (const float*)d_in[20];
    const float* mb3 = (const float*)d_in[21];
    const float* mw4 = (const float*)d_in[22];
    const float* mb4 = (const float*)d_in[23];
    float* outp = (float*)d_out;

    void *pv;
    cudaGetSymbolAddress(&pv, g_xn);   float* p_xn  = (float*)pv;
    cudaGetSymbolAddress(&pv, g_h);    float* p_h   = (float*)pv;
    cudaGetSymbolAddress(&pv, g_cur);  float* p_cur = (float*)pv;

    const int EB = (ET + 255) / 256;
    const int GEMM_B = (NN + 127) / 128;       // 391
    const int WARP8  = (NN + 7) / 8;
    const int AGG_B  = (NN * 32 + 255) / 256;  // 6250

    // Launch order puts k_tgemm at index 3 (the ncu capture slot) while
    // preserving all data dependencies on the serialized default stream:
    //   conv1 GEMM needs only k_xn; the CSR chain must finish before k_aggw.
    k_xn<<<WARP8, 256>>>(x);                                     // 0
    k_count<<<EB, 256>>>(ei);                                    // 1 (g_deg zeroed by prev call / BSS)
    k_part<<<SCB, 256>>>();                                      // 2
    k_tgemm<<<GEMM_B, 256>>>(p_xn, W1, p_h, a1s, a1d, NN, HIDD, FIN);  // 3  <-- profiled
    k_scanb<<<1, 256>>>();                                       // 4
    k_off<<<SCB, 256>>>();                                       // 5 (also resets g_deg)
    k_scatter<<<EB, 256>>>(ei);                                  // 6
    k_aggw<HIDD><<<AGG_B, 256>>>(p_h, b1, p_cur);                // 7

    // conv2..conv4
    for (int i = 0; i < 3; i++) {
        k_tgemm<<<GEMM_B, 256>>>(p_cur, Wm + i * HIDD * HIDD, p_h,
                                 ams + i * HIDD, amd + i * HIDD, NN, HIDD, HIDD);
        k_aggw<HIDD><<<AGG_B, 256>>>(p_h, bm + i * HIDD, p_cur);
    }

    // mask MLP gating (in place on latent)
    k_mask<<<(NN + 31) / 32, 128>>>(p_cur, mw1, mb1, mw2, mb2, mw3, mb3, mw4, mb4);

    // conv5..conv7
    for (int i = 3; i < 6; i++) {
        k_tgemm<<<GEMM_B, 256>>>(p_cur, Wm + i * HIDD * HIDD, p_h,
                                 ams + i * HIDD, amd + i * HIDD, NN, HIDD, HIDD);
        k_aggw<HIDD><<<AGG_B, 256>>>(p_h, bm + i * HIDD, p_cur);
    }

    // conv8: 128 -> 42, writes final output
    k_tgemm<<<GEMM_B, 256>>>(p_cur, W8, p_h, a8s, a8d, NN, FIN, HIDD);
    k_aggw<FIN><<<AGG_B, 256>>>(p_h, b8, outp);
}

// round 7
// speedup vs baseline: 1.2379x; 1.2379x over previous
#include <cuda_runtime.h>
#include <math.h>
#include <stdint.h>

#define NN   50000
#define NE   800000
#define ET   (NE + NN)     // edges + self loops
#define FIN  42
#define HIDD 128
#define SCB  ((NN + 255) / 256)   // 196 scan blocks

// ---------------- scratch (device globals; no allocation allowed) -------------
__device__ float g_xn [NN * FIN];
__device__ float g_h  [NN * HIDD];
__device__ float g_cur[NN * HIDD];
__device__ float g_hsp[2 * NN];   // per-N-block partial a_s dots
__device__ float g_hdp[2 * NN];   // per-N-block partial a_d dots
__device__ int   g_deg [NN];      // zero at start of every launch (BSS init + k_off reset)
__device__ int   g_off [NN + 1];
__device__ int   g_fill[NN];
__device__ int   g_csr [ET];
__device__ int   g_boff[256];

// ---------------- L1 normalize input ----------------
__global__ void k_xn(const float* __restrict__ x) {
    int w = (blockIdx.x * blockDim.x + threadIdx.x) >> 5;
    int lane = threadIdx.x & 31;
    if (w >= NN) return;
    float s = 0.f;
    for (int j = lane; j < FIN; j += 32) s += fabsf(x[w * FIN + j]);
    #pragma unroll
    for (int o = 16; o; o >>= 1) s += __shfl_xor_sync(0xffffffff, s, o);
    float inv = 1.f / fmaxf(s, 1e-12f);
    for (int j = lane; j < FIN; j += 32) g_xn[w * FIN + j] = x[w * FIN + j] * inv;
}

// ---------------- CSR build (by destination) ----------------
__global__ void k_count(const int* __restrict__ ei) {
    int e = blockIdx.x * blockDim.x + threadIdx.x;
    if (e >= ET) return;
    int dst = (e < NE) ? ei[NE + e] : (e - NE);
    atomicAdd(&g_deg[dst], 1);
}

__global__ void k_part() {
    __shared__ int wsum[8];
    int t = threadIdx.x, b = blockIdx.x;
    int node = b * 256 + t;
    int v = (node < NN) ? g_deg[node] : 0;
    #pragma unroll
    for (int o = 16; o; o >>= 1) v += __shfl_xor_sync(0xffffffff, v, o);
    if ((t & 31) == 0) wsum[t >> 5] = v;
    __syncthreads();
    if (t == 0) {
        int s = 0;
        #pragma unroll
        for (int i = 0; i < 8; i++) s += wsum[i];
        g_boff[b] = s;
    }
}

__global__ void k_scanb() {
    __shared__ int sh[256];
    int t = threadIdx.x;
    int v = (t < SCB) ? g_boff[t] : 0;
    sh[t] = v;
    __syncthreads();
    #pragma unroll
    for (int o = 1; o < 256; o <<= 1) {
        int u = (t >= o) ? sh[t - o] : 0;
        __syncthreads();
        sh[t] += u;
        __syncthreads();
    }
    if (t < SCB) g_boff[t] = sh[t] - v;
    if (t == 255) g_off[NN] = sh[255];
}

__global__ void k_off() {
    __shared__ int sh[256];
    int t = threadIdx.x, b = blockIdx.x;
    int node = b * 256 + t;
    int d = (node < NN) ? g_deg[node] : 0;
    sh[t] = d;
    __syncthreads();
    #pragma unroll
    for (int o = 1; o < 256; o <<= 1) {
        int u = (t >= o) ? sh[t - o] : 0;
        __syncthreads();
        sh[t] += u;
        __syncthreads();
    }
    if (node < NN) {
        int off = g_boff[b] + sh[t] - d;
        g_off[node] = off;
        g_fill[node] = off;
        g_deg[node] = 0;          // reset for the next kernel_launch call
    }
}

__global__ void k_scatter(const int* __restrict__ ei) {
    int e = blockIdx.x * blockDim.x + threadIdx.x;
    if (e >= ET) return;
    int src, dst;
    if (e < NE) { src = ei[e]; dst = ei[NE + e]; }
    else        { src = e - NE; dst = e - NE; }
    int pos = atomicAdd(&g_fill[dst], 1);
    g_csr[pos] = src;
}

// ---------------- tf32 tensor-core GEMM, 128x64 tile, fused dots --------------
__device__ __forceinline__ uint32_t f2tf(float f) {
    uint32_t u; asm("cvt.rna.tf32.f32 %0, %1;" : "=r"(u) : "f"(f)); return u;
}
__device__ __forceinline__ void mma_tf32(float c[4],
    uint32_t a0, uint32_t a1, uint32_t a2, uint32_t a3,
    uint32_t b0, uint32_t b1)
{
    asm volatile(
        "mma.sync.aligned.m16n8k8.row.col.f32.tf32.tf32.f32 "
        "{%0,%1,%2,%3}, {%4,%5,%6,%7}, {%8,%9}, {%0,%1,%2,%3};"
        : "+f"(c[0]), "+f"(c[1]), "+f"(c[2]), "+f"(c[3])
        : "r"(a0), "r"(a1), "r"(a2), "r"(a3), "r"(b0), "r"(b1));
}

#define ASTR 36
#define BSTR 72
__global__ void __launch_bounds__(256) k_tgemm(
    const float* __restrict__ A, const float* __restrict__ B,
    float* __restrict__ C,
    const float* __restrict__ as_, const float* __restrict__ ad_,
    int M, int N, int K)
{
    __shared__ uint32_t As[128 * ASTR];   // 18.4 KB
    __shared__ uint32_t Bs[32 * BSTR];    //  9.2 KB
    __shared__ float sa[64], sd[64];
    int tid = threadIdx.x;
    int lane = tid & 31, wid = tid >> 5;      // warp owns rows wid*16..wid*16+15
    int q = lane >> 2, p = lane & 3;
    int row0 = blockIdx.x * 128;
    int n0 = blockIdx.y * 64;
    if (tid < 64) {
        int c = n0 + tid;
        sa[tid] = (c < N) ? as_[c] : 0.f;
        sd[tid] = (c < N) ? ad_[c] : 0.f;
    }
    float acc[8][4];
    #pragma unroll
    for (int j = 0; j < 8; j++)
        #pragma unroll
        for (int r = 0; r < 4; r++) acc[j][r] = 0.f;

    for (int k0 = 0; k0 < K; k0 += 32) {
        // ---- stage A chunk [128 x 32] ----
        if ((K & 3) == 0) {          // K=128: full float4 chunks
            #pragma unroll
            for (int l = 0; l < 4; l++) {
                int slot = tid + l * 256;         // 0..1023
                int r = slot >> 3, kg = slot & 7;
                int gr = row0 + r;
                float4 v = make_float4(0.f, 0.f, 0.f, 0.f);
                if (gr < M) v = *(const float4*)&A[(long)gr * K + k0 + kg * 4];
                uint32_t* dst = &As[r * ASTR + kg * 4];
                dst[0] = f2tf(v.x); dst[1] = f2tf(v.y);
                dst[2] = f2tf(v.z); dst[3] = f2tf(v.w);
            }
        } else {                     // K=42: scalar with guards
            #pragma unroll
            for (int l = 0; l < 16; l++) {
                int slot = tid + l * 256;         // 0..4095
                int r = slot >> 5, k = slot & 31;
                int gr = row0 + r, gk = k0 + k;
                float v = (gr < M && gk < K) ? A[(long)gr * K + gk] : 0.f;
                As[r * ASTR + k] = f2tf(v);
            }
        }
        // ---- stage B chunk [32 x 64] (cols n0..n0+63, zero-padded) ----
        if ((N & 3) == 0) {
            #pragma unroll
            for (int l = 0; l < 2; l++) {
                int slot = tid + l * 256;         // 0..511
                int k = slot >> 4, ng = slot & 15;
                int gk = k0 + k;
                float4 v = make_float4(0.f, 0.f, 0.f, 0.f);
                if (gk < K) v = *(const float4*)&B[(long)gk * N + n0 + ng * 4];
                uint32_t* dst = &Bs[k * BSTR + ng * 4];
                dst[0] = f2tf(v.x); dst[1] = f2tf(v.y);
                dst[2] = f2tf(v.z); dst[3] = f2tf(v.w);
            }
        } else {
            #pragma unroll
            for (int l = 0; l < 8; l++) {
                int slot = tid + l * 256;         // 0..2047
                int k = slot >> 6, n = slot & 63;
                int gk = k0 + k;
                float v = (gk < K && n0 + n < N) ? B[(long)gk * N + n0 + n] : 0.f;
                Bs[k * BSTR + n] = f2tf(v);
            }
        }
        __syncthreads();
        // ---- mma over 4 k8-steps ----
        #pragma unroll
        for (int ks = 0; ks < 4; ks++) {
            int kb = ks * 8;
            int r = wid * 16 + q;
            uint32_t a0 = As[r * ASTR + kb + p];
            uint32_t a1 = As[(r + 8) * ASTR + kb + p];
            uint32_t a2 = As[r * ASTR + kb + p + 4];
            uint32_t a3 = As[(r + 8) * ASTR + kb + p + 4];
            #pragma unroll
            for (int fn = 0; fn < 8; fn++) {
                int n = fn * 8 + q;
                uint32_t b0 = Bs[(kb + p) * BSTR + n];
                uint32_t b1 = Bs[(kb + p + 4) * BSTR + n];
                mma_tf32(acc[fn], a0, a1, a2, a3, b0, b1);
            }
        }
        __syncthreads();
    }

    // ---- epilogue: store C + per-warp fused a_s/a_d row dots ----
    #pragma unroll
    for (int ro = 0; ro < 2; ro++) {
        int rl = wid * 16 + q + ro * 8;
        int r = row0 + rl;
        float s = 0.f, d = 0.f;
        #pragma unroll
        for (int fn = 0; fn < 8; fn++) {
            int cl = fn * 8 + p * 2;
            float v0 = acc[fn][ro * 2 + 0];
            float v1 = acc[fn][ro * 2 + 1];
            s += v0 * sa[cl] + v1 * sa[cl + 1];
            d += v0 * sd[cl] + v1 * sd[cl + 1];
            int c = n0 + cl;
            if (r < M) {
                if (c + 1 < N) *(float2*)&C[(long)r * N + c] = make_float2(v0, v1);
                else if (c < N) C[(long)r * N + c] = v0;
            }
        }
        s += __shfl_xor_sync(0xffffffff, s, 1);
        s += __shfl_xor_sync(0xffffffff, s, 2);
        d += __shfl_xor_sync(0xffffffff, d, 1);
        d += __shfl_xor_sync(0xffffffff, d, 2);
        if (p == 0 && r < M) {
            g_hsp[blockIdx.y * NN + r] = s;   // warp owns these rows+cols exclusively
            g_hdp[blockIdx.y * NN + r] = d;
        }
    }
}

// ------------- warp-per-node softmax aggregation (no barriers) ---------------
// TWO = layer's GEMM had 2 N-blocks -> sum both dot partials.
template<int F>
__global__ void __launch_bounds__(256) k_aggw(
    const float* __restrict__ h, const float* __restrict__ bias,
    float* __restrict__ out)
{
    constexpr bool TWO = (F == 128);
    int w = (blockIdx.x * blockDim.x + threadIdx.x) >> 5;
    int lane = threadIdx.x & 31;
    if (w >= NN) return;
    int beg = g_off[w], end = g_off[w + 1];
    int deg = end - beg;
    int nk = (deg + 31) >> 5;
    float hdv = TWO ? (g_hdp[w] + g_hdp[NN + w]) : g_hdp[w];

    float cW[4]; int cS[4];
    float mymax = -INFINITY;
    for (int c = 0; c < nk; c++) {
        int i = (c << 5) + lane;
        float e = -INFINITY; int s = 0;
        if (i < deg) {
            s = g_csr[beg + i];
            float hs = TWO ? (g_hsp[s] + g_hsp[NN + s]) : g_hsp[s];
            float z = hs + hdv;
            e = (z > 0.f) ? z : 0.2f * z;
        }
        if (c < 4) { cS[c] = s; cW[c] = e; }
        mymax = fmaxf(mymax, e);
    }
    #pragma unroll
    for (int o = 16; o; o >>= 1) mymax = fmaxf(mymax, __shfl_xor_sync(0xffffffff, mymax, o));
    float M = mymax;

    float myS = 0.f;
    for (int c = 0; c < nk; c++) {
        float e;
        if (c < 4) e = cW[c];
        else {
            int i = (c << 5) + lane;
            e = -INFINITY;
            if (i < deg) {
                int s = g_csr[beg + i];
                float hs = TWO ? (g_hsp[s] + g_hsp[NN + s]) : g_hsp[s];
                float z = hs + hdv;
                e = (z > 0.f) ? z : 0.2f * z;
            }
        }
        float wgt = __expf(e - M);
        if (c < 4) cW[c] = wgt;
        myS += wgt;
    }
    #pragma unroll
    for (int o = 16; o; o >>= 1) myS += __shfl_xor_sync(0xffffffff, myS, o);
    float invS = 1.f / (myS + 1e-16f);

    if constexpr (F == 128) {
        const float4* h4 = (const float4*)h;
        float4 acc = make_float4(0.f, 0.f, 0.f, 0.f);
        for (int c = 0; c < nk; c++) {
            int cnt = min(32, deg - (c << 5));
            int s; float wgt;
            if (c < 4) { s = cS[c]; wgt = cW[c]; }
            else {
                int i = (c << 5) + lane;
                s = 0; wgt = 0.f;
                if (i < deg) {
                    s = g_csr[beg + i];
                    float hs = g_hsp[s] + g_hsp[NN + s];
                    float z = hs + hdv;
                    float e = (z > 0.f) ? z : 0.2f * z;
                    wgt = __expf(e - M);
                }
            }
            int k = 0;
            for (; k + 4 <= cnt; k += 4) {
                int   s0 = __shfl_sync(0xffffffff, s, k);
                int   s1 = __shfl_sync(0xffffffff, s, k + 1);
                int   s2 = __shfl_sync(0xffffffff, s, k + 2);
                int   s3 = __shfl_sync(0xffffffff, s, k + 3);
                float w0 = __shfl_sync(0xffffffff, wgt, k);
                float w1 = __shfl_sync(0xffffffff, wgt, k + 1);
                float w2 = __shfl_sync(0xffffffff, wgt, k + 2);
                float w3 = __shfl_sync(0xffffffff, wgt, k + 3);
                float4 v0 = h4[s0 * 32 + lane];
                float4 v1 = h4[s1 * 32 + lane];
                float4 v2 = h4[s2 * 32 + lane];
                float4 v3 = h4[s3 * 32 + lane];
                acc.x += w0 * v0.x + w1 * v1.x + w2 * v2.x + w3 * v3.x;
                acc.y += w0 * v0.y + w1 * v1.y + w2 * v2.y + w3 * v3.y;
                acc.z += w0 * v0.z + w1 * v1.z + w2 * v2.z + w3 * v3.z;
                acc.w += w0 * v0.w + w1 * v1.w + w2 * v2.w + w3 * v3.w;
            }
            for (; k < cnt; k++) {
                int   sk = __shfl_sync(0xffffffff, s, k);
                float wk = __shfl_sync(0xffffffff, wgt, k);
                float4 v = h4[sk * 32 + lane];
                acc.x += wk * v.x; acc.y += wk * v.y;
                acc.z += wk * v.z; acc.w += wk * v.w;
            }
        }
        const float4* b4 = (const float4*)bias;
        float4 bb = b4[lane];
        float4 o;
        o.x = tanhf(acc.x * invS + bb.x);
        o.y = tanhf(acc.y * invS + bb.y);
        o.z = tanhf(acc.z * invS + bb.z);
        o.w = tanhf(acc.w * invS + bb.w);
        ((float4*)out)[w * 32 + lane] = o;
    } else {
        float a0 = 0.f, a1 = 0.f;
        int j0 = lane, j1 = lane + 32;
        for (int c = 0; c < nk; c++) {
            int cnt = min(32, deg - (c << 5));
            int s; float wgt;
            if (c < 4) { s = cS[c]; wgt = cW[c]; }
            else {
                int i = (c << 5) + lane;
                s = 0; wgt = 0.f;
                if (i < deg) {
                    s = g_csr[beg + i];
                    float hs = g_hsp[s];
                    float z = hs + hdv;
                    float e = (z > 0.f) ? z : 0.2f * z;
                    wgt = __expf(e - M);
                }
            }
            for (int k = 0; k < cnt; k++) {
                int   sk = __shfl_sync(0xffffffff, s, k);
                float wk = __shfl_sync(0xffffffff, wgt, k);
                const float* row = h + (long)sk * F;
                a0 += wk * row[j0];
                if (j1 < F) a1 += wk * row[j1];
            }
        }
        out[(long)w * F + j0] = tanhf(a0 * invS + bias[j0]);
        if (j1 < F) out[(long)w * F + j1] = tanhf(a1 * invS + bias[j1]);
    }
}

// ---------------- mask MLP + soft-argmax gating (32 nodes per block) ---------
__global__ void __launch_bounds__(128) k_mask(
    float* __restrict__ cur,
    const float* __restrict__ mw1, const float* __restrict__ mb1,
    const float* __restrict__ mw2, const float* __restrict__ mb2,
    const float* __restrict__ mw3, const float* __restrict__ mb3,
    const float* __restrict__ mw4, const float* __restrict__ mb4)
{
    __shared__ float w1[128 * 64];
    __shared__ float w2[64 * 16];
    __shared__ float w3[16 * 16];
    __shared__ float w4[16 * 2];
    __shared__ float bb1[64], bb2[16], bb3[16], bb4[2];
    __shared__ float lat[128], m1[64], m2[16], m3[16];
    __shared__ float sa;
    int t = threadIdx.x;
    for (int i = t; i < 128 * 64; i += 128) w1[i] = mw1[i];
    for (int i = t; i < 64 * 16;  i += 128) w2[i] = mw2[i];
    for (int i = t; i < 16 * 16;  i += 128) w3[i] = mw3[i];
    if (t < 32) w4[t] = mw4[t];
    if (t < 64) bb1[t] = mb1[t];
    if (t < 16) { bb2[t] = mb2[t]; bb3[t] = mb3[t]; }
    if (t < 2)  bb4[t] = mb4[t];
    __syncthreads();

    int n0 = blockIdx.x * 32;
    int n1 = min(n0 + 32, NN);
    for (int n = n0; n < n1; n++) {
        lat[t] = cur[n * 128 + t];
        __syncthreads();
        if (t < 64) {
            float s = bb1[t];
            #pragma unroll 8
            for (int k = 0; k < 128; k++) s += lat[k] * w1[k * 64 + t];
            m1[t] = tanhf(s);
        }
        __syncthreads();
        if (t < 16) {
            float s = bb2[t];
            #pragma unroll
            for (int k = 0; k < 64; k++) s += m1[k] * w2[k * 16 + t];
            m2[t] = tanhf(s);
        }
        __syncthreads();
        if (t < 16) {
            float s = bb3[t];
            #pragma unroll
            for (int k = 0; k < 16; k++) s += m2[k] * w3[k * 16 + t];
            m3[t] = tanhf(s);
        }
        __syncthreads();
        if (t == 0) {
            float o0 = bb4[0], o1 = bb4[1];
            #pragma unroll
            for (int k = 0; k < 16; k++) {
                o0 += m3[k] * w4[k * 2];
                o1 += m3[k] * w4[k * 2 + 1];
            }
            float mx = fmaxf(o0, o1);
            float e0 = expf(o0 - mx), e1 = expf(o1 - mx);
            sa = e1 / (e0 + e1);
        }
        __syncthreads();
        cur[n * 128 + t] = lat[t] * sa;
    }
}

// ---------------- orchestration ----------------
extern "C" void kernel_launch(void* const* d_in, const int* in_sizes, int n_in,
                              void* d_out, int out_size)
{
    const float* x   = (const float*)d_in[0];
    const int*   ei  = (const int*)  d_in[1];
    const float* W1  = (const float*)d_in[4];
    const float* a1s = (const float*)d_in[5];
    const float* a1d = (const float*)d_in[6];
    const float* b1  = (const float*)d_in[7];
    const float* Wm  = (const float*)d_in[8];
    const float* ams = (const float*)d_in[9];
    const float* amd = (const float*)d_in[10];
    const float* bm  = (const float*)d_in[11];
    const float* W8  = (const float*)d_in[12];
    const float* a8s = (const float*)d_in[13];
    const float* a8d = (const float*)d_in[14];
    const float* b8  = (const float*)d_in[15];
    const float* mw1 = (const float*)d_in[16];
    const float* mb1 = (const float*)d_in[17];
    const float* mw2 = (const float*)d_in[18];
    const float* mb2 = (const float*)d_in[19];
    const float* mw3 = (const float*)d_in[20];
    const float* mb3 = (const float*)d_in[21];
    const float* mw4 = (const float*)d_in[22];
    const float* mb4 = (const float*)d_in[23];
    float* outp = (float*)d_out;

    void *pv;
    cudaGetSymbolAddress(&pv, g_xn);   float* p_xn  = (float*)pv;
    cudaGetSymbolAddress(&pv, g_h);    float* p_h   = (float*)pv;
    cudaGetSymbolAddress(&pv, g_cur);  float* p_cur = (float*)pv;

    const int EB = (ET + 255) / 256;
    const int GEMM_B = (NN + 127) / 128;       // 391
    const dim3 G2(GEMM_B, 2);                  // N=128 layers
    const dim3 G1(GEMM_B, 1);                  // N=42 layer
    const int WARP8  = (NN + 7) / 8;
    const int AGG_B  = (NN * 32 + 255) / 256;  // 6250

    // launch order keeps k_tgemm at index 3 (ncu capture slot)
    k_xn<<<WARP8, 256>>>(x);                                     // 0
    k_count<<<EB, 256>>>(ei);                                    // 1
    k_part<<<SCB, 256>>>();                                      // 2
    k_tgemm<<<G2, 256>>>(p_xn, W1, p_h, a1s, a1d, NN, HIDD, FIN);// 3  <-- profiled
    k_scanb<<<1, 256>>>();                                       // 4
    k_off<<<SCB, 256>>>();                                       // 5
    k_scatter<<<EB, 256>>>(ei);                                  // 6
    k_aggw<HIDD><<<AGG_B, 256>>>(p_h, b1, p_cur);                // 7

    // conv2..conv4
    for (int i = 0; i < 3; i++) {
        k_tgemm<<<G2, 256>>>(p_cur, Wm + i * HIDD * HIDD, p_h,
                             ams + i * HIDD, amd + i * HIDD, NN, HIDD, HIDD);
        k_aggw<HIDD><<<AGG_B, 256>>>(p_h, bm + i * HIDD, p_cur);
    }

    // mask MLP gating (in place on latent)
    k_mask<<<(NN + 31) / 32, 128>>>(p_cur, mw1, mb1, mw2, mb2, mw3, mb3, mw4, mb4);

    // conv5..conv7
    for (int i = 3; i < 6; i++) {
        k_tgemm<<<G2, 256>>>(p_cur, Wm + i * HIDD * HIDD, p_h,
                             ams + i * HIDD, amd + i * HIDD, NN, HIDD, HIDD);
        k_aggw<HIDD><<<AGG_B, 256>>>(p_h, bm + i * HIDD, p_cur);
    }

    // conv8: 128 -> 42, writes final output
    k_tgemm<<<G1, 256>>>(p_cur, W8, p_h, a8s, a8d, NN, FIN, HIDD);
    k_aggw<FIN><<<AGG_B, 256>>>(p_h, b8, outp);
}

// round 8
// speedup vs baseline: 1.5352x; 1.2401x over previous
#include <cuda_runtime.h>
#include <math.h>
#include <stdint.h>

#define NN   50000
#define NE   800000
#define ET   (NE + NN)     // edges + self loops
#define FIN  42
#define KPAD 64            // conv1 K padded to 64
#define HIDD 128
#define SCB  ((NN + 255) / 256)   // 196 scan blocks

// ---------------- scratch (device globals; no allocation allowed) -------------
__device__ float g_xn [NN * KPAD];   // padded normalized input; later reused as m1 buffer
__device__ float g_h  [NN * HIDD];
__device__ float g_cur[NN * HIDD];
__device__ float g_hsp[2 * NN];   // per-N-block partial a_s dots
__device__ float g_hdp[2 * NN];   // per-N-block partial a_d dots
__device__ int   g_deg [NN];      // zero at start of every launch (BSS init + k_off reset)
__device__ int   g_off [NN + 1];
__device__ int   g_fill[NN];
__device__ int   g_csr [ET];
__device__ int   g_boff[256];

// ---------------- L1 normalize input (zero-padded to KPAD cols) ---------------
__global__ void k_xn(const float* __restrict__ x) {
    int w = (blockIdx.x * blockDim.x + threadIdx.x) >> 5;
    int lane = threadIdx.x & 31;
    if (w >= NN) return;
    float s = 0.f;
    for (int j = lane; j < FIN; j += 32) s += fabsf(x[w * FIN + j]);
    #pragma unroll
    for (int o = 16; o; o >>= 1) s += __shfl_xor_sync(0xffffffff, s, o);
    float inv = 1.f / fmaxf(s, 1e-12f);
    for (int j = lane; j < KPAD; j += 32)
        g_xn[w * KPAD + j] = (j < FIN) ? x[w * FIN + j] * inv : 0.f;
}

// ---------------- CSR build (by destination) ----------------
__global__ void k_count(const int* __restrict__ ei) {
    int e = blockIdx.x * blockDim.x + threadIdx.x;
    if (e >= ET) return;
    int dst = (e < NE) ? ei[NE + e] : (e - NE);
    atomicAdd(&g_deg[dst], 1);
}

__global__ void k_part() {
    __shared__ int wsum[8];
    int t = threadIdx.x, b = blockIdx.x;
    int node = b * 256 + t;
    int v = (node < NN) ? g_deg[node] : 0;
    #pragma unroll
    for (int o = 16; o; o >>= 1) v += __shfl_xor_sync(0xffffffff, v, o);
    if ((t & 31) == 0) wsum[t >> 5] = v;
    __syncthreads();
    if (t == 0) {
        int s = 0;
        #pragma unroll
        for (int i = 0; i < 8; i++) s += wsum[i];
        g_boff[b] = s;
    }
}

__global__ void k_scanb() {
    __shared__ int sh[256];
    int t = threadIdx.x;
    int v = (t < SCB) ? g_boff[t] : 0;
    sh[t] = v;
    __syncthreads();
    #pragma unroll
    for (int o = 1; o < 256; o <<= 1) {
        int u = (t >= o) ? sh[t - o] : 0;
        __syncthreads();
        sh[t] += u;
        __syncthreads();
    }
    if (t < SCB) g_boff[t] = sh[t] - v;
    if (t == 255) g_off[NN] = sh[255];
}

__global__ void k_off() {
    __shared__ int sh[256];
    int t = threadIdx.x, b = blockIdx.x;
    int node = b * 256 + t;
    int d = (node < NN) ? g_deg[node] : 0;
    sh[t] = d;
    __syncthreads();
    #pragma unroll
    for (int o = 1; o < 256; o <<= 1) {
        int u = (t >= o) ? sh[t - o] : 0;
        __syncthreads();
        sh[t] += u;
        __syncthreads();
    }
    if (node < NN) {
        int off = g_boff[b] + sh[t] - d;
        g_off[node] = off;
        g_fill[node] = off;
        g_deg[node] = 0;          // reset for the next kernel_launch call
    }
}

__global__ void k_scatter(const int* __restrict__ ei) {
    int e = blockIdx.x * blockDim.x + threadIdx.x;
    if (e >= ET) return;
    int src, dst;
    if (e < NE) { src = ei[e]; dst = ei[NE + e]; }
    else        { src = e - NE; dst = e - NE; }
    int pos = atomicAdd(&g_fill[dst], 1);
    g_csr[pos] = src;
}

// ---------------- tf32 tensor-core GEMM, 128x64 tile ----------------
// mode 0: C = A@B, plus fused dots g_hsp/g_hdp[r] = C_row . as_/ad_
// mode 1: C = tanh(A@B + bias), no dots
__device__ __forceinline__ uint32_t f2tf(float f) {
    uint32_t u; asm("cvt.rna.tf32.f32 %0, %1;" : "=r"(u) : "f"(f)); return u;
}
__device__ __forceinline__ void mma_tf32(float c[4],
    uint32_t a0, uint32_t a1, uint32_t a2, uint32_t a3,
    uint32_t b0, uint32_t b1)
{
    asm volatile(
        "mma.sync.aligned.m16n8k8.row.col.f32.tf32.tf32.f32 "
        "{%0,%1,%2,%3}, {%4,%5,%6,%7}, {%8,%9}, {%0,%1,%2,%3};"
        : "+f"(c[0]), "+f"(c[1]), "+f"(c[2]), "+f"(c[3])
        : "r"(a0), "r"(a1), "r"(a2), "r"(a3), "r"(b0), "r"(b1));
}

#define ASTR 36
#define BSTR 72
__global__ void __launch_bounds__(256, 3) k_tgemm(
    const float* __restrict__ A, const float* __restrict__ B,
    float* __restrict__ C,
    const float* __restrict__ as_, const float* __restrict__ ad_,
    const float* __restrict__ bias,
    int M, int N, int K, int KB, int mode)
{
    __shared__ uint32_t As[128 * ASTR];   // 18.4 KB
    __shared__ uint32_t Bs[32 * BSTR];    //  9.2 KB
    __shared__ float sa[64], sd[64];
    int tid = threadIdx.x;
    int lane = tid & 31, wid = tid >> 5;      // warp owns rows wid*16..wid*16+15
    int q = lane >> 2, p = lane & 3;
    int row0 = blockIdx.x * 128;
    int n0 = blockIdx.y * 64;
    if (tid < 64) {
        int c = n0 + tid;
        if (mode == 0) {
            sa[tid] = (c < N) ? as_[c] : 0.f;
            sd[tid] = (c < N) ? ad_[c] : 0.f;
        } else {
            sa[tid] = (c < N) ? bias[c] : 0.f;
        }
    }
    float acc[8][4];
    #pragma unroll
    for (int j = 0; j < 8; j++)
        #pragma unroll
        for (int r = 0; r < 4; r++) acc[j][r] = 0.f;

    for (int k0 = 0; k0 < K; k0 += 32) {
        // ---- stage A chunk [128 x 32]: K always multiple of 32 (64 or 128) ----
        #pragma unroll
        for (int l = 0; l < 4; l++) {
            int slot = tid + l * 256;         // 0..1023
            int r = slot >> 3, kg = slot & 7;
            int gr = row0 + r;
            float4 v = make_float4(0.f, 0.f, 0.f, 0.f);
            if (gr < M) v = *(const float4*)&A[(long)gr * K + k0 + kg * 4];
            uint32_t* dst = &As[r * ASTR + kg * 4];
            dst[0] = f2tf(v.x); dst[1] = f2tf(v.y);
            dst[2] = f2tf(v.z); dst[3] = f2tf(v.w);
        }
        // ---- stage B chunk [32 x 64] (rows bounded by KB, cols zero-padded) ----
        if ((N & 3) == 0) {
            #pragma unroll
            for (int l = 0; l < 2; l++) {
                int slot = tid + l * 256;         // 0..511
                int k = slot >> 4, ng = slot & 15;
                int gk = k0 + k;
                float4 v = make_float4(0.f, 0.f, 0.f, 0.f);
                if (gk < KB) v = *(const float4*)&B[(long)gk * N + n0 + ng * 4];
                uint32_t* dst = &Bs[k * BSTR + ng * 4];
                dst[0] = f2tf(v.x); dst[1] = f2tf(v.y);
                dst[2] = f2tf(v.z); dst[3] = f2tf(v.w);
            }
        } else {
            #pragma unroll
            for (int l = 0; l < 8; l++) {
                int slot = tid + l * 256;         // 0..2047
                int k = slot >> 6, n = slot & 63;
                int gk = k0 + k;
                float v = (gk < KB && n0 + n < N) ? B[(long)gk * N + n0 + n] : 0.f;
                Bs[k * BSTR + n] = f2tf(v);
            }
        }
        __syncthreads();
        // ---- mma over 4 k8-steps ----
        #pragma unroll
        for (int ks = 0; ks < 4; ks++) {
            int kb = ks * 8;
            int r = wid * 16 + q;
            uint32_t a0 = As[r * ASTR + kb + p];
            uint32_t a1 = As[(r + 8) * ASTR + kb + p];
            uint32_t a2 = As[r * ASTR + kb + p + 4];
            uint32_t a3 = As[(r + 8) * ASTR + kb + p + 4];
            #pragma unroll
            for (int fn = 0; fn < 8; fn++) {
                int n = fn * 8 + q;
                uint32_t b0 = Bs[(kb + p) * BSTR + n];
                uint32_t b1 = Bs[(kb + p + 4) * BSTR + n];
                mma_tf32(acc[fn], a0, a1, a2, a3, b0, b1);
            }
        }
        __syncthreads();
    }

    if (mode == 0) {
        // ---- epilogue: store C + per-warp fused a_s/a_d row dots ----
        #pragma unroll
        for (int ro = 0; ro < 2; ro++) {
            int rl = wid * 16 + q + ro * 8;
            int r = row0 + rl;
            float s = 0.f, d = 0.f;
            #pragma unroll
            for (int fn = 0; fn < 8; fn++) {
                int cl = fn * 8 + p * 2;
                float v0 = acc[fn][ro * 2 + 0];
                float v1 = acc[fn][ro * 2 + 1];
                s += v0 * sa[cl] + v1 * sa[cl + 1];
                d += v0 * sd[cl] + v1 * sd[cl + 1];
                int c = n0 + cl;
                if (r < M) {
                    if (c + 1 < N) *(float2*)&C[(long)r * N + c] = make_float2(v0, v1);
                    else if (c < N) C[(long)r * N + c] = v0;
                }
            }
            s += __shfl_xor_sync(0xffffffff, s, 1);
            s += __shfl_xor_sync(0xffffffff, s, 2);
            d += __shfl_xor_sync(0xffffffff, d, 1);
            d += __shfl_xor_sync(0xffffffff, d, 2);
            if (p == 0 && r < M) {
                g_hsp[blockIdx.y * NN + r] = s;
                g_hdp[blockIdx.y * NN + r] = d;
            }
        }
    } else {
        // ---- epilogue: C = tanh(acc + bias) ----
        #pragma unroll
        for (int ro = 0; ro < 2; ro++) {
            int rl = wid * 16 + q + ro * 8;
            int r = row0 + rl;
            if (r >= M) continue;
            #pragma unroll
            for (int fn = 0; fn < 8; fn++) {
                int cl = fn * 8 + p * 2;
                int c = n0 + cl;
                float v0 = tanhf(acc[fn][ro * 2 + 0] + sa[cl]);
                float v1 = tanhf(acc[fn][ro * 2 + 1] + sa[cl + 1]);
                if (c + 1 < N) *(float2*)&C[(long)r * N + c] = make_float2(v0, v1);
                else if (c < N) C[(long)r * N + c] = v0;
            }
        }
    }
}

// ------------- warp-per-node softmax aggregation (no barriers) ---------------
template<int F>
__global__ void __launch_bounds__(256) k_aggw(
    const float* __restrict__ h, const float* __restrict__ bias,
    float* __restrict__ out)
{
    constexpr bool TWO = (F == 128);
    int w = (blockIdx.x * blockDim.x + threadIdx.x) >> 5;
    int lane = threadIdx.x & 31;
    if (w >= NN) return;
    int beg = g_off[w], end = g_off[w + 1];
    int deg = end - beg;
    int nk = (deg + 31) >> 5;
    float hdv = TWO ? (g_hdp[w] + g_hdp[NN + w]) : g_hdp[w];

    float cW[4]; int cS[4];
    float mymax = -INFINITY;
    for (int c = 0; c < nk; c++) {
        int i = (c << 5) + lane;
        float e = -INFINITY; int s = 0;
        if (i < deg) {
            s = g_csr[beg + i];
            float hs = TWO ? (g_hsp[s] + g_hsp[NN + s]) : g_hsp[s];
            float z = hs + hdv;
            e = (z > 0.f) ? z : 0.2f * z;
        }
        if (c < 4) { cS[c] = s; cW[c] = e; }
        mymax = fmaxf(mymax, e);
    }
    #pragma unroll
    for (int o = 16; o; o >>= 1) mymax = fmaxf(mymax, __shfl_xor_sync(0xffffffff, mymax, o));
    float M = mymax;

    float myS = 0.f;
    for (int c = 0; c < nk; c++) {
        float e;
        if (c < 4) e = cW[c];
        else {
            int i = (c << 5) + lane;
            e = -INFINITY;
            if (i < deg) {
                int s = g_csr[beg + i];
                float hs = TWO ? (g_hsp[s] + g_hsp[NN + s]) : g_hsp[s];
                float z = hs + hdv;
                e = (z > 0.f) ? z : 0.2f * z;
            }
        }
        float wgt = __expf(e - M);
        if (c < 4) cW[c] = wgt;
        myS += wgt;
    }
    #pragma unroll
    for (int o = 16; o; o >>= 1) myS += __shfl_xor_sync(0xffffffff, myS, o);
    float invS = 1.f / (myS + 1e-16f);

    if constexpr (F == 128) {
        const float4* h4 = (const float4*)h;
        float4 acc = make_float4(0.f, 0.f, 0.f, 0.f);
        for (int c = 0; c < nk; c++) {
            int cnt = min(32, deg - (c << 5));
            int s; float wgt;
            if (c < 4) { s = cS[c]; wgt = cW[c]; }
            else {
                int i = (c << 5) + lane;
                s = 0; wgt = 0.f;
                if (i < deg) {
                    s = g_csr[beg + i];
                    float hs = g_hsp[s] + g_hsp[NN + s];
                    float z = hs + hdv;
                    float e = (z > 0.f) ? z : 0.2f * z;
                    wgt = __expf(e - M);
                }
            }
            int k = 0;
            for (; k + 4 <= cnt; k += 4) {
                int   s0 = __shfl_sync(0xffffffff, s, k);
                int   s1 = __shfl_sync(0xffffffff, s, k + 1);
                int   s2 = __shfl_sync(0xffffffff, s, k + 2);
                int   s3 = __shfl_sync(0xffffffff, s, k + 3);
                float w0 = __shfl_sync(0xffffffff, wgt, k);
                float w1 = __shfl_sync(0xffffffff, wgt, k + 1);
                float w2 = __shfl_sync(0xffffffff, wgt, k + 2);
                float w3 = __shfl_sync(0xffffffff, wgt, k + 3);
                float4 v0 = h4[s0 * 32 + lane];
                float4 v1 = h4[s1 * 32 + lane];
                float4 v2 = h4[s2 * 32 + lane];
                float4 v3 = h4[s3 * 32 + lane];
                acc.x += w0 * v0.x + w1 * v1.x + w2 * v2.x + w3 * v3.x;
                acc.y += w0 * v0.y + w1 * v1.y + w2 * v2.y + w3 * v3.y;
                acc.z += w0 * v0.z + w1 * v1.z + w2 * v2.z + w3 * v3.z;
                acc.w += w0 * v0.w + w1 * v1.w + w2 * v2.w + w3 * v3.w;
            }
            for (; k < cnt; k++) {
                int   sk = __shfl_sync(0xffffffff, s, k);
                float wk = __shfl_sync(0xffffffff, wgt, k);
                float4 v = h4[sk * 32 + lane];
                acc.x += wk * v.x; acc.y += wk * v.y;
                acc.z += wk * v.z; acc.w += wk * v.w;
            }
        }
        const float4* b4 = (const float4*)bias;
        float4 bb = b4[lane];
        float4 o;
        o.x = tanhf(acc.x * invS + bb.x);
        o.y = tanhf(acc.y * invS + bb.y);
        o.z = tanhf(acc.z * invS + bb.z);
        o.w = tanhf(acc.w * invS + bb.w);
        ((float4*)out)[w * 32 + lane] = o;
    } else {
        float a0 = 0.f, a1 = 0.f;
        int j0 = lane, j1 = lane + 32;
        for (int c = 0; c < nk; c++) {
            int cnt = min(32, deg - (c << 5));
            int s; float wgt;
            if (c < 4) { s = cS[c]; wgt = cW[c]; }
            else {
                int i = (c << 5) + lane;
                s = 0; wgt = 0.f;
                if (i < deg) {
                    s = g_csr[beg + i];
                    float hs = g_hsp[s];
                    float z = hs + hdv;
                    float e = (z > 0.f) ? z : 0.2f * z;
                    wgt = __expf(e - M);
                }
            }
            for (int k = 0; k < cnt; k++) {
                int   sk = __shfl_sync(0xffffffff, s, k);
                float wk = __shfl_sync(0xffffffff, wgt, k);
                const float* row = h + (long)sk * F;
                a0 += wk * row[j0];
                if (j1 < F) a1 += wk * row[j1];
            }
        }
        out[(long)w * F + j0] = tanhf(a0 * invS + bias[j0]);
        if (j1 < F) out[(long)w * F + j1] = tanhf(a1 * invS + bias[j1]);
    }
}

// -------- mask MLP tail (m2..m4) + soft-argmax gating, warp per node ---------
// m1 = tanh(latent @ mw1 + mb1) precomputed by k_tgemm mode 1 into g_xn.
__global__ void __launch_bounds__(256) k_mask2(
    float* __restrict__ cur, const float* __restrict__ m1,
    const float* __restrict__ mw2, const float* __restrict__ mb2,
    const float* __restrict__ mw3, const float* __restrict__ mb3,
    const float* __restrict__ mw4, const float* __restrict__ mb4)
{
    __shared__ float w2[64 * 16];
    __shared__ float w3[16 * 16];
    __shared__ float w4[32];
    __shared__ float bb2[16], bb3[16], bb4[2];
    int t = threadIdx.x;
    for (int i = t; i < 64 * 16; i += 256) w2[i] = mw2[i];
    if (t < 256 && t < 16 * 16) w3[t] = mw3[t];
    if (t < 32) w4[t] = mw4[t];
    if (t < 16) { bb2[t] = mb2[t]; bb3[t] = mb3[t]; }
    if (t < 2)  bb4[t] = mb4[t];
    __syncthreads();

    int n = blockIdx.x * 8 + (t >> 5);
    int lane = t & 31;
    if (n >= NN) return;

    // m1 row: lane holds m1[lane], m1[lane+32]
    float a0 = m1[(long)n * 64 + lane];
    float a1 = m1[(long)n * 64 + lane + 32];

    // m2[16] (replicated in both half-warps via lane&15)
    int l16 = lane & 15;
    float s2 = bb2[l16];
    #pragma unroll
    for (int k = 0; k < 32; k++)
        s2 += __shfl_sync(0xffffffff, a0, k) * w2[k * 16 + l16];
    #pragma unroll
    for (int k = 0; k < 32; k++)
        s2 += __shfl_sync(0xffffffff, a1, k) * w2[(k + 32) * 16 + l16];
    s2 = tanhf(s2);

    // m3[16]
    float s3 = bb3[l16];
    #pragma unroll
    for (int k = 0; k < 16; k++)
        s3 += __shfl_sync(0xffffffff, s2, k) * w3[k * 16 + l16];
    s3 = tanhf(s3);

    // m4[2] + softmax soft-argmax
    int l2 = lane & 1;
    float o = bb4[l2];
    #pragma unroll
    for (int k = 0; k < 16; k++)
        o += __shfl_sync(0xffffffff, s3, k) * w4[k * 2 + l2];
    float o0 = __shfl_sync(0xffffffff, o, 0);
    float o1 = __shfl_sync(0xffffffff, o, 1);
    float mx = fmaxf(o0, o1);
    float e0 = expf(o0 - mx), e1 = expf(o1 - mx);
    float sa = e1 / (e0 + e1);

    float4* c4 = (float4*)&cur[(long)n * 128];
    float4 v = c4[lane];
    v.x *= sa; v.y *= sa; v.z *= sa; v.w *= sa;
    c4[lane] = v;
}

// ---------------- orchestration ----------------
extern "C" void kernel_launch(void* const* d_in, const int* in_sizes, int n_in,
                              void* d_out, int out_size)
{
    const float* x   = (const float*)d_in[0];
    const int*   ei  = (const int*)  d_in[1];
    const float* W1  = (const float*)d_in[4];
    const float* a1s = (const float*)d_in[5];
    const float* a1d = (const float*)d_in[6];
    const float* b1  = (const float*)d_in[7];
    const float* Wm  = (const float*)d_in[8];
    const float* ams = (const float*)d_in[9];
    const float* amd = (const float*)d_in[10];
    const float* bm  = (const float*)d_in[11];
    const float* W8  = (const float*)d_in[12];
    const float* a8s = (const float*)d_in[13];
    const float* a8d = (const float*)d_in[14];
    const float* b8  = (const float*)d_in[15];
    const float* mw1 = (const float*)d_in[16];
    const float* mb1 = (const float*)d_in[17];
    const float* mw2 = (const float*)d_in[18];
    const float* mb2 = (const float*)d_in[19];
    const float* mw3 = (const float*)d_in[20];
    const float* mb3 = (const float*)d_in[21];
    const float* mw4 = (const float*)d_in[22];
    const float* mb4 = (const float*)d_in[23];
    float* outp = (float*)d_out;

    void *pv;
    cudaGetSymbolAddress(&pv, g_xn);   float* p_xn  = (float*)pv;
    cudaGetSymbolAddress(&pv, g_h);    float* p_h   = (float*)pv;
    cudaGetSymbolAddress(&pv, g_cur);  float* p_cur = (float*)pv;

    const int EB = (ET + 255) / 256;
    const int GEMM_B = (NN + 127) / 128;       // 391
    const dim3 G2(GEMM_B, 2);                  // N=128 layers
    const dim3 G1(GEMM_B, 1);                  // N<=64 layers
    const int WARP8  = (NN + 7) / 8;
    const int AGG_B  = (NN * 32 + 255) / 256;  // 6250

    // launch order keeps conv1's k_tgemm at index 3 (ncu capture slot)
    k_xn<<<WARP8, 256>>>(x);                                     // 0
    k_count<<<EB, 256>>>(ei);                                    // 1
    k_part<<<SCB, 256>>>();                                      // 2
    k_tgemm<<<G2, 256>>>(p_xn, W1, p_h, a1s, a1d, b1,
                         NN, HIDD, KPAD, FIN, 0);                // 3  <-- profiled
    k_scanb<<<1, 256>>>();                                       // 4
    k_off<<<SCB, 256>>>();                                       // 5
    k_scatter<<<EB, 256>>>(ei);                                  // 6
    k_aggw<HIDD><<<AGG_B, 256>>>(p_h, b1, p_cur);                // 7

    // conv2..conv4
    for (int i = 0; i < 3; i++) {
        k_tgemm<<<G2, 256>>>(p_cur, Wm + i * HIDD * HIDD, p_h,
                             ams + i * HIDD, amd + i * HIDD, bm,
                             NN, HIDD, HIDD, HIDD, 0);
        k_aggw<HIDD><<<AGG_B, 256>>>(p_h, bm + i * HIDD, p_cur);
    }

    // mask MLP: m1 via GEMM (bias+tanh epilogue) into g_xn, then tail + gating
    k_tgemm<<<G1, 256>>>(p_cur, mw1, p_xn, a1s, a1d, mb1,
                         NN, 64, HIDD, HIDD, 1);
    k_mask2<<<(NN + 7) / 8, 256>>>(p_cur, p_xn, mw2, mb2, mw3, mb3, mw4, mb4);

    // conv5..conv7
    for (int i = 3; i < 6; i++) {
        k_tgemm<<<G2, 256>>>(p_cur, Wm + i * HIDD * HIDD, p_h,
                             ams + i * HIDD, amd + i * HIDD, bm,
                             NN, HIDD, HIDD, HIDD, 0);
        k_aggw<HIDD><<<AGG_B, 256>>>(p_h, bm + i * HIDD, p_cur);
    }

    // conv8: 128 -> 42, writes final output
    k_tgemm<<<G1, 256>>>(p_cur, W8, p_h, a8s, a8d, b8,
                         NN, FIN, HIDD, HIDD, 0);
    k_aggw<FIN><<<AGG_B, 256>>>(p_h, b8, outp);
}

// round 9
// speedup vs baseline: 1.5388x; 1.0023x over previous
#include <cuda_runtime.h>
#include <math.h>
#include <stdint.h>

#define NN   50000
#define NE   800000
#define ET   (NE + NN)     // edges + self loops
#define FIN  42
#define KPAD 64            // conv1 K padded to 64
#define HIDD 128
#define SCB  ((NN + 255) / 256)   // 196 scan blocks

// ---------------- scratch (device globals; no allocation allowed) -------------
__device__ float g_xn [NN * KPAD];   // padded normalized input; later reused as m1 buffer
__device__ float g_h  [NN * HIDD];
__device__ float g_cur[NN * HIDD];
__device__ float g_hsp[2 * NN];   // per-N-block partial a_s dots
__device__ float g_hdp[2 * NN];   // per-N-block partial a_d dots
__device__ int   g_deg [NN];      // zero at start of every launch (BSS init + k_off reset)
__device__ int   g_off [NN + 1];
__device__ int   g_fill[NN];
__device__ int   g_csr [ET];
__device__ int   g_boff[256];

// ---------------- L1 normalize input (zero-padded to KPAD cols) ---------------
__global__ void k_xn(const float* __restrict__ x) {
    int w = (blockIdx.x * blockDim.x + threadIdx.x) >> 5;
    int lane = threadIdx.x & 31;
    if (w >= NN) return;
    float s = 0.f;
    for (int j = lane; j < FIN; j += 32) s += fabsf(x[w * FIN + j]);
    #pragma unroll
    for (int o = 16; o; o >>= 1) s += __shfl_xor_sync(0xffffffff, s, o);
    float inv = 1.f / fmaxf(s, 1e-12f);
    for (int j = lane; j < KPAD; j += 32)
        g_xn[w * KPAD + j] = (j < FIN) ? x[w * FIN + j] * inv : 0.f;
}

// ---------------- CSR build (by destination) ----------------
__global__ void k_count(const int* __restrict__ ei) {
    int e = blockIdx.x * blockDim.x + threadIdx.x;
    if (e >= ET) return;
    int dst = (e < NE) ? ei[NE + e] : (e - NE);
    atomicAdd(&g_deg[dst], 1);
}

__global__ void k_part() {
    __shared__ int wsum[8];
    int t = threadIdx.x, b = blockIdx.x;
    int node = b * 256 + t;
    int v = (node < NN) ? g_deg[node] : 0;
    #pragma unroll
    for (int o = 16; o; o >>= 1) v += __shfl_xor_sync(0xffffffff, v, o);
    if ((t & 31) == 0) wsum[t >> 5] = v;
    __syncthreads();
    if (t == 0) {
        int s = 0;
        #pragma unroll
        for (int i = 0; i < 8; i++) s += wsum[i];
        g_boff[b] = s;
    }
}

__global__ void k_scanb() {
    __shared__ int sh[256];
    int t = threadIdx.x;
    int v = (t < SCB) ? g_boff[t] : 0;
    sh[t] = v;
    __syncthreads();
    #pragma unroll
    for (int o = 1; o < 256; o <<= 1) {
        int u = (t >= o) ? sh[t - o] : 0;
        __syncthreads();
        sh[t] += u;
        __syncthreads();
    }
    if (t < SCB) g_boff[t] = sh[t] - v;
    if (t == 255) g_off[NN] = sh[255];
}

__global__ void k_off() {
    __shared__ int sh[256];
    int t = threadIdx.x, b = blockIdx.x;
    int node = b * 256 + t;
    int d = (node < NN) ? g_deg[node] : 0;
    sh[t] = d;
    __syncthreads();
    #pragma unroll
    for (int o = 1; o < 256; o <<= 1) {
        int u = (t >= o) ? sh[t - o] : 0;
        __syncthreads();
        sh[t] += u;
        __syncthreads();
    }
    if (node < NN) {
        int off = g_boff[b] + sh[t] - d;
        g_off[node] = off;
        g_fill[node] = off;
        g_deg[node] = 0;          // reset for the next kernel_launch call
    }
}

__global__ void k_scatter(const int* __restrict__ ei) {
    int e = blockIdx.x * blockDim.x + threadIdx.x;
    if (e >= ET) return;
    int src, dst;
    if (e < NE) { src = ei[e]; dst = ei[NE + e]; }
    else        { src = e - NE; dst = e - NE; }
    int pos = atomicAdd(&g_fill[dst], 1);
    g_csr[pos] = src;
}

// -------- tf32 tensor-core GEMM, 128x64 tile, double-buffered pipeline --------
// mode 0: C = A@B, plus fused dots g_hsp/g_hdp[r] = C_row . as_/ad_
// mode 1: C = tanh(A@B + bias), no dots
__device__ __forceinline__ uint32_t f2tf(float f) {
    uint32_t u; asm("cvt.rna.tf32.f32 %0, %1;" : "=r"(u) : "f"(f)); return u;
}
__device__ __forceinline__ void mma_tf32(float c[4],
    uint32_t a0, uint32_t a1, uint32_t a2, uint32_t a3,
    uint32_t b0, uint32_t b1)
{
    asm volatile(
        "mma.sync.aligned.m16n8k8.row.col.f32.tf32.tf32.f32 "
        "{%0,%1,%2,%3}, {%4,%5,%6,%7}, {%8,%9}, {%0,%1,%2,%3};"
        : "+f"(c[0]), "+f"(c[1]), "+f"(c[2]), "+f"(c[3])
        : "r"(a0), "r"(a1), "r"(a2), "r"(a3), "r"(b0), "r"(b1));
}

#define ASTR 36
#define BSTR 72
#define ABUF (128 * ASTR)
#define BBUF (32 * BSTR)
#define SMEM_DYN (2 * (ABUF + BBUF) * 4)   // 55296 bytes

__global__ void __launch_bounds__(256, 2) k_tgemm(
    const float* __restrict__ A, const float* __restrict__ B,
    float* __restrict__ C,
    const float* __restrict__ as_, const float* __restrict__ ad_,
    const float* __restrict__ bias,
    int M, int N, int K, int KB, int mode)
{
    extern __shared__ uint32_t dynsm[];
    uint32_t* AsB = dynsm;             // [2][ABUF]
    uint32_t* BsB = dynsm + 2 * ABUF;  // [2][BBUF]
    __shared__ float sa[64], sd[64];
    int tid = threadIdx.x;
    int lane = tid & 31, wid = tid >> 5;      // warp owns rows wid*16..wid*16+15
    int q = lane >> 2, p = lane & 3;
    int row0 = blockIdx.x * 128;
    int n0 = blockIdx.y * 64;
    if (tid < 64) {
        int c = n0 + tid;
        if (mode == 0) {
            sa[tid] = (c < N) ? as_[c] : 0.f;
            sd[tid] = (c < N) ? ad_[c] : 0.f;
        } else {
            sa[tid] = (c < N) ? bias[c] : 0.f;
        }
    }
    float acc[8][4];
    #pragma unroll
    for (int j = 0; j < 8; j++)
        #pragma unroll
        for (int r = 0; r < 4; r++) acc[j][r] = 0.f;

    const bool vecN = ((N & 3) == 0);
    const int nc = K >> 5;                    // K is 64 or 128
    float4 ra[4];
    float4 rb[2];
    float  rbs[8];

#define LDG_CHUNK(K0)                                                          \
    {                                                                          \
        int _k0 = (K0);                                                        \
        _Pragma("unroll")                                                      \
        for (int l = 0; l < 4; l++) {                                          \
            int slot = tid + l * 256;                                          \
            int r = slot >> 3, kg = slot & 7;                                  \
            int gr = row0 + r;                                                 \
            ra[l] = make_float4(0.f, 0.f, 0.f, 0.f);                           \
            if (gr < M) ra[l] = *(const float4*)&A[(long)gr * K + _k0 + kg * 4];\
        }                                                                      \
        if (vecN) {                                                            \
            _Pragma("unroll")                                                  \
            for (int l = 0; l < 2; l++) {                                      \
                int slot = tid + l * 256;                                      \
                int k = slot >> 4, ng = slot & 15;                             \
                rb[l] = make_float4(0.f, 0.f, 0.f, 0.f);                       \
                if (_k0 + k < KB)                                              \
                    rb[l] = *(const float4*)&B[(long)(_k0 + k) * N + n0 + ng * 4];\
            }                                                                  \
        } else {                                                               \
            _Pragma("unroll")                                                  \
            for (int l = 0; l < 8; l++) {                                      \
                int slot = tid + l * 256;                                      \
                int k = slot >> 6, n = slot & 63;                              \
                rbs[l] = (_k0 + k < KB && n0 + n < N)                          \
                       ? B[(long)(_k0 + k) * N + n0 + n] : 0.f;                \
            }                                                                  \
        }                                                                      \
    }

#define STS_CHUNK(BUF)                                                         \
    {                                                                          \
        uint32_t* _As = AsB + (BUF) * ABUF;                                    \
        uint32_t* _Bs = BsB + (BUF) * BBUF;                                    \
        _Pragma("unroll")                                                      \
        for (int l = 0; l < 4; l++) {                                          \
            int slot = tid + l * 256;                                          \
            int r = slot >> 3, kg = slot & 7;                                  \
            uint32_t* d = &_As[r * ASTR + kg * 4];                             \
            d[0] = f2tf(ra[l].x); d[1] = f2tf(ra[l].y);                        \
            d[2] = f2tf(ra[l].z); d[3] = f2tf(ra[l].w);                        \
        }                                                                      \
        if (vecN) {                                                            \
            _Pragma("unroll")                                                  \
            for (int l = 0; l < 2; l++) {                                      \
                int slot = tid + l * 256;                                      \
                int k = slot >> 4, ng = slot & 15;                             \
                uint32_t* d = &_Bs[k * BSTR + ng * 4];                         \
                d[0] = f2tf(rb[l].x); d[1] = f2tf(rb[l].y);                    \
                d[2] = f2tf(rb[l].z); d[3] = f2tf(rb[l].w);                    \
            }                                                                  \
        } else {                                                               \
            _Pragma("unroll")                                                  \
            for (int l = 0; l < 8; l++) {                                      \
                int slot = tid + l * 256;                                      \
                int k = slot >> 6, n = slot & 63;                              \
                _Bs[k * BSTR + n] = f2tf(rbs[l]);                              \
            }                                                                  \
        }                                                                      \
    }

    // prologue: stage chunk 0 into buffer 0
    LDG_CHUNK(0);
    STS_CHUNK(0);

    for (int c = 0; c < nc; c++) {
        __syncthreads();                       // buffer c&1 ready (and sa/sd on c==0)
        int buf = c & 1;
        if (c + 1 < nc) LDG_CHUNK((c + 1) << 5);   // global loads only — overlap with MMA
        uint32_t* As = AsB + buf * ABUF;
        uint32_t* Bs = BsB + buf * BBUF;
        #pragma unroll
        for (int ks = 0; ks < 4; ks++) {
            int kb = ks * 8;
            int r = wid * 16 + q;
            uint32_t a0 = As[r * ASTR + kb + p];
            uint32_t a1 = As[(r + 8) * ASTR + kb + p];
            uint32_t a2 = As[r * ASTR + kb + p + 4];
            uint32_t a3 = As[(r + 8) * ASTR + kb + p + 4];
            #pragma unroll
            for (int fn = 0; fn < 8; fn++) {
                int n = fn * 8 + q;
                uint32_t b0 = Bs[(kb + p) * BSTR + n];
                uint32_t b1 = Bs[(kb + p + 4) * BSTR + n];
                mma_tf32(acc[fn], a0, a1, a2, a3, b0, b1);
            }
        }
        if (c + 1 < nc) STS_CHUNK(buf ^ 1);    // visible after next loop's sync
    }

    if (mode == 0) {
        // ---- epilogue: store C + per-warp fused a_s/a_d row dots ----
        #pragma unroll
        for (int ro = 0; ro < 2; ro++) {
            int rl = wid * 16 + q + ro * 8;
            int r = row0 + rl;
            float s = 0.f, d = 0.f;
            #pragma unroll
            for (int fn = 0; fn < 8; fn++) {
                int cl = fn * 8 + p * 2;
                float v0 = acc[fn][ro * 2 + 0];
                float v1 = acc[fn][ro * 2 + 1];
                s += v0 * sa[cl] + v1 * sa[cl + 1];
                d += v0 * sd[cl] + v1 * sd[cl + 1];
                int c = n0 + cl;
                if (r < M) {
                    if (c + 1 < N) *(float2*)&C[(long)r * N + c] = make_float2(v0, v1);
                    else if (c < N) C[(long)r * N + c] = v0;
                }
            }
            s += __shfl_xor_sync(0xffffffff, s, 1);
            s += __shfl_xor_sync(0xffffffff, s, 2);
            d += __shfl_xor_sync(0xffffffff, d, 1);
            d += __shfl_xor_sync(0xffffffff, d, 2);
            if (p == 0 && r < M) {
                g_hsp[blockIdx.y * NN + r] = s;
                g_hdp[blockIdx.y * NN + r] = d;
            }
        }
    } else {
        // ---- epilogue: C = tanh(acc + bias) ----
        #pragma unroll
        for (int ro = 0; ro < 2; ro++) {
            int rl = wid * 16 + q + ro * 8;
            int r = row0 + rl;
            if (r >= M) continue;
            #pragma unroll
            for (int fn = 0; fn < 8; fn++) {
                int cl = fn * 8 + p * 2;
                int c = n0 + cl;
                float v0 = tanhf(acc[fn][ro * 2 + 0] + sa[cl]);
                float v1 = tanhf(acc[fn][ro * 2 + 1] + sa[cl + 1]);
                if (c + 1 < N) *(float2*)&C[(long)r * N + c] = make_float2(v0, v1);
                else if (c < N) C[(long)r * N + c] = v0;
            }
        }
    }
#undef LDG_CHUNK
#undef STS_CHUNK
}

// ------------- warp-per-node softmax aggregation (no barriers) ---------------
template<int F>
__global__ void __launch_bounds__(256) k_aggw(
    const float* __restrict__ h, const float* __restrict__ bias,
    float* __restrict__ out)
{
    constexpr bool TWO = (F == 128);
    int w = (blockIdx.x * blockDim.x + threadIdx.x) >> 5;
    int lane = threadIdx.x & 31;
    if (w >= NN) return;
    int beg = g_off[w], end = g_off[w + 1];
    int deg = end - beg;
    int nk = (deg + 31) >> 5;
    float hdv = TWO ? (g_hdp[w] + g_hdp[NN + w]) : g_hdp[w];

    float cW[4]; int cS[4];
    float mymax = -INFINITY;
    for (int c = 0; c < nk; c++) {
        int i = (c << 5) + lane;
        float e = -INFINITY; int s = 0;
        if (i < deg) {
            s = g_csr[beg + i];
            float hs = TWO ? (g_hsp[s] + g_hsp[NN + s]) : g_hsp[s];
            float z = hs + hdv;
            e = (z > 0.f) ? z : 0.2f * z;
        }
        if (c < 4) { cS[c] = s; cW[c] = e; }
        mymax = fmaxf(mymax, e);
    }
    #pragma unroll
    for (int o = 16; o; o >>= 1) mymax = fmaxf(mymax, __shfl_xor_sync(0xffffffff, mymax, o));
    float M = mymax;

    float myS = 0.f;
    for (int c = 0; c < nk; c++) {
        float e;
        if (c < 4) e = cW[c];
        else {
            int i = (c << 5) + lane;
            e = -INFINITY;
            if (i < deg) {
                int s = g_csr[beg + i];
                float hs = TWO ? (g_hsp[s] + g_hsp[NN + s]) : g_hsp[s];
                float z = hs + hdv;
                e = (z > 0.f) ? z : 0.2f * z;
            }
        }
        float wgt = __expf(e - M);
        if (c < 4) cW[c] = wgt;
        myS += wgt;
    }
    #pragma unroll
    for (int o = 16; o; o >>= 1) myS += __shfl_xor_sync(0xffffffff, myS, o);
    float invS = 1.f / (myS + 1e-16f);

    if constexpr (F == 128) {
        const float4* h4 = (const float4*)h;
        float4 acc = make_float4(0.f, 0.f, 0.f, 0.f);
        for (int c = 0; c < nk; c++) {
            int cnt = min(32, deg - (c << 5));
            int s; float wgt;
            if (c < 4) { s = cS[c]; wgt = cW[c]; }
            else {
                int i = (c << 5) + lane;
                s = 0; wgt = 0.f;
                if (i < deg) {
                    s = g_csr[beg + i];
                    float hs = g_hsp[s] + g_hsp[NN + s];
                    float z = hs + hdv;
                    float e = (z > 0.f) ? z : 0.2f * z;
                    wgt = __expf(e - M);
                }
            }
            int k = 0;
            for (; k + 4 <= cnt; k += 4) {
                int   s0 = __shfl_sync(0xffffffff, s, k);
                int   s1 = __shfl_sync(0xffffffff, s, k + 1);
                int   s2 = __shfl_sync(0xffffffff, s, k + 2);
                int   s3 = __shfl_sync(0xffffffff, s, k + 3);
                float w0 = __shfl_sync(0xffffffff, wgt, k);
                float w1 = __shfl_sync(0xffffffff, wgt, k + 1);
                float w2 = __shfl_sync(0xffffffff, wgt, k + 2);
                float w3 = __shfl_sync(0xffffffff, wgt, k + 3);
                float4 v0 = h4[s0 * 32 + lane];
                float4 v1 = h4[s1 * 32 + lane];
                float4 v2 = h4[s2 * 32 + lane];
                float4 v3 = h4[s3 * 32 + lane];
                acc.x += w0 * v0.x + w1 * v1.x + w2 * v2.x + w3 * v3.x;
                acc.y += w0 * v0.y + w1 * v1.y + w2 * v2.y + w3 * v3.y;
                acc.z += w0 * v0.z + w1 * v1.z + w2 * v2.z + w3 * v3.z;
                acc.w += w0 * v0.w + w1 * v1.w + w2 * v2.w + w3 * v3.w;
            }
            for (; k < cnt; k++) {
                int   sk = __shfl_sync(0xffffffff, s, k);
                float wk = __shfl_sync(0xffffffff, wgt, k);
                float4 v = h4[sk * 32 + lane];
                acc.x += wk * v.x; acc.y += wk * v.y;
                acc.z += wk * v.z; acc.w += wk * v.w;
            }
        }
        const float4* b4 = (const float4*)bias;
        float4 bb = b4[lane];
        float4 o;
        o.x = tanhf(acc.x * invS + bb.x);
        o.y = tanhf(acc.y * invS + bb.y);
        o.z = tanhf(acc.z * invS + bb.z);
        o.w = tanhf(acc.w * invS + bb.w);
        ((float4*)out)[w * 32 + lane] = o;
    } else {
        float a0 = 0.f, a1 = 0.f;
        int j0 = lane, j1 = lane + 32;
        for (int c = 0; c < nk; c++) {
            int cnt = min(32, deg - (c << 5));
            int s; float wgt;
            if (c < 4) { s = cS[c]; wgt = cW[c]; }
            else {
                int i = (c << 5) + lane;
                s = 0; wgt = 0.f;
                if (i < deg) {
                    s = g_csr[beg + i];
                    float hs = g_hsp[s];
                    float z = hs + hdv;
                    float e = (z > 0.f) ? z : 0.2f * z;
                    wgt = __expf(e - M);
                }
            }
            for (int k = 0; k < cnt; k++) {
                int   sk = __shfl_sync(0xffffffff, s, k);
                float wk = __shfl_sync(0xffffffff, wgt, k);
                const float* row = h + (long)sk * F;
                a0 += wk * row[j0];
                if (j1 < F) a1 += wk * row[j1];
            }
        }
        out[(long)w * F + j0] = tanhf(a0 * invS + bias[j0]);
        if (j1 < F) out[(long)w * F + j1] = tanhf(a1 * invS + bias[j1]);
    }
}

// -------- mask MLP tail (m2..m4) + soft-argmax gating, warp per node ---------
// m1 = tanh(latent @ mw1 + mb1) precomputed by k_tgemm mode 1 into g_xn.
__global__ void __launch_bounds__(256) k_mask2(
    float* __restrict__ cur, const float* __restrict__ m1,
    const float* __restrict__ mw2, const float* __restrict__ mb2,
    const float* __restrict__ mw3, const float* __restrict__ mb3,
    const float* __restrict__ mw4, const float* __restrict__ mb4)
{
    __shared__ float w2[64 * 16];
    __shared__ float w3[16 * 16];
    __shared__ float w4[32];
    __shared__ float bb2[16], bb3[16], bb4[2];
    int t = threadIdx.x;
    for (int i = t; i < 64 * 16; i += 256) w2[i] = mw2[i];
    if (t < 256 && t < 16 * 16) w3[t] = mw3[t];
    if (t < 32) w4[t] = mw4[t];
    if (t < 16) { bb2[t] = mb2[t]; bb3[t] = mb3[t]; }
    if (t < 2)  bb4[t] = mb4[t];
    __syncthreads();

    int n = blockIdx.x * 8 + (t >> 5);
    int lane = t & 31;
    if (n >= NN) return;

    float a0 = m1[(long)n * 64 + lane];
    float a1 = m1[(long)n * 64 + lane + 32];

    int l16 = lane & 15;
    float s2 = bb2[l16];
    #pragma unroll
    for (int k = 0; k < 32; k++)
        s2 += __shfl_sync(0xffffffff, a0, k) * w2[k * 16 + l16];
    #pragma unroll
    for (int k = 0; k < 32; k++)
        s2 += __shfl_sync(0xffffffff, a1, k) * w2[(k + 32) * 16 + l16];
    s2 = tanhf(s2);

    float s3 = bb3[l16];
    #pragma unroll
    for (int k = 0; k < 16; k++)
        s3 += __shfl_sync(0xffffffff, s2, k) * w3[k * 16 + l16];
    s3 = tanhf(s3);

    int l2 = lane & 1;
    float o = bb4[l2];
    #pragma unroll
    for (int k = 0; k < 16; k++)
        o += __shfl_sync(0xffffffff, s3, k) * w4[k * 2 + l2];
    float o0 = __shfl_sync(0xffffffff, o, 0);
    float o1 = __shfl_sync(0xffffffff, o, 1);
    float mx = fmaxf(o0, o1);
    float e0 = expf(o0 - mx), e1 = expf(o1 - mx);
    float sa = e1 / (e0 + e1);

    float4* c4 = (float4*)&cur[(long)n * 128];
    float4 v = c4[lane];
    v.x *= sa; v.y *= sa; v.z *= sa; v.w *= sa;
    c4[lane] = v;
}

// ---------------- orchestration ----------------
extern "C" void kernel_launch(void* const* d_in, const int* in_sizes, int n_in,
                              void* d_out, int out_size)
{
    const float* x   = (const float*)d_in[0];
    const int*   ei  = (const int*)  d_in[1];
    const float* W1  = (const float*)d_in[4];
    const float* a1s = (const float*)d_in[5];
    const float* a1d = (const float*)d_in[6];
    const float* b1  = (const float*)d_in[7];
    const float* Wm  = (const float*)d_in[8];
    const float* ams = (const float*)d_in[9];
    const float* amd = (const float*)d_in[10];
    const float* bm  = (const float*)d_in[11];
    const float* W8  = (const float*)d_in[12];
    const float* a8s = (const float*)d_in[13];
    const float* a8d = (const float*)d_in[14];
    const float* b8  = (const float*)d_in[15];
    const float* mw1 = (const float*)d_in[16];
    const float* mb1 = (const float*)d_in[17];
    const float* mw2 = (const float*)d_in[18];
    const float* mb2 = (const float*)d_in[19];
    const float* mw3 = (const float*)d_in[20];
    const float* mb3 = (const float*)d_in[21];
    const float* mw4 = (const float*)d_in[22];
    const float* mb4 = (const float*)d_in[23];
    float* outp = (float*)d_out;

    void *pv;
    cudaGetSymbolAddress(&pv, g_xn);   float* p_xn  = (float*)pv;
    cudaGetSymbolAddress(&pv, g_h);    float* p_h   = (float*)pv;
    cudaGetSymbolAddress(&pv, g_cur);  float* p_cur = (float*)pv;

    static bool attr_done = false;
    if (!attr_done) {
        cudaFuncSetAttribute(k_tgemm, cudaFuncAttributeMaxDynamicSharedMemorySize, SMEM_DYN);
        attr_done = true;
    }

    const int EB = (ET + 255) / 256;
    const int GEMM_B = (NN + 127) / 128;       // 391
    const dim3 G2(GEMM_B, 2);                  // N=128 layers
    const dim3 G1(GEMM_B, 1);                  // N<=64 layers
    const int WARP8  = (NN + 7) / 8;
    const int AGG_B  = (NN * 32 + 255) / 256;  // 6250

    // launch order keeps conv1's k_tgemm at index 3 (ncu capture slot)
    k_xn<<<WARP8, 256>>>(x);                                     // 0
    k_count<<<EB, 256>>>(ei);                                    // 1
    k_part<<<SCB, 256>>>();                                      // 2
    k_tgemm<<<G2, 256, SMEM_DYN>>>(p_xn, W1, p_h, a1s, a1d, b1,
                         NN, HIDD, KPAD, FIN, 0);                // 3  <-- profiled
    k_scanb<<<1, 256>>>();                                       // 4
    k_off<<<SCB, 256>>>();                                       // 5
    k_scatter<<<EB, 256>>>(ei);                                  // 6
    k_aggw<HIDD><<<AGG_B, 256>>>(p_h, b1, p_cur);                // 7

    // conv2..conv4
    for (int i = 0; i < 3; i++) {
        k_tgemm<<<G2, 256, SMEM_DYN>>>(p_cur, Wm + i * HIDD * HIDD, p_h,
                             ams + i * HIDD, amd + i * HIDD, bm,
                             NN, HIDD, HIDD, HIDD, 0);
        k_aggw<HIDD><<<AGG_B, 256>>>(p_h, bm + i * HIDD, p_cur);
    }

    // mask MLP: m1 via GEMM (bias+tanh epilogue) into g_xn, then tail + gating
    k_tgemm<<<G1, 256, SMEM_DYN>>>(p_cur, mw1, p_xn, a1s, a1d, mb1,
                         NN, 64, HIDD, HIDD, 1);
    k_mask2<<<(NN + 7) / 8, 256>>>(p_cur, p_xn, mw2, mb2, mw3, mb3, mw4, mb4);

    // conv5..conv7
    for (int i = 3; i < 6; i++) {
        k_tgemm<<<G2, 256, SMEM_DYN>>>(p_cur, Wm + i * HIDD * HIDD, p_h,
                             ams + i * HIDD, amd + i * HIDD, bm,
                             NN, HIDD, HIDD, HIDD, 0);
        k_aggw<HIDD><<<AGG_B, 256>>>(p_h, bm + i * HIDD, p_cur);
    }

    // conv8: 128 -> 42, writes final output
    k_tgemm<<<G1, 256, SMEM_DYN>>>(p_cur, W8, p_h, a8s, a8d, b8,
                         NN, FIN, HIDD, HIDD, 0);
    k_aggw<FIN><<<AGG_B, 256>>>(p_h, b8, outp);
}

// round 11
// speedup vs baseline: 1.5705x; 1.0206x over previous
#include <cuda_runtime.h>
#include <cuda_fp16.h>
#include <math.h>
#include <stdint.h>

#define NN   50000
#define NE   800000
#define ET   (NE + NN)     // edges + self loops
#define FIN  42
#define KPAD 64            // conv1 K padded to 64
#define HIDD 128
#define SCB  ((NN + 255) / 256)   // 196 scan blocks

// ---------------- scratch (device globals; no allocation allowed) -------------
__device__ float   g_xn [NN * KPAD];  // padded normalized input; later reused as m1 buffer
__device__ __half2 g_h2 [NN * 64];    // GEMM output h in fp16 (max 128 cols)
__device__ float   g_cur[NN * HIDD];
__device__ float   g_hsp[2 * NN];     // per-N-block partial a_s dots
__device__ float   g_hdp[2 * NN];     // per-N-block partial a_d dots
__device__ int     g_deg [NN];
__device__ int     g_off [NN + 1];
__device__ int     g_fill[NN];
__device__ int     g_csr [ET];
__device__ int     g_boff[256];

// ---------------- L1 normalize input (zero-padded to KPAD cols) ---------------
__global__ void k_xn(const float* __restrict__ x) {
    int w = (blockIdx.x * blockDim.x + threadIdx.x) >> 5;
    int lane = threadIdx.x & 31;
    if (w >= NN) return;
    float s = 0.f;
    for (int j = lane; j < FIN; j += 32) s += fabsf(x[w * FIN + j]);
    #pragma unroll
    for (int o = 16; o; o >>= 1) s += __shfl_xor_sync(0xffffffff, s, o);
    float inv = 1.f / fmaxf(s, 1e-12f);
    for (int j = lane; j < KPAD; j += 32)
        g_xn[w * KPAD + j] = (j < FIN) ? x[w * FIN + j] * inv : 0.f;
}

// ---------------- CSR build (by destination) ----------------
__global__ void k_count(const int* __restrict__ ei) {
    int e = blockIdx.x * blockDim.x + threadIdx.x;
    if (e >= ET) return;
    int dst = (e < NE) ? ei[NE + e] : (e - NE);
    atomicAdd(&g_deg[dst], 1);
}

__global__ void k_part() {
    __shared__ int wsum[8];
    int t = threadIdx.x, b = blockIdx.x;
    int node = b * 256 + t;
    int v = (node < NN) ? g_deg[node] : 0;
    #pragma unroll
    for (int o = 16; o; o >>= 1) v += __shfl_xor_sync(0xffffffff, v, o);
    if ((t & 31) == 0) wsum[t >> 5] = v;
    __syncthreads();
    if (t == 0) {
        int s = 0;
        #pragma unroll
        for (int i = 0; i < 8; i++) s += wsum[i];
        g_boff[b] = s;
    }
}

__global__ void k_scanb() {
    __shared__ int sh[256];
    int t = threadIdx.x;
    int v = (t < SCB) ? g_boff[t] : 0;
    sh[t] = v;
    __syncthreads();
    #pragma unroll
    for (int o = 1; o < 256; o <<= 1) {
        int u = (t >= o) ? sh[t - o] : 0;
        __syncthreads();
        sh[t] += u;
        __syncthreads();
    }
    if (t < SCB) g_boff[t] = sh[t] - v;
    if (t == 255) g_off[NN] = sh[255];
}

__global__ void k_off() {
    __shared__ int sh[256];
    int t = threadIdx.x, b = blockIdx.x;
    int node = b * 256 + t;
    int d = (node < NN) ? g_deg[node] : 0;
    sh[t] = d;
    __syncthreads();
    #pragma unroll
    for (int o = 1; o < 256; o <<= 1) {
        int u = (t >= o) ? sh[t - o] : 0;
        __syncthreads();
        sh[t] += u;
        __syncthreads();
    }
    if (node < NN) {
        int off = g_boff[b] + sh[t] - d;
        g_off[node] = off;
        g_fill[node] = off;
        g_deg[node] = 0;          // reset for the next kernel_launch call
    }
}

__global__ void k_scatter(const int* __restrict__ ei) {
    int e = blockIdx.x * blockDim.x + threadIdx.x;
    if (e >= ET) return;
    int src, dst;
    if (e < NE) { src = ei[e]; dst = ei[NE + e]; }
    else        { src = e - NE; dst = e - NE; }
    int pos = atomicAdd(&g_fill[dst], 1);
    g_csr[pos] = src;
}

// -------- tf32 tensor-core GEMM, 128x64 tile, double-buffered pipeline --------
// mode 0: C(half2) = A@B, plus fused dots g_hsp/g_hdp[r] = C_row . as_/ad_
// mode 1: C(float) = tanh(A@B + bias), no dots
__device__ __forceinline__ uint32_t f2tf(float f) {
    uint32_t u; asm("cvt.rna.tf32.f32 %0, %1;" : "=r"(u) : "f"(f)); return u;
}
__device__ __forceinline__ void mma_tf32(float c[4],
    uint32_t a0, uint32_t a1, uint32_t a2, uint32_t a3,
    uint32_t b0, uint32_t b1)
{
    asm volatile(
        "mma.sync.aligned.m16n8k8.row.col.f32.tf32.tf32.f32 "
        "{%0,%1,%2,%3}, {%4,%5,%6,%7}, {%8,%9}, {%0,%1,%2,%3};"
        : "+f"(c[0]), "+f"(c[1]), "+f"(c[2]), "+f"(c[3])
        : "r"(a0), "r"(a1), "r"(a2), "r"(a3), "r"(b0), "r"(b1));
}

#define ASTR 36
#define BSTR 72
#define ABUF (128 * ASTR)
#define BBUF (32 * BSTR)
#define SMEM_DYN (2 * (ABUF + BBUF) * 4)   // 55296 bytes

__global__ void __launch_bounds__(256, 2) k_tgemm(
    const float* __restrict__ A, const float* __restrict__ B,
    void* __restrict__ Cout,
    const float* __restrict__ as_, const float* __restrict__ ad_,
    const float* __restrict__ bias,
    int M, int N, int K, int KB, int mode)
{
    extern __shared__ uint32_t dynsm[];
    uint32_t* AsB = dynsm;             // [2][ABUF]
    uint32_t* BsB = dynsm + 2 * ABUF;  // [2][BBUF]
    __shared__ float sa[64], sd[64];
    int tid = threadIdx.x;
    int lane = tid & 31, wid = tid >> 5;      // warp owns rows wid*16..wid*16+15
    int q = lane >> 2, p = lane & 3;
    int row0 = blockIdx.x * 128;
    int n0 = blockIdx.y * 64;
    if (tid < 64) {
        int c = n0 + tid;
        if (mode == 0) {
            sa[tid] = (c < N) ? as_[c] : 0.f;
            sd[tid] = (c < N) ? ad_[c] : 0.f;
        } else {
            sa[tid] = (c < N) ? bias[c] : 0.f;
        }
    }
    float acc[8][4];
    #pragma unroll
    for (int j = 0; j < 8; j++)
        #pragma unroll
        for (int r = 0; r < 4; r++) acc[j][r] = 0.f;

    const bool vecN = ((N & 3) == 0);
    const int nc = K >> 5;                    // K is 64 or 128
    float4 ra[4];
    float4 rb[2];
    float  rbs[8];

#define LDG_CHUNK(K0)                                                          \
    {                                                                          \
        int _k0 = (K0);                                                        \
        _Pragma("unroll")                                                      \
        for (int l = 0; l < 4; l++) {                                          \
            int slot = tid + l * 256;                                          \
            int r = slot >> 3, kg = slot & 7;                                  \
            int gr = row0 + r;                                                 \
            ra[l] = make_float4(0.f, 0.f, 0.f, 0.f);                           \
            if (gr < M) ra[l] = *(const float4*)&A[(long)gr * K + _k0 + kg * 4];\
        }                                                                      \
        if (vecN) {                                                            \
            _Pragma("unroll")                                                  \
            for (int l = 0; l < 2; l++) {                                      \
                int slot = tid + l * 256;                                      \
                int k = slot >> 4, ng = slot & 15;                             \
                rb[l] = make_float4(0.f, 0.f, 0.f, 0.f);                       \
                if (_k0 + k < KB)                                              \
                    rb[l] = *(const float4*)&B[(long)(_k0 + k) * N + n0 + ng * 4];\
            }                                                                  \
        } else {                                                               \
            _Pragma("unroll")                                                  \
            for (int l = 0; l < 8; l++) {                                      \
                int slot = tid + l * 256;                                      \
                int k = slot >> 6, n = slot & 63;                              \
                rbs[l] = (_k0 + k < KB && n0 + n < N)                          \
                       ? B[(long)(_k0 + k) * N + n0 + n] : 0.f;                \
            }                                                                  \
        }                                                                      \
    }

#define STS_CHUNK(BUF)                                                         \
    {                                                                          \
        uint32_t* _As = AsB + (BUF) * ABUF;                                    \
        uint32_t* _Bs = BsB + (BUF) * BBUF;                                    \
        _Pragma("unroll")                                                      \
        for (int l = 0; l < 4; l++) {                                          \
            int slot = tid + l * 256;                                          \
            int r = slot >> 3, kg = slot & 7;                                  \
            uint32_t* d = &_As[r * ASTR + kg * 4];                             \
            d[0] = f2tf(ra[l].x); d[1] = f2tf(ra[l].y);                        \
            d[2] = f2tf(ra[l].z); d[3] = f2tf(ra[l].w);                        \
        }                                                                      \
        if (vecN) {                                                            \
            _Pragma("unroll")                                                  \
            for (int l = 0; l < 2; l++) {                                      \
                int slot = tid + l * 256;                                      \
                int k = slot >> 4, ng = slot & 15;                             \
                uint32_t* d = &_Bs[k * BSTR + ng * 4];                         \
                d[0] = f2tf(rb[l].x); d[1] = f2tf(rb[l].y);                    \
                d[2] = f2tf(rb[l].z); d[3] = f2tf(rb[l].w);                    \
            }                                                                  \
        } else {                                                               \
            _Pragma("unroll")                                                  \
            for (int l = 0; l < 8; l++) {                                      \
                int slot = tid + l * 256;                                      \
                int k = slot >> 6, n = slot & 63;                              \
                _Bs[k * BSTR + n] = f2tf(rbs[l]);                              \
            }                                                                  \
        }                                                                      \
    }

    // prologue: stage chunk 0 into buffer 0
    LDG_CHUNK(0);
    STS_CHUNK(0);

    for (int c = 0; c < nc; c++) {
        __syncthreads();                       // buffer c&1 ready (and sa/sd on c==0)
        int buf = c & 1;
        if (c + 1 < nc) LDG_CHUNK((c + 1) << 5);   // global loads only — overlap with MMA
        uint32_t* As = AsB + buf * ABUF;
        uint32_t* Bs = BsB + buf * BBUF;
        #pragma unroll
        for (int ks = 0; ks < 4; ks++) {
            int kb = ks * 8;
            int r = wid * 16 + q;
            uint32_t a0 = As[r * ASTR + kb + p];
            uint32_t a1 = As[(r + 8) * ASTR + kb + p];
            uint32_t a2 = As[r * ASTR + kb + p + 4];
            uint32_t a3 = As[(r + 8) * ASTR + kb + p + 4];
            #pragma unroll
            for (int fn = 0; fn < 8; fn++) {
                int n = fn * 8 + q;
                uint32_t b0 = Bs[(kb + p) * BSTR + n];
                uint32_t b1 = Bs[(kb + p + 4) * BSTR + n];
                mma_tf32(acc[fn], a0, a1, a2, a3, b0, b1);
            }
        }
        if (c + 1 < nc) STS_CHUNK(buf ^ 1);    // visible after next loop's sync
    }

    if (mode == 0) {
        // ---- epilogue: store C as half2 + per-warp fused a_s/a_d row dots ----
        __half2* C2 = (__half2*)Cout;
        #pragma unroll
        for (int ro = 0; ro < 2; ro++) {
            int rl = wid * 16 + q + ro * 8;
            int r = row0 + rl;
            float s = 0.f, d = 0.f;
            #pragma unroll
            for (int fn = 0; fn < 8; fn++) {
                int cl = fn * 8 + p * 2;
                float v0 = acc[fn][ro * 2 + 0];
                float v1 = acc[fn][ro * 2 + 1];
                s += v0 * sa[cl] + v1 * sa[cl + 1];
                d += v0 * sd[cl] + v1 * sd[cl + 1];
                int c = n0 + cl;
                if (r < M && c + 1 < N)
                    C2[((long)r * N + c) >> 1] = __floats2half2_rn(v0, v1);
            }
            s += __shfl_xor_sync(0xffffffff, s, 1);
            s += __shfl_xor_sync(0xffffffff, s, 2);
            d += __shfl_xor_sync(0xffffffff, d, 1);
            d += __shfl_xor_sync(0xffffffff, d, 2);
            if (p == 0 && r < M) {
                g_hsp[blockIdx.y * NN + r] = s;
                g_hdp[blockIdx.y * NN + r] = d;
            }
        }
    } else {
        // ---- epilogue: C(float) = tanh(acc + bias) ----
        float* Cf = (float*)Cout;
        #pragma unroll
        for (int ro = 0; ro < 2; ro++) {
            int rl = wid * 16 + q + ro * 8;
            int r = row0 + rl;
            if (r >= M) continue;
            #pragma unroll
            for (int fn = 0; fn < 8; fn++) {
                int cl = fn * 8 + p * 2;
                int c = n0 + cl;
                float v0 = tanhf(acc[fn][ro * 2 + 0] + sa[cl]);
                float v1 = tanhf(acc[fn][ro * 2 + 1] + sa[cl + 1]);
                if (c + 1 < N) *(float2*)&Cf[(long)r * N + c] = make_float2(v0, v1);
                else if (c < N) Cf[(long)r * N + c] = v0;
            }
        }
    }
#undef LDG_CHUNK
#undef STS_CHUNK
}

// ------------- warp-per-node softmax aggregation (fp16 gather) ---------------
template<int F>
__global__ void __launch_bounds__(256) k_aggw(
    const __half2* __restrict__ h2, const float* __restrict__ bias,
    float* __restrict__ out)
{
    constexpr bool TWO = (F == 128);
    constexpr int RSTR = F / 2;               // half2 per row
    int w = (blockIdx.x * blockDim.x + threadIdx.x) >> 5;
    int lane = threadIdx.x & 31;
    if (w >= NN) return;
    int beg = g_off[w], end = g_off[w + 1];
    int deg = end - beg;
    int nk = (deg + 31) >> 5;
    float hdv = TWO ? (g_hdp[w] + g_hdp[NN + w]) : g_hdp[w];

    float cW[4]; int cS[4];
    float mymax = -INFINITY;
    for (int c = 0; c < nk; c++) {
        int i = (c << 5) + lane;
        float e = -INFINITY; int s = 0;
        if (i < deg) {
            s = g_csr[beg + i];
            float hs = TWO ? (g_hsp[s] + g_hsp[NN + s]) : g_hsp[s];
            float z = hs + hdv;
            e = (z > 0.f) ? z : 0.2f * z;
        }
        if (c < 4) { cS[c] = s; cW[c] = e; }
        mymax = fmaxf(mymax, e);
    }
    #pragma unroll
    for (int o = 16; o; o >>= 1) mymax = fmaxf(mymax, __shfl_xor_sync(0xffffffff, mymax, o));
    float M = mymax;

    float myS = 0.f;
    for (int c = 0; c < nk; c++) {
        float e;
        if (c < 4) e = cW[c];
        else {
            int i = (c << 5) + lane;
            e = -INFINITY;
            if (i < deg) {
                int s = g_csr[beg + i];
                float hs = TWO ? (g_hsp[s] + g_hsp[NN + s]) : g_hsp[s];
                float z = hs + hdv;
                e = (z > 0.f) ? z : 0.2f * z;
            }
        }
        float wgt = __expf(e - M);
        if (c < 4) cW[c] = wgt;
        myS += wgt;
    }
    #pragma unroll
    for (int o = 16; o; o >>= 1) myS += __shfl_xor_sync(0xffffffff, myS, o);
    float invS = 1.f / (myS + 1e-16f);

    if constexpr (F == 128) {
        float4 acc = make_float4(0.f, 0.f, 0.f, 0.f);
        for (int c = 0; c < nk; c++) {
            int cnt = min(32, deg - (c << 5));
            int s; float wgt;
            if (c < 4) { s = cS[c]; wgt = cW[c]; }
            else {
                int i = (c << 5) + lane;
                s = 0; wgt = 0.f;
                if (i < deg) {
                    s = g_csr[beg + i];
                    float hs = g_hsp[s] + g_hsp[NN + s];
                    float z = hs + hdv;
                    float e = (z > 0.f) ? z : 0.2f * z;
                    wgt = __expf(e - M);
                }
            }
            int k = 0;
            for (; k + 4 <= cnt; k += 4) {
                int   s0 = __shfl_sync(0xffffffff, s, k);
                int   s1 = __shfl_sync(0xffffffff, s, k + 1);
                int   s2 = __shfl_sync(0xffffffff, s, k + 2);
                int   s3 = __shfl_sync(0xffffffff, s, k + 3);
                float w0 = __shfl_sync(0xffffffff, wgt, k);
                float w1 = __shfl_sync(0xffffffff, wgt, k + 1);
                float w2 = __shfl_sync(0xffffffff, wgt, k + 2);
                float w3 = __shfl_sync(0xffffffff, wgt, k + 3);
                uint2 u0 = ((const uint2*)(h2 + (long)s0 * RSTR))[lane];
                uint2 u1 = ((const uint2*)(h2 + (long)s1 * RSTR))[lane];
                uint2 u2 = ((const uint2*)(h2 + (long)s2 * RSTR))[lane];
                uint2 u3 = ((const uint2*)(h2 + (long)s3 * RSTR))[lane];
                float2 a0 = __half22float2(*(__half2*)&u0.x);
                float2 b0 = __half22float2(*(__half2*)&u0.y);
                float2 a1 = __half22float2(*(__half2*)&u1.x);
                float2 b1 = __half22float2(*(__half2*)&u1.y);
                float2 a2 = __half22float2(*(__half2*)&u2.x);
                float2 b2 = __half22float2(*(__half2*)&u2.y);
                float2 a3 = __half22float2(*(__half2*)&u3.x);
                float2 b3 = __half22float2(*(__half2*)&u3.y);
                acc.x += w0 * a0.x + w1 * a1.x + w2 * a2.x + w3 * a3.x;
                acc.y += w0 * a0.y + w1 * a1.y + w2 * a2.y + w3 * a3.y;
                acc.z += w0 * b0.x + w1 * b1.x + w2 * b2.x + w3 * b3.x;
                acc.w += w0 * b0.y + w1 * b1.y + w2 * b2.y + w3 * b3.y;
            }
            for (; k < cnt; k++) {
                int   sk = __shfl_sync(0xffffffff, s, k);
                float wk = __shfl_sync(0xffffffff, wgt, k);
                uint2 u = ((const uint2*)(h2 + (long)sk * RSTR))[lane];
                float2 a = __half22float2(*(__half2*)&u.x);
                float2 b = __half22float2(*(__half2*)&u.y);
                acc.x += wk * a.x; acc.y += wk * a.y;
                acc.z += wk * b.x; acc.w += wk * b.y;
            }
        }
        const float4* b4 = (const float4*)bias;
        float4 bb = b4[lane];
        float4 o;
        o.x = tanhf(acc.x * invS + bb.x);
        o.y = tanhf(acc.y * invS + bb.y);
        o.z = tanhf(acc.z * invS + bb.z);
        o.w = tanhf(acc.w * invS + bb.w);
        ((float4*)out)[w * 32 + lane] = o;
    } else {
        float a0 = 0.f, a1 = 0.f;
        int j0 = lane, j1 = lane + 32;
        for (int c = 0; c < nk; c++) {
            int cnt = min(32, deg - (c << 5));
            int s; float wgt;
            if (c < 4) { s = cS[c]; wgt = cW[c]; }
            else {
                int i = (c << 5) + lane;
                s = 0; wgt = 0.f;
                if (i < deg) {
                    s = g_csr[beg + i];
                    float hs = g_hsp[s];
                    float z = hs + hdv;
                    float e = (z > 0.f) ? z : 0.2f * z;
                    wgt = __expf(e - M);
                }
            }
            for (int k = 0; k < cnt; k++) {
                int   sk = __shfl_sync(0xffffffff, s, k);
                float wk = __shfl_sync(0xffffffff, wgt, k);
                const __half* row = (const __half*)(h2 + (long)sk * RSTR);
                a0 += wk * __half2float(row[j0]);
                if (j1 < F) a1 += wk * __half2float(row[j1]);
            }
        }
        out[(long)w * F + j0] = tanhf(a0 * invS + bias[j0]);
        if (j1 < F) out[(long)w * F + j1] = tanhf(a1 * invS + bias[j1]);
    }
}

// -------- mask MLP tail (m2..m4) + soft-argmax gating, warp per node ---------
// m1 = tanh(latent @ mw1 + mb1) precomputed by k_tgemm mode 1 into g_xn.
__global__ void __launch_bounds__(256) k_mask2(
    float* __restrict__ cur, const float* __restrict__ m1,
    const float* __restrict__ mw2, const float* __restrict__ mb2,
    const float* __restrict__ mw3, const float* __restrict__ mb3,
    const float* __restrict__ mw4, const float* __restrict__ mb4)
{
    __shared__ float w2[64 * 16];
    __shared__ float w3[16 * 16];
    __shared__ float w4[32];
    __shared__ float bb2[16], bb3[16], bb4[2];
    int t = threadIdx.x;
    for (int i = t; i < 64 * 16; i += 256) w2[i] = mw2[i];
    if (t < 256 && t < 16 * 16) w3[t] = mw3[t];
    if (t < 32) w4[t] = mw4[t];
    if (t < 16) { bb2[t] = mb2[t]; bb3[t] = mb3[t]; }
    if (t < 2)  bb4[t] = mb4[t];
    __syncthreads();

    int n = blockIdx.x * 8 + (t >> 5);
    int lane = t & 31;
    if (n >= NN) return;

    float a0 = m1[(long)n * 64 + lane];
    float a1 = m1[(long)n * 64 + lane + 32];

    int l16 = lane & 15;
    float s2 = bb2[l16];
    #pragma unroll
    for (int k = 0; k < 32; k++)
        s2 += __shfl_sync(0xffffffff, a0, k) * w2[k * 16 + l16];
    #pragma unroll
    for (int k = 0; k < 32; k++)
        s2 += __shfl_sync(0xffffffff, a1, k) * w2[(k + 32) * 16 + l16];
    s2 = tanhf(s2);

    float s3 = bb3[l16];
    #pragma unroll
    for (int k = 0; k < 16; k++)
        s3 += __shfl_sync(0xffffffff, s2, k) * w3[k * 16 + l16];
    s3 = tanhf(s3);

    int l2 = lane & 1;
    float o = bb4[l2];
    #pragma unroll
    for (int k = 0; k < 16; k++)
        o += __shfl_sync(0xffffffff, s3, k) * w4[k * 2 + l2];
    float o0 = __shfl_sync(0xffffffff, o, 0);
    float o1 = __shfl_sync(0xffffffff, o, 1);
    float mx = fmaxf(o0, o1);
    float e0 = expf(o0 - mx), e1 = expf(o1 - mx);
    float sa = e1 / (e0 + e1);

    float4* c4 = (float4*)&cur[(long)n * 128];
    float4 v = c4[lane];
    v.x *= sa; v.y *= sa; v.z *= sa; v.w *= sa;
    c4[lane] = v;
}

// ---------------- orchestration ----------------
extern "C" void kernel_launch(void* const* d_in, const int* in_sizes, int n_in,
                              void* d_out, int out_size)
{
    const float* x   = (const float*)d_in[0];
    const int*   ei  = (const int*)  d_in[1];
    const float* W1  = (const float*)d_in[4];
    const float* a1s = (const float*)d_in[5];
    const float* a1d = (const float*)d_in[6];
    const float* b1  = (const float*)d_in[7];
    const float* Wm  = (const float*)d_in[8];
    const float* ams = (const float*)d_in[9];
    const float* amd = (const float*)d_in[10];
    const float* bm  = (const float*)d_in[11];
    const float* W8  = (const float*)d_in[12];
    const float* a8s = (const float*)d_in[13];
    const float* a8d = (const float*)d_in[14];
    const float* b8  = (const float*)d_in[15];
    const float* mw1 = (const float*)d_in[16];
    const float* mb1 = (const float*)d_in[17];
    const float* mw2 = (const float*)d_in[18];
    const float* mb2 = (const float*)d_in[19];
    const float* mw3 = (const float*)d_in[20];
    const float* mb3 = (const float*)d_in[21];
    const float* mw4 = (const float*)d_in[22];
    const float* mb4 = (const float*)d_in[23];
    float* outp = (float*)d_out;

    void *pv;
    cudaGetSymbolAddress(&pv, g_xn);   float*   p_xn  = (float*)pv;
    cudaGetSymbolAddress(&pv, g_h2);   __half2* p_h2  = (__half2*)pv;
    cudaGetSymbolAddress(&pv, g_cur);  float*   p_cur = (float*)pv;

    cudaFuncSetAttribute(k_tgemm, cudaFuncAttributeMaxDynamicSharedMemorySize, SMEM_DYN);

    const int EB = (ET + 255) / 256;
    const int GEMM_B = (NN + 127) / 128;       // 391
    const dim3 G2(GEMM_B, 2);                  // N=128 layers
    const dim3 G1(GEMM_B, 1);                  // N<=64 layers
    const int WARP8  = (NN + 7) / 8;
    const int AGG_B  = (NN * 32 + 255) / 256;  // 6250

    // launch order keeps conv1's k_tgemm at index 3 (ncu capture slot)
    k_xn<<<WARP8, 256>>>(x);                                     // 0
    k_count<<<EB, 256>>>(ei);                                    // 1
    k_part<<<SCB, 256>>>();                                      // 2
    k_tgemm<<<G2, 256, SMEM_DYN>>>(p_xn, W1, p_h2, a1s, a1d, b1,
                         NN, HIDD, KPAD, FIN, 0);                // 3  <-- profiled
    k_scanb<<<1, 256>>>();                                       // 4
    k_off<<<SCB, 256>>>();                                       // 5
    k_scatter<<<EB, 256>>>(ei);                                  // 6
    k_aggw<HIDD><<<AGG_B, 256>>>(p_h2, b1, p_cur);               // 7

    // conv2..conv4
    for (int i = 0; i < 3; i++) {
        k_tgemm<<<G2, 256, SMEM_DYN>>>(p_cur, Wm + i * HIDD * HIDD, p_h2,
                             ams + i * HIDD, amd + i * HIDD, bm,
                             NN, HIDD, HIDD, HIDD, 0);
        k_aggw<HIDD><<<AGG_B, 256>>>(p_h2, bm + i * HIDD, p_cur);
    }

    // mask MLP: m1 via GEMM (bias+tanh epilogue) into g_xn, then tail + gating
    k_tgemm<<<G1, 256, SMEM_DYN>>>(p_cur, mw1, p_xn, a1s, a1d, mb1,
                         NN, 64, HIDD, HIDD, 1);
    k_mask2<<<(NN + 7) / 8, 256>>>(p_cur, p_xn, mw2, mb2, mw3, mb3, mw4, mb4);

    // conv5..conv7
    for (int i = 3; i < 6; i++) {
        k_tgemm<<<G2, 256, SMEM_DYN>>>(p_cur, Wm + i * HIDD * HIDD, p_h2,
                             ams + i * HIDD, amd + i * HIDD, bm,
                             NN, HIDD, HIDD, HIDD, 0);
        k_aggw<HIDD><<<AGG_B, 256>>>(p_h2, bm + i * HIDD, p_cur);
    }

    // conv8: 128 -> 42, writes final output
    k_tgemm<<<G1, 256, SMEM_DYN>>>(p_cur, W8, p_h2, a8s, a8d, b8,
                         NN, FIN, HIDD, HIDD, 0);
    k_aggw<FIN><<<AGG_B, 256>>>(p_h2, b8, outp);
}

// round 13
// speedup vs baseline: 1.7710x; 1.1277x over previous
#include <cuda_runtime.h>
#include <cuda_fp16.h>
#include <math.h>
#include <stdint.h>

#define NN   50000
#define NE   800000
#define ET   (NE + NN)     // edges + self loops
#define FIN  42
#define KPAD 64            // conv1 K padded to 64
#define HIDD 128
#define SCB  ((NN + 255) / 256)   // 196 scan blocks

// ---------------- scratch (device globals; no allocation allowed) -------------
__device__ float   g_xn [NN * KPAD];  // padded normalized input; later reused as m1 buffer
__device__ __half2 g_h2 [NN * 64];    // GEMM output h in fp16 (max 128 cols)
__device__ float   g_cur[NN * HIDD];
__device__ float   g_hsp[2 * NN];     // per-N-block partial a_s dots
__device__ float   g_hdp[2 * NN];     // per-N-block partial a_d dots
__device__ int     g_deg [NN];
__device__ int     g_off [NN + 1];
__device__ int     g_fill[NN];
__device__ int     g_csr [ET];
__device__ int     g_boff[256];

// ---------------- L1 normalize input (zero-padded to KPAD cols) ---------------
__global__ void k_xn(const float* __restrict__ x) {
    int w = (blockIdx.x * blockDim.x + threadIdx.x) >> 5;
    int lane = threadIdx.x & 31;
    if (w >= NN) return;
    float s = 0.f;
    for (int j = lane; j < FIN; j += 32) s += fabsf(x[w * FIN + j]);
    #pragma unroll
    for (int o = 16; o; o >>= 1) s += __shfl_xor_sync(0xffffffff, s, o);
    float inv = 1.f / fmaxf(s, 1e-12f);
    for (int j = lane; j < KPAD; j += 32)
        g_xn[w * KPAD + j] = (j < FIN) ? x[w * FIN + j] * inv : 0.f;
}

// ---------------- CSR build (by destination) ----------------
__global__ void k_count(const int* __restrict__ ei) {
    int e = blockIdx.x * blockDim.x + threadIdx.x;
    if (e >= ET) return;
    int dst = (e < NE) ? ei[NE + e] : (e - NE);
    atomicAdd(&g_deg[dst], 1);
}

__global__ void k_part() {
    __shared__ int wsum[8];
    int t = threadIdx.x, b = blockIdx.x;
    int node = b * 256 + t;
    int v = (node < NN) ? g_deg[node] : 0;
    #pragma unroll
    for (int o = 16; o; o >>= 1) v += __shfl_xor_sync(0xffffffff, v, o);
    if ((t & 31) == 0) wsum[t >> 5] = v;
    __syncthreads();
    if (t == 0) {
        int s = 0;
        #pragma unroll
        for (int i = 0; i < 8; i++) s += wsum[i];
        g_boff[b] = s;
    }
}

__global__ void k_scanb() {
    __shared__ int sh[256];
    int t = threadIdx.x;
    int v = (t < SCB) ? g_boff[t] : 0;
    sh[t] = v;
    __syncthreads();
    #pragma unroll
    for (int o = 1; o < 256; o <<= 1) {
        int u = (t >= o) ? sh[t - o] : 0;
        __syncthreads();
        sh[t] += u;
        __syncthreads();
    }
    if (t < SCB) g_boff[t] = sh[t] - v;
    if (t == 255) g_off[NN] = sh[255];
}

__global__ void k_off() {
    __shared__ int sh[256];
    int t = threadIdx.x, b = blockIdx.x;
    int node = b * 256 + t;
    int d = (node < NN) ? g_deg[node] : 0;
    sh[t] = d;
    __syncthreads();
    #pragma unroll
    for (int o = 1; o < 256; o <<= 1) {
        int u = (t >= o) ? sh[t - o] : 0;
        __syncthreads();
        sh[t] += u;
        __syncthreads();
    }
    if (node < NN) {
        int off = g_boff[b] + sh[t] - d;
        g_off[node] = off;
        g_fill[node] = off;
        g_deg[node] = 0;          // reset for the next kernel_launch call
    }
}

__global__ void k_scatter(const int* __restrict__ ei) {
    int e = blockIdx.x * blockDim.x + threadIdx.x;
    if (e >= ET) return;
    int src, dst;
    if (e < NE) { src = ei[e]; dst = ei[NE + e]; }
    else        { src = e - NE; dst = e - NE; }
    int pos = atomicAdd(&g_fill[dst], 1);
    g_csr[pos] = src;
}

// -------- tf32 tensor-core GEMM, 128x64 tile, double-buffered pipeline --------
// mode 0: C(half2) = A@B, plus fused dots g_hsp/g_hdp[r] = C_row . as_/ad_
// mode 1: C(float) = tanh(A@B + bias), no dots
__device__ __forceinline__ uint32_t f2tf(float f) {
    uint32_t u; asm("cvt.rna.tf32.f32 %0, %1;" : "=r"(u) : "f"(f)); return u;
}
__device__ __forceinline__ void mma_tf32(float c[4],
    uint32_t a0, uint32_t a1, uint32_t a2, uint32_t a3,
    uint32_t b0, uint32_t b1)
{
    asm volatile(
        "mma.sync.aligned.m16n8k8.row.col.f32.tf32.tf32.f32 "
        "{%0,%1,%2,%3}, {%4,%5,%6,%7}, {%8,%9}, {%0,%1,%2,%3};"
        : "+f"(c[0]), "+f"(c[1]), "+f"(c[2]), "+f"(c[3])
        : "r"(a0), "r"(a1), "r"(a2), "r"(a3), "r"(b0), "r"(b1));
}

#define ASTR 36
#define BSTR 72
#define ABUF (128 * ASTR)
#define BBUF (32 * BSTR)
#define SMEM_DYN (2 * (ABUF + BBUF) * 4)   // 55296 bytes

__global__ void __launch_bounds__(256, 2) k_tgemm(
    const float* __restrict__ A, const float* __restrict__ B,
    void* __restrict__ Cout,
    const float* __restrict__ as_, const float* __restrict__ ad_,
    const float* __restrict__ bias,
    int M, int N, int K, int KB, int mode)
{
    extern __shared__ uint32_t dynsm[];
    uint32_t* AsB = dynsm;             // [2][ABUF]
    uint32_t* BsB = dynsm + 2 * ABUF;  // [2][BBUF]
    __shared__ float sa[64], sd[64];
    int tid = threadIdx.x;
    int lane = tid & 31, wid = tid >> 5;      // warp owns rows wid*16..wid*16+15
    int q = lane >> 2, p = lane & 3;
    int row0 = blockIdx.x * 128;
    int n0 = blockIdx.y * 64;
    if (tid < 64) {
        int c = n0 + tid;
        if (mode == 0) {
            sa[tid] = (c < N) ? as_[c] : 0.f;
            sd[tid] = (c < N) ? ad_[c] : 0.f;
        } else {
            sa[tid] = (c < N) ? bias[c] : 0.f;
        }
    }
    float acc[8][4];
    #pragma unroll
    for (int j = 0; j < 8; j++)
        #pragma unroll
        for (int r = 0; r < 4; r++) acc[j][r] = 0.f;

    const bool vecN = ((N & 3) == 0);
    const int nc = K >> 5;                    // K is 64 or 128
    float4 ra[4];
    float4 rb[2];
    float  rbs[8];

#define LDG_CHUNK(K0)                                                          \
    {                                                                          \
        int _k0 = (K0);                                                        \
        _Pragma("unroll")                                                      \
        for (int l = 0; l < 4; l++) {                                          \
            int slot = tid + l * 256;                                          \
            int r = slot >> 3, kg = slot & 7;                                  \
            int gr = row0 + r;                                                 \
            ra[l] = make_float4(0.f, 0.f, 0.f, 0.f);                           \
            if (gr < M) ra[l] = *(const float4*)&A[(long)gr * K + _k0 + kg * 4];\
        }                                                                      \
        if (vecN) {                                                            \
            _Pragma("unroll")                                                  \
            for (int l = 0; l < 2; l++) {                                      \
                int slot = tid + l * 256;                                      \
                int k = slot >> 4, ng = slot & 15;                             \
                rb[l] = make_float4(0.f, 0.f, 0.f, 0.f);                       \
                if (_k0 + k < KB)                                              \
                    rb[l] = *(const float4*)&B[(long)(_k0 + k) * N + n0 + ng * 4];\
            }                                                                  \
        } else {                                                               \
            _Pragma("unroll")                                                  \
            for (int l = 0; l < 8; l++) {                                      \
                int slot = tid + l * 256;                                      \
                int k = slot >> 6, n = slot & 63;                              \
                rbs[l] = (_k0 + k < KB && n0 + n < N)                          \
                       ? B[(long)(_k0 + k) * N + n0 + n] : 0.f;                \
            }                                                                  \
        }                                                                      \
    }

#define STS_CHUNK(BUF)                                                         \
    {                                                                          \
        uint32_t* _As = AsB + (BUF) * ABUF;                                    \
        uint32_t* _Bs = BsB + (BUF) * BBUF;                                    \
        _Pragma("unroll")                                                      \
        for (int l = 0; l < 4; l++) {                                          \
            int slot = tid + l * 256;                                          \
            int r = slot >> 3, kg = slot & 7;                                  \
            uint32_t* d = &_As[r * ASTR + kg * 4];                             \
            d[0] = f2tf(ra[l].x); d[1] = f2tf(ra[l].y);                        \
            d[2] = f2tf(ra[l].z); d[3] = f2tf(ra[l].w);                        \
        }                                                                      \
        if (vecN) {                                                            \
            _Pragma("unroll")                                                  \
            for (int l = 0; l < 2; l++) {                                      \
                int slot = tid + l * 256;                                      \
                int k = slot >> 4, ng = slot & 15;                             \
                uint32_t* d = &_Bs[k * BSTR + ng * 4];                         \
                d[0] = f2tf(rb[l].x); d[1] = f2tf(rb[l].y);                    \
                d[2] = f2tf(rb[l].z); d[3] = f2tf(rb[l].w);                    \
            }                                                                  \
        } else {                                                               \
            _Pragma("unroll")                                                  \
            for (int l = 0; l < 8; l++) {                                      \
                int slot = tid + l * 256;                                      \
                int k = slot >> 6, n = slot & 63;                              \
                _Bs[k * BSTR + n] = f2tf(rbs[l]);                              \
            }                                                                  \
        }                                                                      \
    }

    // prologue: stage chunk 0 into buffer 0
    LDG_CHUNK(0);
    STS_CHUNK(0);

    for (int c = 0; c < nc; c++) {
        __syncthreads();                       // buffer c&1 ready (and sa/sd on c==0)
        int buf = c & 1;
        if (c + 1 < nc) LDG_CHUNK((c + 1) << 5);   // global loads only — overlap with MMA
        uint32_t* As = AsB + buf * ABUF;
        uint32_t* Bs = BsB + buf * BBUF;
        #pragma unroll
        for (int ks = 0; ks < 4; ks++) {
            int kb = ks * 8;
            int r = wid * 16 + q;
            uint32_t a0 = As[r * ASTR + kb + p];
            uint32_t a1 = As[(r + 8) * ASTR + kb + p];
            uint32_t a2 = As[r * ASTR + kb + p + 4];
            uint32_t a3 = As[(r + 8) * ASTR + kb + p + 4];
            #pragma unroll
            for (int fn = 0; fn < 8; fn++) {
                int n = fn * 8 + q;
                uint32_t b0 = Bs[(kb + p) * BSTR + n];
                uint32_t b1 = Bs[(kb + p + 4) * BSTR + n];
                mma_tf32(acc[fn], a0, a1, a2, a3, b0, b1);
            }
        }
        if (c + 1 < nc) STS_CHUNK(buf ^ 1);    // visible after next loop's sync
    }

    if (mode == 0) {
        // ---- epilogue: store C as half2 + per-warp fused a_s/a_d row dots ----
        __half2* C2 = (__half2*)Cout;
        #pragma unroll
        for (int ro = 0; ro < 2; ro++) {
            int rl = wid * 16 + q + ro * 8;
            int r = row0 + rl;
            float s = 0.f, d = 0.f;
            #pragma unroll
            for (int fn = 0; fn < 8; fn++) {
                int cl = fn * 8 + p * 2;
                float v0 = acc[fn][ro * 2 + 0];
                float v1 = acc[fn][ro * 2 + 1];
                s += v0 * sa[cl] + v1 * sa[cl + 1];
                d += v0 * sd[cl] + v1 * sd[cl + 1];
                int c = n0 + cl;
                if (r < M && c + 1 < N)
                    C2[((long)r * N + c) >> 1] = __floats2half2_rn(v0, v1);
            }
            s += __shfl_xor_sync(0xffffffff, s, 1);
            s += __shfl_xor_sync(0xffffffff, s, 2);
            d += __shfl_xor_sync(0xffffffff, d, 1);
            d += __shfl_xor_sync(0xffffffff, d, 2);
            if (p == 0 && r < M) {
                g_hsp[blockIdx.y * NN + r] = s;
                g_hdp[blockIdx.y * NN + r] = d;
            }
        }
    } else {
        // ---- epilogue: C(float) = tanh(acc + bias) ----
        float* Cf = (float*)Cout;
        #pragma unroll
        for (int ro = 0; ro < 2; ro++) {
            int rl = wid * 16 + q + ro * 8;
            int r = row0 + rl;
            if (r >= M) continue;
            #pragma unroll
            for (int fn = 0; fn < 8; fn++) {
                int cl = fn * 8 + p * 2;
                int c = n0 + cl;
                float v0 = tanhf(acc[fn][ro * 2 + 0] + sa[cl]);
                float v1 = tanhf(acc[fn][ro * 2 + 1] + sa[cl + 1]);
                if (c + 1 < N) *(float2*)&Cf[(long)r * N + c] = make_float2(v0, v1);
                else if (c < N) Cf[(long)r * N + c] = v0;
            }
        }
    }
#undef LDG_CHUNK
#undef STS_CHUNK
}

// -------- warp-per-node softmax aggregation: SINGLE PASS (no max-sub) --------
// Logits are bounded (|z| << 88) so exp() cannot overflow in fp32; softmax
// without the max shift is bit-compatible to ~ulp with the shifted form.
template<int F>
__global__ void __launch_bounds__(256) k_aggw(
    const __half2* __restrict__ h2, const float* __restrict__ bias,
    float* __restrict__ out)
{
    constexpr bool TWO = (F == 128);
    constexpr int RSTR = F / 2;               // half2 per row
    int w = (blockIdx.x * blockDim.x + threadIdx.x) >> 5;
    int lane = threadIdx.x & 31;
    if (w >= NN) return;
    int beg = g_off[w], end = g_off[w + 1];
    int deg = end - beg;
    int nk = (deg + 31) >> 5;
    float hdv = TWO ? (g_hdp[w] + g_hdp[NN + w]) : g_hdp[w];

    float myS = 0.f;

    if constexpr (F == 128) {
        float4 acc = make_float4(0.f, 0.f, 0.f, 0.f);
        for (int c = 0; c < nk; c++) {
            int i = (c << 5) + lane;
            int s = 0; float wgt = 0.f;
            if (i < deg) {
                s = g_csr[beg + i];
                float hs = g_hsp[s] + g_hsp[NN + s];
                float z = hs + hdv;
                float e = (z > 0.f) ? z : 0.2f * z;
                wgt = __expf(e);
            }
            myS += wgt;
            int cnt = min(32, deg - (c << 5));
            int k = 0;
            for (; k + 4 <= cnt; k += 4) {
                int   s0 = __shfl_sync(0xffffffff, s, k);
                int   s1 = __shfl_sync(0xffffffff, s, k + 1);
                int   s2 = __shfl_sync(0xffffffff, s, k + 2);
                int   s3 = __shfl_sync(0xffffffff, s, k + 3);
                float w0 = __shfl_sync(0xffffffff, wgt, k);
                float w1 = __shfl_sync(0xffffffff, wgt, k + 1);
                float w2 = __shfl_sync(0xffffffff, wgt, k + 2);
                float w3 = __shfl_sync(0xffffffff, wgt, k + 3);
                uint2 u0 = ((const uint2*)(h2 + (long)s0 * RSTR))[lane];
                uint2 u1 = ((const uint2*)(h2 + (long)s1 * RSTR))[lane];
                uint2 u2 = ((const uint2*)(h2 + (long)s2 * RSTR))[lane];
                uint2 u3 = ((const uint2*)(h2 + (long)s3 * RSTR))[lane];
                float2 a0 = __half22float2(*(__half2*)&u0.x);
                float2 b0 = __half22float2(*(__half2*)&u0.y);
                float2 a1 = __half22float2(*(__half2*)&u1.x);
                float2 b1 = __half22float2(*(__half2*)&u1.y);
                float2 a2 = __half22float2(*(__half2*)&u2.x);
                float2 b2 = __half22float2(*(__half2*)&u2.y);
                float2 a3 = __half22float2(*(__half2*)&u3.x);
                float2 b3 = __half22float2(*(__half2*)&u3.y);
                acc.x += w0 * a0.x + w1 * a1.x + w2 * a2.x + w3 * a3.x;
                acc.y += w0 * a0.y + w1 * a1.y + w2 * a2.y + w3 * a3.y;
                acc.z += w0 * b0.x + w1 * b1.x + w2 * b2.x + w3 * b3.x;
                acc.w += w0 * b0.y + w1 * b1.y + w2 * b2.y + w3 * b3.y;
            }
            for (; k < cnt; k++) {
                int   sk = __shfl_sync(0xffffffff, s, k);
                float wk = __shfl_sync(0xffffffff, wgt, k);
                uint2 u = ((const uint2*)(h2 + (long)sk * RSTR))[lane];
                float2 a = __half22float2(*(__half2*)&u.x);
                float2 b = __half22float2(*(__half2*)&u.y);
                acc.x += wk * a.x; acc.y += wk * a.y;
                acc.z += wk * b.x; acc.w += wk * b.y;
            }
        }
        #pragma unroll
        for (int o = 16; o; o >>= 1) myS += __shfl_xor_sync(0xffffffff, myS, o);
        float invS = 1.f / (myS + 1e-16f);
        const float4* b4 = (const float4*)bias;
        float4 bb = b4[lane];
        float4 o;
        o.x = tanhf(acc.x * invS + bb.x);
        o.y = tanhf(acc.y * invS + bb.y);
        o.z = tanhf(acc.z * invS + bb.z);
        o.w = tanhf(acc.w * invS + bb.w);
        ((float4*)out)[w * 32 + lane] = o;
    } else {
        float a0 = 0.f, a1 = 0.f;
        int j0 = lane, j1 = lane + 32;
        for (int c = 0; c < nk; c++) {
            int i = (c << 5) + lane;
            int s = 0; float wgt = 0.f;
            if (i < deg) {
                s = g_csr[beg + i];
                float hs = g_hsp[s];
                float z = hs + hdv;
                float e = (z > 0.f) ? z : 0.2f * z;
                wgt = __expf(e);
            }
            myS += wgt;
            int cnt = min(32, deg - (c << 5));
            for (int k = 0; k < cnt; k++) {
                int   sk = __shfl_sync(0xffffffff, s, k);
                float wk = __shfl_sync(0xffffffff, wgt, k);
                const __half* row = (const __half*)(h2 + (long)sk * RSTR);
                a0 += wk * __half2float(row[j0]);
                if (j1 < F) a1 += wk * __half2float(row[j1]);
            }
        }
        #pragma unroll
        for (int o = 16; o; o >>= 1) myS += __shfl_xor_sync(0xffffffff, myS, o);
        float invS = 1.f / (myS + 1e-16f);
        out[(long)w * F + j0] = tanhf(a0 * invS + bias[j0]);
        if (j1 < F) out[(long)w * F + j1] = tanhf(a1 * invS + bias[j1]);
    }
}

// -------- mask MLP tail (m2..m4) + soft-argmax gating, warp per node ---------
// m1 = tanh(latent @ mw1 + mb1) precomputed by k_tgemm mode 1 into g_xn.
__global__ void __launch_bounds__(256) k_mask2(
    float* __restrict__ cur, const float* __restrict__ m1,
    const float* __restrict__ mw2, const float* __restrict__ mb2,
    const float* __restrict__ mw3, const float* __restrict__ mb3,
    const float* __restrict__ mw4, const float* __restrict__ mb4)
{
    __shared__ float w2[64 * 16];
    __shared__ float w3[16 * 16];
    __shared__ float w4[32];
    __shared__ float bb2[16], bb3[16], bb4[2];
    int t = threadIdx.x;
    for (int i = t; i < 64 * 16; i += 256) w2[i] = mw2[i];
    if (t < 256 && t < 16 * 16) w3[t] = mw3[t];
    if (t < 32) w4[t] = mw4[t];
    if (t < 16) { bb2[t] = mb2[t]; bb3[t] = mb3[t]; }
    if (t < 2)  bb4[t] = mb4[t];
    __syncthreads();

    int n = blockIdx.x * 8 + (t >> 5);
    int lane = t & 31;
    if (n >= NN) return;

    float a0 = m1[(long)n * 64 + lane];
    float a1 = m1[(long)n * 64 + lane + 32];

    int l16 = lane & 15;
    float s2 = bb2[l16];
    #pragma unroll
    for (int k = 0; k < 32; k++)
        s2 += __shfl_sync(0xffffffff, a0, k) * w2[k * 16 + l16];
    #pragma unroll
    for (int k = 0; k < 32; k++)
        s2 += __shfl_sync(0xffffffff, a1, k) * w2[(k + 32) * 16 + l16];
    s2 = tanhf(s2);

    float s3 = bb3[l16];
    #pragma unroll
    for (int k = 0; k < 16; k++)
        s3 += __shfl_sync(0xffffffff, s2, k) * w3[k * 16 + l16];
    s3 = tanhf(s3);

    int l2 = lane & 1;
    float o = bb4[l2];
    #pragma unroll
    for (int k = 0; k < 16; k++)
        o += __shfl_sync(0xffffffff, s3, k) * w4[k * 2 + l2];
    float o0 = __shfl_sync(0xffffffff, o, 0);
    float o1 = __shfl_sync(0xffffffff, o, 1);
    float mx = fmaxf(o0, o1);
    float e0 = expf(o0 - mx), e1 = expf(o1 - mx);
    float sa = e1 / (e0 + e1);

    float4* c4 = (float4*)&cur[(long)n * 128];
    float4 v = c4[lane];
    v.x *= sa; v.y *= sa; v.z *= sa; v.w *= sa;
    c4[lane] = v;
}

// ---------------- orchestration ----------------
extern "C" void kernel_launch(void* const* d_in, const int* in_sizes, int n_in,
                              void* d_out, int out_size)
{
    const float* x   = (const float*)d_in[0];
    const int*   ei  = (const int*)  d_in[1];
    const float* W1  = (const float*)d_in[4];
    const float* a1s = (const float*)d_in[5];
    const float* a1d = (const float*)d_in[6];
    const float* b1  = (const float*)d_in[7];
    const float* Wm  = (const float*)d_in[8];
    const float* ams = (const float*)d_in[9];
    const float* amd = (const float*)d_in[10];
    const float* bm  = (const float*)d_in[11];
    const float* W8  = (const float*)d_in[12];
    const float* a8s = (const float*)d_in[13];
    const float* a8d = (const float*)d_in[14];
    const float* b8  = (const float*)d_in[15];
    const float* mw1 = (const float*)d_in[16];
    const float* mb1 = (const float*)d_in[17];
    const float* mw2 = (const float*)d_in[18];
    const float* mb2 = (const float*)d_in[19];
    const float* mw3 = (const float*)d_in[20];
    const float* mb3 = (const float*)d_in[21];
    const float* mw4 = (const float*)d_in[22];
    const float* mb4 = (const float*)d_in[23];
    float* outp = (float*)d_out;

    void *pv;
    cudaGetSymbolAddress(&pv, g_xn);   float*   p_xn  = (float*)pv;
    cudaGetSymbolAddress(&pv, g_h2);   __half2* p_h2  = (__half2*)pv;
    cudaGetSymbolAddress(&pv, g_cur);  float*   p_cur = (float*)pv;

    cudaFuncSetAttribute(k_tgemm, cudaFuncAttributeMaxDynamicSharedMemorySize, SMEM_DYN);

    const int EB = (ET + 255) / 256;
    const int GEMM_B = (NN + 127) / 128;       // 391
    const dim3 G2(GEMM_B, 2);                  // N=128 layers
    const dim3 G1(GEMM_B, 1);                  // N<=64 layers
    const int WARP8  = (NN + 7) / 8;
    const int AGG_B  = (NN * 32 + 255) / 256;  // 6250

    // launch order keeps conv1's k_tgemm at index 3 (ncu capture slot)
    k_xn<<<WARP8, 256>>>(x);                                     // 0
    k_count<<<EB, 256>>>(ei);                                    // 1
    k_part<<<SCB, 256>>>();                                      // 2
    k_tgemm<<<G2, 256, SMEM_DYN>>>(p_xn, W1, p_h2, a1s, a1d, b1,
                         NN, HIDD, KPAD, FIN, 0);                // 3  <-- profiled
    k_scanb<<<1, 256>>>();                                       // 4
    k_off<<<SCB, 256>>>();                                       // 5
    k_scatter<<<EB, 256>>>(ei);                                  // 6
    k_aggw<HIDD><<<AGG_B, 256>>>(p_h2, b1, p_cur);               // 7

    // conv2..conv4
    for (int i = 0; i < 3; i++) {
        k_tgemm<<<G2, 256, SMEM_DYN>>>(p_cur, Wm + i * HIDD * HIDD, p_h2,
                             ams + i * HIDD, amd + i * HIDD, bm,
                             NN, HIDD, HIDD, HIDD, 0);
        k_aggw<HIDD><<<AGG_B, 256>>>(p_h2, bm + i * HIDD, p_cur);
    }

    // mask MLP: m1 via GEMM (bias+tanh epilogue) into g_xn, then tail + gating
    k_tgemm<<<G1, 256, SMEM_DYN>>>(p_cur, mw1, p_xn, a1s, a1d, mb1,
                         NN, 64, HIDD, HIDD, 1);
    k_mask2<<<(NN + 7) / 8, 256>>>(p_cur, p_xn, mw2, mb2, mw3, mb3, mw4, mb4);

    // conv5..conv7
    for (int i = 3; i < 6; i++) {
        k_tgemm<<<G2, 256, SMEM_DYN>>>(p_cur, Wm + i * HIDD * HIDD, p_h2,
                             ams + i * HIDD, amd + i * HIDD, bm,
                             NN, HIDD, HIDD, HIDD, 0);
        k_aggw<HIDD><<<AGG_B, 256>>>(p_h2, bm + i * HIDD, p_cur);
    }

    // conv8: 128 -> 42, writes final output
    k_tgemm<<<G1, 256, SMEM_DYN>>>(p_cur, W8, p_h2, a8s, a8d, b8,
                         NN, FIN, HIDD, HIDD, 0);
    k_aggw<FIN><<<AGG_B, 256>>>(p_h2, b8, outp);
}

// round 14
// speedup vs baseline: 1.8634x; 1.0522x over previous
#include <cuda_runtime.h>
#include <cuda_fp16.h>
#include <math.h>
#include <stdint.h>

#define NN   50000
#define NE   800000
#define ET   (NE + NN)     // edges + self loops
#define FIN  42
#define KPAD 64            // conv1 K padded to 64
#define HIDD 128
#define SCB  ((NN + 255) / 256)   // 196 scan blocks

// pre-rounded (tf32) weight scratch offsets
#define W1_OFF  0
#define WM_OFF  (FIN * HIDD)                       // 5376
#define W8_OFF  (WM_OFF + 6 * HIDD * HIDD)         // 103680
#define MW1_OFF (W8_OFF + HIDD * FIN)              // 109056
#define WT_TOT  (MW1_OFF + HIDD * 64)              // 117248

// ---------------- scratch (device globals; no allocation allowed) -------------
__device__ float   g_xn [NN * KPAD];  // padded normalized input; later reused as m1 buffer
__device__ __half2 g_h2 [NN * 64];    // GEMM output h in fp16 (max 128 cols)
__device__ float   g_cur[NN * HIDD];
__device__ float   g_hsp[2 * NN];     // per-N-block partial a_s dots
__device__ float   g_hdp[2 * NN];     // per-N-block partial a_d dots
__device__ float   g_wt [WT_TOT];     // tf32-pre-rounded weights
__device__ int     g_deg [NN];
__device__ int     g_off [NN + 1];
__device__ int     g_fill[NN];
__device__ int     g_csr [ET];
__device__ int     g_boff[256];

__device__ __forceinline__ uint32_t f2tf(float f) {
    uint32_t u; asm("cvt.rna.tf32.f32 %0, %1;" : "=r"(u) : "f"(f)); return u;
}

// ---------------- L1 normalize input (zero-padded to KPAD cols) ---------------
__global__ void k_xn(const float* __restrict__ x) {
    int w = (blockIdx.x * blockDim.x + threadIdx.x) >> 5;
    int lane = threadIdx.x & 31;
    if (w >= NN) return;
    float s = 0.f;
    for (int j = lane; j < FIN; j += 32) s += fabsf(x[w * FIN + j]);
    #pragma unroll
    for (int o = 16; o; o >>= 1) s += __shfl_xor_sync(0xffffffff, s, o);
    float inv = 1.f / fmaxf(s, 1e-12f);
    for (int j = lane; j < KPAD; j += 32)
        g_xn[w * KPAD + j] = (j < FIN) ? x[w * FIN + j] * inv : 0.f;
}

// -------- pre-round all weight matrices to tf32 once per launch ----------
__global__ void k_round(const float* __restrict__ W1, const float* __restrict__ Wm,
                        const float* __restrict__ W8, const float* __restrict__ mw1)
{
    int i = blockIdx.x * blockDim.x + threadIdx.x;
    if (i >= WT_TOT) return;
    float v;
    if (i < WM_OFF)        v = W1[i];
    else if (i < W8_OFF)   v = Wm[i - WM_OFF];
    else if (i < MW1_OFF)  v = W8[i - W8_OFF];
    else                   v = mw1[i - MW1_OFF];
    g_wt[i] = __uint_as_float(f2tf(v));
}

// ---------------- CSR build (by destination) ----------------
__global__ void k_count(const int* __restrict__ ei) {
    int e = blockIdx.x * blockDim.x + threadIdx.x;
    if (e >= ET) return;
    int dst = (e < NE) ? ei[NE + e] : (e - NE);
    atomicAdd(&g_deg[dst], 1);
}

__global__ void k_part() {
    __shared__ int wsum[8];
    int t = threadIdx.x, b = blockIdx.x;
    int node = b * 256 + t;
    int v = (node < NN) ? g_deg[node] : 0;
    #pragma unroll
    for (int o = 16; o; o >>= 1) v += __shfl_xor_sync(0xffffffff, v, o);
    if ((t & 31) == 0) wsum[t >> 5] = v;
    __syncthreads();
    if (t == 0) {
        int s = 0;
        #pragma unroll
        for (int i = 0; i < 8; i++) s += wsum[i];
        g_boff[b] = s;
    }
}

__global__ void k_scanb() {
    __shared__ int sh[256];
    int t = threadIdx.x;
    int v = (t < SCB) ? g_boff[t] : 0;
    sh[t] = v;
    __syncthreads();
    #pragma unroll
    for (int o = 1; o < 256; o <<= 1) {
        int u = (t >= o) ? sh[t - o] : 0;
        __syncthreads();
        sh[t] += u;
        __syncthreads();
    }
    if (t < SCB) g_boff[t] = sh[t] - v;
    if (t == 255) g_off[NN] = sh[255];
}

__global__ void k_off() {
    __shared__ int sh[256];
    int t = threadIdx.x, b = blockIdx.x;
    int node = b * 256 + t;
    int d = (node < NN) ? g_deg[node] : 0;
    sh[t] = d;
    __syncthreads();
    #pragma unroll
    for (int o = 1; o < 256; o <<= 1) {
        int u = (t >= o) ? sh[t - o] : 0;
        __syncthreads();
        sh[t] += u;
        __syncthreads();
    }
    if (node < NN) {
        int off = g_boff[b] + sh[t] - d;
        g_off[node] = off;
        g_fill[node] = off;
        g_deg[node] = 0;          // reset for the next kernel_launch call
    }
}

__global__ void k_scatter(const int* __restrict__ ei) {
    int e = blockIdx.x * blockDim.x + threadIdx.x;
    if (e >= ET) return;
    int src, dst;
    if (e < NE) { src = ei[e]; dst = ei[NE + e]; }
    else        { src = e - NE; dst = e - NE; }
    int pos = atomicAdd(&g_fill[dst], 1);
    g_csr[pos] = src;
}

// -------- tf32 tensor-core GEMM, 128x64 tile, cp.async double buffer ---------
// B must be tf32-pre-rounded (g_wt). A is raw fp32, rounded at MMA-read.
// mode 0: C(half2) = A@B, plus fused dots g_hsp/g_hdp[r] = C_row . as_/ad_
// mode 1: C(float) = tanh(A@B + bias), no dots
__device__ __forceinline__ void mma_tf32(float c[4],
    uint32_t a0, uint32_t a1, uint32_t a2, uint32_t a3,
    uint32_t b0, uint32_t b1)
{
    asm volatile(
        "mma.sync.aligned.m16n8k8.row.col.f32.tf32.tf32.f32 "
        "{%0,%1,%2,%3}, {%4,%5,%6,%7}, {%8,%9}, {%0,%1,%2,%3};"
        : "+f"(c[0]), "+f"(c[1]), "+f"(c[2]), "+f"(c[3])
        : "r"(a0), "r"(a1), "r"(a2), "r"(a3), "r"(b0), "r"(b1));
}
__device__ __forceinline__ void cpa16(uint32_t d, const void* s, int sz) {
    asm volatile("cp.async.cg.shared.global [%0], [%1], 16, %2;"
                 :: "r"(d), "l"(s), "r"(sz) : "memory");
}
__device__ __forceinline__ void cpa4(uint32_t d, const void* s, int sz) {
    asm volatile("cp.async.ca.shared.global [%0], [%1], 4, %2;"
                 :: "r"(d), "l"(s), "r"(sz) : "memory");
}

#define ASTR 36
#define BSTR 72
#define ABUF (128 * ASTR)
#define BBUF (32 * BSTR)
#define SMEM_DYN (2 * (ABUF + BBUF) * 4)   // 55296 bytes

__global__ void __launch_bounds__(256, 3) k_tgemm(
    const float* __restrict__ A, const float* __restrict__ B,
    void* __restrict__ Cout,
    const float* __restrict__ as_, const float* __restrict__ ad_,
    const float* __restrict__ bias,
    int M, int N, int K, int KB, int mode)
{
    extern __shared__ __align__(16) uint32_t dynsm[];
    uint32_t* AsB = dynsm;             // [2][ABUF]
    uint32_t* BsB = dynsm + 2 * ABUF;  // [2][BBUF]
    __shared__ float sa[64], sd[64];
    int tid = threadIdx.x;
    int lane = tid & 31, wid = tid >> 5;      // warp owns rows wid*16..wid*16+15
    int q = lane >> 2, p = lane & 3;
    int row0 = blockIdx.x * 128;
    int n0 = blockIdx.y * 64;
    uint32_t asb = (uint32_t)__cvta_generic_to_shared(AsB);
    uint32_t bsb = (uint32_t)__cvta_generic_to_shared(BsB);
    if (tid < 64) {
        int c = n0 + tid;
        if (mode == 0) {
            sa[tid] = (c < N) ? as_[c] : 0.f;
            sd[tid] = (c < N) ? ad_[c] : 0.f;
        } else {
            sa[tid] = (c < N) ? bias[c] : 0.f;
        }
    }
    float acc[8][4];
    #pragma unroll
    for (int j = 0; j < 8; j++)
        #pragma unroll
        for (int r = 0; r < 4; r++) acc[j][r] = 0.f;

    const bool vecN = ((N & 3) == 0);
    const int nc = K >> 5;                    // K is 64 or 128

#define ISSUE_CHUNK(K0, BUF)                                                   \
    {                                                                          \
        int _k0 = (K0);                                                        \
        uint32_t _as = asb + (BUF) * (ABUF * 4);                               \
        uint32_t _bs = bsb + (BUF) * (BBUF * 4);                               \
        _Pragma("unroll")                                                      \
        for (int l = 0; l < 4; l++) {                                          \
            int slot = tid + l * 256;                                          \
            int r = slot >> 3, kg = slot & 7;                                  \
            int gr = row0 + r;                                                 \
            int ok = (gr < M) ? 16 : 0;                                        \
            const float* src = &A[(long)min(gr, M - 1) * K + _k0 + kg * 4];    \
            cpa16(_as + (uint32_t)(r * ASTR + kg * 4) * 4u, src, ok);          \
        }                                                                      \
        if (vecN) {                                                            \
            _Pragma("unroll")                                                  \
            for (int l = 0; l < 2; l++) {                                      \
                int slot = tid + l * 256;                                      \
                int k = slot >> 4, ng = slot & 15;                             \
                int gk = _k0 + k;                                              \
                int ok = (gk < KB) ? 16 : 0;                                   \
                const float* src = &B[(long)min(gk, KB - 1) * N + n0 + ng * 4];\
                cpa16(_bs + (uint32_t)(k * BSTR + ng * 4) * 4u, src, ok);      \
            }                                                                  \
        } else {                                                               \
            _Pragma("unroll")                                                  \
            for (int l = 0; l < 8; l++) {                                      \
                int slot = tid + l * 256;                                      \
                int k = slot >> 6, n = slot & 63;                              \
                int gk = _k0 + k;                                              \
                int ok = (gk < KB && n0 + n < N) ? 4 : 0;                      \
                const float* src = &B[(long)min(gk, KB - 1) * N + min(n0 + n, N - 1)];\
                cpa4(_bs + (uint32_t)(k * BSTR + n) * 4u, src, ok);            \
            }                                                                  \
        }                                                                      \
        asm volatile("cp.async.commit_group;" ::: "memory");                   \
    }

    ISSUE_CHUNK(0, 0);

    for (int c = 0; c < nc; c++) {
        int buf = c & 1;
        asm volatile("cp.async.wait_group 0;" ::: "memory");
        __syncthreads();                       // chunk c visible; prev buffer free
        if (c + 1 < nc) ISSUE_CHUNK((c + 1) << 5, buf ^ 1);   // overlaps MMA below
        uint32_t* As = AsB + buf * ABUF;
        uint32_t* Bs = BsB + buf * BBUF;
        #pragma unroll
        for (int ks = 0; ks < 4; ks++) {
            int kb = ks * 8;
            int r = wid * 16 + q;
            uint32_t a0 = f2tf(__uint_as_float(As[r * ASTR + kb + p]));
            uint32_t a1 = f2tf(__uint_as_float(As[(r + 8) * ASTR + kb + p]));
            uint32_t a2 = f2tf(__uint_as_float(As[r * ASTR + kb + p + 4]));
            uint32_t a3 = f2tf(__uint_as_float(As[(r + 8) * ASTR + kb + p + 4]));
            #pragma unroll
            for (int fn = 0; fn < 8; fn++) {
                int n = fn * 8 + q;
                uint32_t b0 = Bs[(kb + p) * BSTR + n];
                uint32_t b1 = Bs[(kb + p + 4) * BSTR + n];
                mma_tf32(acc[fn], a0, a1, a2, a3, b0, b1);
            }
        }
        __syncthreads();                       // all reads of buf done before reuse
    }

    if (mode == 0) {
        // ---- epilogue: store C as half2 + per-warp fused a_s/a_d row dots ----
        __half2* C2 = (__half2*)Cout;
        #pragma unroll
        for (int ro = 0; ro < 2; ro++) {
            int rl = wid * 16 + q + ro * 8;
            int r = row0 + rl;
            float s = 0.f, d = 0.f;
            #pragma unroll
            for (int fn = 0; fn < 8; fn++) {
                int cl = fn * 8 + p * 2;
                float v0 = acc[fn][ro * 2 + 0];
                float v1 = acc[fn][ro * 2 + 1];
                s += v0 * sa[cl] + v1 * sa[cl + 1];
                d += v0 * sd[cl] + v1 * sd[cl + 1];
                int c = n0 + cl;
                if (r < M && c + 1 < N)
                    C2[((long)r * N + c) >> 1] = __floats2half2_rn(v0, v1);
            }
            s += __shfl_xor_sync(0xffffffff, s, 1);
            s += __shfl_xor_sync(0xffffffff, s, 2);
            d += __shfl_xor_sync(0xffffffff, d, 1);
            d += __shfl_xor_sync(0xffffffff, d, 2);
            if (p == 0 && r < M) {
                g_hsp[blockIdx.y * NN + r] = s;
                g_hdp[blockIdx.y * NN + r] = d;
            }
        }
    } else {
        // ---- epilogue: C(float) = tanh(acc + bias) ----
        float* Cf = (float*)Cout;
        #pragma unroll
        for (int ro = 0; ro < 2; ro++) {
            int rl = wid * 16 + q + ro * 8;
            int r = row0 + rl;
            if (r >= M) continue;
            #pragma unroll
            for (int fn = 0; fn < 8; fn++) {
                int cl = fn * 8 + p * 2;
                int c = n0 + cl;
                float v0 = tanhf(acc[fn][ro * 2 + 0] + sa[cl]);
                float v1 = tanhf(acc[fn][ro * 2 + 1] + sa[cl + 1]);
                if (c + 1 < N) *(float2*)&Cf[(long)r * N + c] = make_float2(v0, v1);
                else if (c < N) Cf[(long)r * N + c] = v0;
            }
        }
    }
#undef ISSUE_CHUNK
}

// -------- warp-per-node softmax aggregation: SINGLE PASS (no max-sub) --------
template<int F>
__global__ void __launch_bounds__(256) k_aggw(
    const __half2* __restrict__ h2, const float* __restrict__ bias,
    float* __restrict__ out)
{
    constexpr bool TWO = (F == 128);
    constexpr int RSTR = F / 2;               // half2 per row
    int w = (blockIdx.x * blockDim.x + threadIdx.x) >> 5;
    int lane = threadIdx.x & 31;
    if (w >= NN) return;
    int beg = g_off[w], end = g_off[w + 1];
    int deg = end - beg;
    int nk = (deg + 31) >> 5;
    float hdv = TWO ? (g_hdp[w] + g_hdp[NN + w]) : g_hdp[w];

    float myS = 0.f;

    if constexpr (F == 128) {
        float4 acc = make_float4(0.f, 0.f, 0.f, 0.f);
        for (int c = 0; c < nk; c++) {
            int i = (c << 5) + lane;
            int s = 0; float wgt = 0.f;
            if (i < deg) {
                s = g_csr[beg + i];
                float hs = g_hsp[s] + g_hsp[NN + s];
                float z = hs + hdv;
                float e = (z > 0.f) ? z : 0.2f * z;
                wgt = __expf(e);
            }
            myS += wgt;
            int cnt = min(32, deg - (c << 5));
            int k = 0;
            for (; k + 4 <= cnt; k += 4) {
                int   s0 = __shfl_sync(0xffffffff, s, k);
                int   s1 = __shfl_sync(0xffffffff, s, k + 1);
                int   s2 = __shfl_sync(0xffffffff, s, k + 2);
                int   s3 = __shfl_sync(0xffffffff, s, k + 3);
                float w0 = __shfl_sync(0xffffffff, wgt, k);
                float w1 = __shfl_sync(0xffffffff, wgt, k + 1);
                float w2 = __shfl_sync(0xffffffff, wgt, k + 2);
                float w3 = __shfl_sync(0xffffffff, wgt, k + 3);
                uint2 u0 = ((const uint2*)(h2 + (long)s0 * RSTR))[lane];
                uint2 u1 = ((const uint2*)(h2 + (long)s1 * RSTR))[lane];
                uint2 u2 = ((const uint2*)(h2 + (long)s2 * RSTR))[lane];
                uint2 u3 = ((const uint2*)(h2 + (long)s3 * RSTR))[lane];
                float2 a0 = __half22float2(*(__half2*)&u0.x);
                float2 b0 = __half22float2(*(__half2*)&u0.y);
                float2 a1 = __half22float2(*(__half2*)&u1.x);
                float2 b1 = __half22float2(*(__half2*)&u1.y);
                float2 a2 = __half22float2(*(__half2*)&u2.x);
                float2 b2 = __half22float2(*(__half2*)&u2.y);
                float2 a3 = __half22float2(*(__half2*)&u3.x);
                float2 b3 = __half22float2(*(__half2*)&u3.y);
                acc.x += w0 * a0.x + w1 * a1.x + w2 * a2.x + w3 * a3.x;
                acc.y += w0 * a0.y + w1 * a1.y + w2 * a2.y + w3 * a3.y;
                acc.z += w0 * b0.x + w1 * b1.x + w2 * b2.x + w3 * b3.x;
                acc.w += w0 * b0.y + w1 * b1.y + w2 * b2.y + w3 * b3.y;
            }
            for (; k < cnt; k++) {
                int   sk = __shfl_sync(0xffffffff, s, k);
                float wk = __shfl_sync(0xffffffff, wgt, k);
                uint2 u = ((const uint2*)(h2 + (long)sk * RSTR))[lane];
                float2 a = __half22float2(*(__half2*)&u.x);
                float2 b = __half22float2(*(__half2*)&u.y);
                acc.x += wk * a.x; acc.y += wk * a.y;
                acc.z += wk * b.x; acc.w += wk * b.y;
            }
        }
        #pragma unroll
        for (int o = 16; o; o >>= 1) myS += __shfl_xor_sync(0xffffffff, myS, o);
        float invS = 1.f / (myS + 1e-16f);
        const float4* b4 = (const float4*)bias;
        float4 bb = b4[lane];
        float4 o;
        o.x = tanhf(acc.x * invS + bb.x);
        o.y = tanhf(acc.y * invS + bb.y);
        o.z = tanhf(acc.z * invS + bb.z);
        o.w = tanhf(acc.w * invS + bb.w);
        ((float4*)out)[w * 32 + lane] = o;
    } else {
        float a0 = 0.f, a1 = 0.f;
        int j0 = lane, j1 = lane + 32;
        for (int c = 0; c < nk; c++) {
            int i = (c << 5) + lane;
            int s = 0; float wgt = 0.f;
            if (i < deg) {
                s = g_csr[beg + i];
                float hs = g_hsp[s];
                float z = hs + hdv;
                float e = (z > 0.f) ? z : 0.2f * z;
                wgt = __expf(e);
            }
            myS += wgt;
            int cnt = min(32, deg - (c << 5));
            for (int k = 0; k < cnt; k++) {
                int   sk = __shfl_sync(0xffffffff, s, k);
                float wk = __shfl_sync(0xffffffff, wgt, k);
                const __half* row = (const __half*)(h2 + (long)sk * RSTR);
                a0 += wk * __half2float(row[j0]);
                if (j1 < F) a1 += wk * __half2float(row[j1]);
            }
        }
        #pragma unroll
        for (int o = 16; o; o >>= 1) myS += __shfl_xor_sync(0xffffffff, myS, o);
        float invS = 1.f / (myS + 1e-16f);
        out[(long)w * F + j0] = tanhf(a0 * invS + bias[j0]);
        if (j1 < F) out[(long)w * F + j1] = tanhf(a1 * invS + bias[j1]);
    }
}

// -------- mask MLP tail (m2..m4) + soft-argmax gating, warp per node ---------
// m1 = tanh(latent @ mw1 + mb1) precomputed by k_tgemm mode 1 into g_xn.
__global__ void __launch_bounds__(256) k_mask2(
    float* __restrict__ cur, const float* __restrict__ m1,
    const float* __restrict__ mw2, const float* __restrict__ mb2,
    const float* __restrict__ mw3, const float* __restrict__ mb3,
    const float* __restrict__ mw4, const float* __restrict__ mb4)
{
    __shared__ float w2[64 * 16];
    __shared__ float w3[16 * 16];
    __shared__ float w4[32];
    __shared__ float bb2[16], bb3[16], bb4[2];
    int t = threadIdx.x;
    for (int i = t; i < 64 * 16; i += 256) w2[i] = mw2[i];
    if (t < 256 && t < 16 * 16) w3[t] = mw3[t];
    if (t < 32) w4[t] = mw4[t];
    if (t < 16) { bb2[t] = mb2[t]; bb3[t] = mb3[t]; }
    if (t < 2)  bb4[t] = mb4[t];
    __syncthreads();

    int n = blockIdx.x * 8 + (t >> 5);
    int lane = t & 31;
    if (n >= NN) return;

    float a0 = m1[(long)n * 64 + lane];
    float a1 = m1[(long)n * 64 + lane + 32];

    int l16 = lane & 15;
    float s2 = bb2[l16];
    #pragma unroll
    for (int k = 0; k < 32; k++)
        s2 += __shfl_sync(0xffffffff, a0, k) * w2[k * 16 + l16];
    #pragma unroll
    for (int k = 0; k < 32; k++)
        s2 += __shfl_sync(0xffffffff, a1, k) * w2[(k + 32) * 16 + l16];
    s2 = tanhf(s2);

    float s3 = bb3[l16];
    #pragma unroll
    for (int k = 0; k < 16; k++)
        s3 += __shfl_sync(0xffffffff, s2, k) * w3[k * 16 + l16];
    s3 = tanhf(s3);

    int l2 = lane & 1;
    float o = bb4[l2];
    #pragma unroll
    for (int k = 0; k < 16; k++)
        o += __shfl_sync(0xffffffff, s3, k) * w4[k * 2 + l2];
    float o0 = __shfl_sync(0xffffffff, o, 0);
    float o1 = __shfl_sync(0xffffffff, o, 1);
    float mx = fmaxf(o0, o1);
    float e0 = expf(o0 - mx), e1 = expf(o1 - mx);
    float sa = e1 / (e0 + e1);

    float4* c4 = (float4*)&cur[(long)n * 128];
    float4 v = c4[lane];
    v.x *= sa; v.y *= sa; v.z *= sa; v.w *= sa;
    c4[lane] = v;
}

// ---------------- orchestration ----------------
extern "C" void kernel_launch(void* const* d_in, const int* in_sizes, int n_in,
                              void* d_out, int out_size)
{
    const float* x   = (const float*)d_in[0];
    const int*   ei  = (const int*)  d_in[1];
    const float* W1  = (const float*)d_in[4];
    const float* a1s = (const float*)d_in[5];
    const float* a1d = (const float*)d_in[6];
    const float* b1  = (const float*)d_in[7];
    const float* Wm  = (const float*)d_in[8];
    const float* ams = (const float*)d_in[9];
    const float* amd = (const float*)d_in[10];
    const float* bm  = (const float*)d_in[11];
    const float* W8  = (const float*)d_in[12];
    const float* a8s = (const float*)d_in[13];
    const float* a8d = (const float*)d_in[14];
    const float* b8  = (const float*)d_in[15];
    const float* mw1 = (const float*)d_in[16];
    const float* mb1 = (const float*)d_in[17];
    const float* mw2 = (const float*)d_in[18];
    const float* mb2 = (const float*)d_in[19];
    const float* mw3 = (const float*)d_in[20];
    const float* mb3 = (const float*)d_in[21];
    const float* mw4 = (const float*)d_in[22];
    const float* mb4 = (const float*)d_in[23];
    float* outp = (float*)d_out;

    void *pv;
    cudaGetSymbolAddress(&pv, g_xn);   float*   p_xn  = (float*)pv;
    cudaGetSymbolAddress(&pv, g_h2);   __half2* p_h2  = (__half2*)pv;
    cudaGetSymbolAddress(&pv, g_cur);  float*   p_cur = (float*)pv;
    cudaGetSymbolAddress(&pv, g_wt);   float*   p_wt  = (float*)pv;

    cudaFuncSetAttribute(k_tgemm, cudaFuncAttributeMaxDynamicSharedMemorySize, SMEM_DYN);

    const int EB = (ET + 255) / 256;
    const int GEMM_B = (NN + 127) / 128;       // 391
    const dim3 G2(GEMM_B, 2);                  // N=128 layers
    const dim3 G1(GEMM_B, 1);                  // N<=64 layers
    const int WARP8  = (NN + 7) / 8;
    const int AGG_B  = (NN * 32 + 255) / 256;  // 6250

    // launch order keeps conv1's k_tgemm at index 3 (ncu capture slot)
    k_xn<<<WARP8, 256>>>(x);                                     // 0
    k_count<<<EB, 256>>>(ei);                                    // 1
    k_round<<<(WT_TOT + 255) / 256, 256>>>(W1, Wm, W8, mw1);     // 2
    k_tgemm<<<G2, 256, SMEM_DYN>>>(p_xn, p_wt + W1_OFF, p_h2, a1s, a1d, b1,
                         NN, HIDD, KPAD, FIN, 0);                // 3  <-- profiled
    k_part<<<SCB, 256>>>();                                      // 4
    k_scanb<<<1, 256>>>();                                       // 5
    k_off<<<SCB, 256>>>();                                       // 6
    k_scatter<<<EB, 256>>>(ei);                                  // 7
    k_aggw<HIDD><<<AGG_B, 256>>>(p_h2, b1, p_cur);               // 8

    // conv2..conv4
    for (int i = 0; i < 3; i++) {
        k_tgemm<<<G2, 256, SMEM_DYN>>>(p_cur, p_wt + WM_OFF + i * HIDD * HIDD, p_h2,
                             ams + i * HIDD, amd + i * HIDD, bm,
                             NN, HIDD, HIDD, HIDD, 0);
        k_aggw<HIDD><<<AGG_B, 256>>>(p_h2, bm + i * HIDD, p_cur);
    }

    // mask MLP: m1 via GEMM (bias+tanh epilogue) into g_xn, then tail + gating
    k_tgemm<<<G1, 256, SMEM_DYN>>>(p_cur, p_wt + MW1_OFF, p_xn, a1s, a1d, mb1,
                         NN, 64, HIDD, HIDD, 1);
    k_mask2<<<(NN + 7) / 8, 256>>>(p_cur, p_xn, mw2, mb2, mw3, mb3, mw4, mb4);

    // conv5..conv7
    for (int i = 3; i < 6; i++) {
        k_tgemm<<<G2, 256, SMEM_DYN>>>(p_cur, p_wt + WM_OFF + i * HIDD * HIDD, p_h2,
                             ams + i * HIDD, amd + i * HIDD, bm,
                             NN, HIDD, HIDD, HIDD, 0);
        k_aggw<HIDD><<<AGG_B, 256>>>(p_h2, bm + i * HIDD, p_cur);
    }

    // conv8: 128 -> 42, writes final output
    k_tgemm<<<G1, 256, SMEM_DYN>>>(p_cur, p_wt + W8_OFF, p_h2, a8s, a8d, b8,
                         NN, FIN, HIDD, HIDD, 0);
    k_aggw<FIN><<<AGG_B, 256>>>(p_h2, b8, outp);
}

// round 15
// speedup vs baseline: 1.8763x; 1.0069x over previous
#include <cuda_runtime.h>
#include <cuda_fp16.h>
#include <math.h>
#include <stdint.h>

#define NN   50000
#define NE   800000
#define ET   (NE + NN)     // edges + self loops
#define FIN  42
#define KPAD 64            // conv1 K padded to 64
#define HIDD 128
#define SCB  ((NN + 255) / 256)   // 196 scan blocks

// pre-rounded (tf32) weight scratch offsets
#define W1_OFF  0
#define WM_OFF  (FIN * HIDD)                       // 5376
#define W8_OFF  (WM_OFF + 6 * HIDD * HIDD)         // 103680
#define MW1_OFF (W8_OFF + HIDD * FIN)              // 109056
#define WT_TOT  (MW1_OFF + HIDD * 64)              // 117248

// ---------------- scratch (device globals; no allocation allowed) -------------
__device__ float   g_xn [NN * KPAD];  // padded normalized input (tf32); later m1 buffer
__device__ __half2 g_h2 [NN * 64];    // GEMM output h in fp16 (max 128 cols)
__device__ float   g_cur[NN * HIDD];  // features (tf32-rounded when feeding a GEMM)
__device__ float2  g_hs2[NN];         // packed per-N-block a_s dot partials
__device__ float2  g_hd2[NN];         // packed per-N-block a_d dot partials
__device__ float   g_wt [WT_TOT];     // tf32-pre-rounded weights
__device__ int     g_deg [NN];
__device__ int     g_off [NN + 1];
__device__ int     g_fill[NN];
__device__ int     g_csr [ET];
__device__ int     g_boff[256];

__device__ __forceinline__ uint32_t f2tf(float f) {
    uint32_t u; asm("cvt.rna.tf32.f32 %0, %1;" : "=r"(u) : "f"(f)); return u;
}
__device__ __forceinline__ float rnd_tf(float f) { return __uint_as_float(f2tf(f)); }

// ---------------- L1 normalize input (tf32-rounded, zero-padded) --------------
__global__ void k_xn(const float* __restrict__ x) {
    int w = (blockIdx.x * blockDim.x + threadIdx.x) >> 5;
    int lane = threadIdx.x & 31;
    if (w >= NN) return;
    float s = 0.f;
    for (int j = lane; j < FIN; j += 32) s += fabsf(x[w * FIN + j]);
    #pragma unroll
    for (int o = 16; o; o >>= 1) s += __shfl_xor_sync(0xffffffff, s, o);
    float inv = 1.f / fmaxf(s, 1e-12f);
    for (int j = lane; j < KPAD; j += 32)
        g_xn[w * KPAD + j] = (j < FIN) ? rnd_tf(x[w * FIN + j] * inv) : 0.f;
}

// -------- pre-round all weight matrices to tf32 once per launch ----------
__global__ void k_round(const float* __restrict__ W1, const float* __restrict__ Wm,
                        const float* __restrict__ W8, const float* __restrict__ mw1)
{
    int i = blockIdx.x * blockDim.x + threadIdx.x;
    if (i >= WT_TOT) return;
    float v;
    if (i < WM_OFF)        v = W1[i];
    else if (i < W8_OFF)   v = Wm[i - WM_OFF];
    else if (i < MW1_OFF)  v = W8[i - W8_OFF];
    else                   v = mw1[i - MW1_OFF];
    g_wt[i] = rnd_tf(v);
}

// ---------------- CSR build (by destination) ----------------
__global__ void k_count(const int* __restrict__ ei) {
    int e = blockIdx.x * blockDim.x + threadIdx.x;
    if (e >= ET) return;
    int dst = (e < NE) ? ei[NE + e] : (e - NE);
    atomicAdd(&g_deg[dst], 1);
}

__global__ void k_part() {
    __shared__ int wsum[8];
    int t = threadIdx.x, b = blockIdx.x;
    int node = b * 256 + t;
    int v = (node < NN) ? g_deg[node] : 0;
    #pragma unroll
    for (int o = 16; o; o >>= 1) v += __shfl_xor_sync(0xffffffff, v, o);
    if ((t & 31) == 0) wsum[t >> 5] = v;
    __syncthreads();
    if (t == 0) {
        int s = 0;
        #pragma unroll
        for (int i = 0; i < 8; i++) s += wsum[i];
        g_boff[b] = s;
    }
}

__global__ void k_scanb() {
    __shared__ int sh[256];
    int t = threadIdx.x;
    int v = (t < SCB) ? g_boff[t] : 0;
    sh[t] = v;
    __syncthreads();
    #pragma unroll
    for (int o = 1; o < 256; o <<= 1) {
        int u = (t >= o) ? sh[t - o] : 0;
        __syncthreads();
        sh[t] += u;
        __syncthreads();
    }
    if (t < SCB) g_boff[t] = sh[t] - v;
    if (t == 255) g_off[NN] = sh[255];
}

__global__ void k_off() {
    __shared__ int sh[256];
    int t = threadIdx.x, b = blockIdx.x;
    int node = b * 256 + t;
    int d = (node < NN) ? g_deg[node] : 0;
    sh[t] = d;
    __syncthreads();
    #pragma unroll
    for (int o = 1; o < 256; o <<= 1) {
        int u = (t >= o) ? sh[t - o] : 0;
        __syncthreads();
        sh[t] += u;
        __syncthreads();
    }
    if (node < NN) {
        int off = g_boff[b] + sh[t] - d;
        g_off[node] = off;
        g_fill[node] = off;
        g_deg[node] = 0;          // reset for the next kernel_launch call
    }
}

__global__ void k_scatter(const int* __restrict__ ei) {
    int e = blockIdx.x * blockDim.x + threadIdx.x;
    if (e >= ET) return;
    int src, dst;
    if (e < NE) { src = ei[e]; dst = ei[NE + e]; }
    else        { src = e - NE; dst = e - NE; }
    int pos = atomicAdd(&g_fill[dst], 1);
    g_csr[pos] = src;
}

// -------- tf32 tensor-core GEMM, 128x64 tile, cp.async double buffer ---------
// A and B must be tf32-pre-rounded (raw bits fed to MMA).
// mode 0: C(half2) = A@B, plus fused dots into g_hs2/.g_hd2[r] component bIdx.y
// mode 1: C(float) = tanh(A@B + bias), no dots
__device__ __forceinline__ void mma_tf32(float c[4],
    uint32_t a0, uint32_t a1, uint32_t a2, uint32_t a3,
    uint32_t b0, uint32_t b1)
{
    asm volatile(
        "mma.sync.aligned.m16n8k8.row.col.f32.tf32.tf32.f32 "
        "{%0,%1,%2,%3}, {%4,%5,%6,%7}, {%8,%9}, {%0,%1,%2,%3};"
        : "+f"(c[0]), "+f"(c[1]), "+f"(c[2]), "+f"(c[3])
        : "r"(a0), "r"(a1), "r"(a2), "r"(a3), "r"(b0), "r"(b1));
}
__device__ __forceinline__ void cpa16(uint32_t d, const void* s, int sz) {
    asm volatile("cp.async.cg.shared.global [%0], [%1], 16, %2;"
                 :: "r"(d), "l"(s), "r"(sz) : "memory");
}
__device__ __forceinline__ void cpa4(uint32_t d, const void* s, int sz) {
    asm volatile("cp.async.ca.shared.global [%0], [%1], 4, %2;"
                 :: "r"(d), "l"(s), "r"(sz) : "memory");
}

#define ASTR 36
#define BSTR 72
#define ABUF (128 * ASTR)
#define BBUF (32 * BSTR)
#define SMEM_DYN (2 * (ABUF + BBUF) * 4)   // 55296 bytes

__global__ void __launch_bounds__(256, 3) k_tgemm(
    const float* __restrict__ A, const float* __restrict__ B,
    void* __restrict__ Cout,
    const float* __restrict__ as_, const float* __restrict__ ad_,
    const float* __restrict__ bias,
    int M, int N, int K, int KB, int mode)
{
    extern __shared__ __align__(16) uint32_t dynsm[];
    uint32_t* AsB = dynsm;             // [2][ABUF]
    uint32_t* BsB = dynsm + 2 * ABUF;  // [2][BBUF]
    __shared__ float sa[64], sd[64];
    int tid = threadIdx.x;
    int lane = tid & 31, wid = tid >> 5;      // warp owns rows wid*16..wid*16+15
    int q = lane >> 2, p = lane & 3;
    int row0 = blockIdx.x * 128;
    int n0 = blockIdx.y * 64;
    uint32_t asb = (uint32_t)__cvta_generic_to_shared(AsB);
    uint32_t bsb = (uint32_t)__cvta_generic_to_shared(BsB);
    if (tid < 64) {
        int c = n0 + tid;
        if (mode == 0) {
            sa[tid] = (c < N) ? as_[c] : 0.f;
            sd[tid] = (c < N) ? ad_[c] : 0.f;
        } else {
            sa[tid] = (c < N) ? bias[c] : 0.f;
        }
    }
    float acc[8][4];
    #pragma unroll
    for (int j = 0; j < 8; j++)
        #pragma unroll
        for (int r = 0; r < 4; r++) acc[j][r] = 0.f;

    const bool vecN = ((N & 3) == 0);
    const int nc = K >> 5;                    // K is 64 or 128

#define ISSUE_CHUNK(K0, BUF)                                                   \
    {                                                                          \
        int _k0 = (K0);                                                        \
        uint32_t _as = asb + (BUF) * (ABUF * 4);                               \
        uint32_t _bs = bsb + (BUF) * (BBUF * 4);                               \
        _Pragma("unroll")                                                      \
        for (int l = 0; l < 4; l++) {                                          \
            int slot = tid + l * 256;                                          \
            int r = slot >> 3, kg = slot & 7;                                  \
            int gr = row0 + r;                                                 \
            int ok = (gr < M) ? 16 : 0;                                        \
            const float* src = &A[(long)min(gr, M - 1) * K + _k0 + kg * 4];    \
            cpa16(_as + (uint32_t)(r * ASTR + kg * 4) * 4u, src, ok);          \
        }                                                                      \
        if (vecN) {                                                            \
            _Pragma("unroll")                                                  \
            for (int l = 0; l < 2; l++) {                                      \
                int slot = tid + l * 256;                                      \
                int k = slot >> 4, ng = slot & 15;                             \
                int gk = _k0 + k;                                              \
                int ok = (gk < KB) ? 16 : 0;                                   \
                const float* src = &B[(long)min(gk, KB - 1) * N + n0 + ng * 4];\
                cpa16(_bs + (uint32_t)(k * BSTR + ng * 4) * 4u, src, ok);      \
            }                                                                  \
        } else {                                                               \
            _Pragma("unroll")                                                  \
            for (int l = 0; l < 8; l++) {                                      \
                int slot = tid + l * 256;                                      \
                int k = slot >> 6, n = slot & 63;                              \
                int gk = _k0 + k;                                              \
                int ok = (gk < KB && n0 + n < N) ? 4 : 0;                      \
                const float* src = &B[(long)min(gk, KB - 1) * N + min(n0 + n, N - 1)];\
                cpa4(_bs + (uint32_t)(k * BSTR + n) * 4u, src, ok);            \
            }                                                                  \
        }                                                                      \
        asm volatile("cp.async.commit_group;" ::: "memory");                   \
    }

    ISSUE_CHUNK(0, 0);

    for (int c = 0; c < nc; c++) {
        int buf = c & 1;
        asm volatile("cp.async.wait_group 0;" ::: "memory");
        __syncthreads();                       // chunk c visible; prev buffer free
        if (c + 1 < nc) ISSUE_CHUNK((c + 1) << 5, buf ^ 1);   // overlaps MMA below
        uint32_t* As = AsB + buf * ABUF;
        uint32_t* Bs = BsB + buf * BBUF;
        #pragma unroll
        for (int ks = 0; ks < 4; ks++) {
            int kb = ks * 8;
            int r = wid * 16 + q;
            uint32_t a0 = As[r * ASTR + kb + p];
            uint32_t a1 = As[(r + 8) * ASTR + kb + p];
            uint32_t a2 = As[r * ASTR + kb + p + 4];
            uint32_t a3 = As[(r + 8) * ASTR + kb + p + 4];
            #pragma unroll
            for (int fn = 0; fn < 8; fn++) {
                int n = fn * 8 + q;
                uint32_t b0 = Bs[(kb + p) * BSTR + n];
                uint32_t b1 = Bs[(kb + p + 4) * BSTR + n];
                mma_tf32(acc[fn], a0, a1, a2, a3, b0, b1);
            }
        }
        __syncthreads();                       // all reads of buf done before reuse
    }

    if (mode == 0) {
        // ---- epilogue: store C as half2 + per-warp fused a_s/a_d row dots ----
        __half2* C2 = (__half2*)Cout;
        float* hs2f = (float*)g_hs2;
        float* hd2f = (float*)g_hd2;
        #pragma unroll
        for (int ro = 0; ro < 2; ro++) {
            int rl = wid * 16 + q + ro * 8;
            int r = row0 + rl;
            float s = 0.f, d = 0.f;
            #pragma unroll
            for (int fn = 0; fn < 8; fn++) {
                int cl = fn * 8 + p * 2;
                float v0 = acc[fn][ro * 2 + 0];
                float v1 = acc[fn][ro * 2 + 1];
                s += v0 * sa[cl] + v1 * sa[cl + 1];
                d += v0 * sd[cl] + v1 * sd[cl + 1];
                int c = n0 + cl;
                if (r < M && c + 1 < N)
                    C2[((long)r * N + c) >> 1] = __floats2half2_rn(v0, v1);
            }
            s += __shfl_xor_sync(0xffffffff, s, 1);
            s += __shfl_xor_sync(0xffffffff, s, 2);
            d += __shfl_xor_sync(0xffffffff, d, 1);
            d += __shfl_xor_sync(0xffffffff, d, 2);
            if (p == 0 && r < M) {
                hs2f[r * 2 + blockIdx.y] = s;   // packed: .x = block 0, .y = block 1
                hd2f[r * 2 + blockIdx.y] = d;
            }
        }
    } else {
        // ---- epilogue: C(float) = tanh(acc + bias) ----
        float* Cf = (float*)Cout;
        #pragma unroll
        for (int ro = 0; ro < 2; ro++) {
            int rl = wid * 16 + q + ro * 8;
            int r = row0 + rl;
            if (r >= M) continue;
            #pragma unroll
            for (int fn = 0; fn < 8; fn++) {
                int cl = fn * 8 + p * 2;
                int c = n0 + cl;
                float v0 = tanhf(acc[fn][ro * 2 + 0] + sa[cl]);
                float v1 = tanhf(acc[fn][ro * 2 + 1] + sa[cl + 1]);
                if (c + 1 < N) *(float2*)&Cf[(long)r * N + c] = make_float2(v0, v1);
                else if (c < N) Cf[(long)r * N + c] = v0;
            }
        }
    }
#undef ISSUE_CHUNK
}

// -------- warp-per-node softmax aggregation: SINGLE PASS (no max-sub) --------
// RND: tf32-round outputs (when they feed the next layer's GEMM).
template<int F, bool RND>
__global__ void __launch_bounds__(256) k_aggw(
    const __half2* __restrict__ h2, const float* __restrict__ bias,
    float* __restrict__ out)
{
    constexpr bool TWO = (F == 128);
    constexpr int RSTR = F / 2;               // half2 per row
    int w = (blockIdx.x * blockDim.x + threadIdx.x) >> 5;
    int lane = threadIdx.x & 31;
    if (w >= NN) return;
    int beg = g_off[w], end = g_off[w + 1];
    int deg = end - beg;
    int nk = (deg + 31) >> 5;
    float2 hdp = g_hd2[w];
    float hdv = TWO ? (hdp.x + hdp.y) : hdp.x;

    float myS = 0.f;

    if constexpr (F == 128) {
        float4 acc = make_float4(0.f, 0.f, 0.f, 0.f);
        for (int c = 0; c < nk; c++) {
            int i = (c << 5) + lane;
            int s = 0; float wgt = 0.f;
            if (i < deg) {
                s = g_csr[beg + i];
                float2 hv = g_hs2[s];          // single 8B random load
                float z = hv.x + hv.y + hdv;
                float e = (z > 0.f) ? z : 0.2f * z;
                wgt = __expf(e);
            }
            myS += wgt;
            int cnt = min(32, deg - (c << 5));
            int k = 0;
            for (; k + 4 <= cnt; k += 4) {
                int   s0 = __shfl_sync(0xffffffff, s, k);
                int   s1 = __shfl_sync(0xffffffff, s, k + 1);
                int   s2 = __shfl_sync(0xffffffff, s, k + 2);
                int   s3 = __shfl_sync(0xffffffff, s, k + 3);
                float w0 = __shfl_sync(0xffffffff, wgt, k);
                float w1 = __shfl_sync(0xffffffff, wgt, k + 1);
                float w2 = __shfl_sync(0xffffffff, wgt, k + 2);
                float w3 = __shfl_sync(0xffffffff, wgt, k + 3);
                uint2 u0 = ((const uint2*)(h2 + (long)s0 * RSTR))[lane];
                uint2 u1 = ((const uint2*)(h2 + (long)s1 * RSTR))[lane];
                uint2 u2 = ((const uint2*)(h2 + (long)s2 * RSTR))[lane];
                uint2 u3 = ((const uint2*)(h2 + (long)s3 * RSTR))[lane];
                float2 a0 = __half22float2(*(__half2*)&u0.x);
                float2 b0 = __half22float2(*(__half2*)&u0.y);
                float2 a1 = __half22float2(*(__half2*)&u1.x);
                float2 b1 = __half22float2(*(__half2*)&u1.y);
                float2 a2 = __half22float2(*(__half2*)&u2.x);
                float2 b2 = __half22float2(*(__half2*)&u2.y);
                float2 a3 = __half22float2(*(__half2*)&u3.x);
                float2 b3 = __half22float2(*(__half2*)&u3.y);
                acc.x += w0 * a0.x + w1 * a1.x + w2 * a2.x + w3 * a3.x;
                acc.y += w0 * a0.y + w1 * a1.y + w2 * a2.y + w3 * a3.y;
                acc.z += w0 * b0.x + w1 * b1.x + w2 * b2.x + w3 * b3.x;
                acc.w += w0 * b0.y + w1 * b1.y + w2 * b2.y + w3 * b3.y;
            }
            for (; k < cnt; k++) {
                int   sk = __shfl_sync(0xffffffff, s, k);
                float wk = __shfl_sync(0xffffffff, wgt, k);
                uint2 u = ((const uint2*)(h2 + (long)sk * RSTR))[lane];
                float2 a = __half22float2(*(__half2*)&u.x);
                float2 b = __half22float2(*(__half2*)&u.y);
                acc.x += wk * a.x; acc.y += wk * a.y;
                acc.z += wk * b.x; acc.w += wk * b.y;
            }
        }
        #pragma unroll
        for (int o = 16; o; o >>= 1) myS += __shfl_xor_sync(0xffffffff, myS, o);
        float invS = 1.f / (myS + 1e-16f);
        const float4* b4 = (const float4*)bias;
        float4 bb = b4[lane];
        float4 o;
        o.x = tanhf(acc.x * invS + bb.x);
        o.y = tanhf(acc.y * invS + bb.y);
        o.z = tanhf(acc.z * invS + bb.z);
        o.w = tanhf(acc.w * invS + bb.w);
        if (RND) {
            o.x = rnd_tf(o.x); o.y = rnd_tf(o.y);
            o.z = rnd_tf(o.z); o.w = rnd_tf(o.w);
        }
        ((float4*)out)[w * 32 + lane] = o;
    } else {
        float a0 = 0.f, a1 = 0.f;
        int j0 = lane, j1 = lane + 32;
        for (int c = 0; c < nk; c++) {
            int i = (c << 5) + lane;
            int s = 0; float wgt = 0.f;
            if (i < deg) {
                s = g_csr[beg + i];
                float z = g_hs2[s].x + hdv;
                float e = (z > 0.f) ? z : 0.2f * z;
                wgt = __expf(e);
            }
            myS += wgt;
            int cnt = min(32, deg - (c << 5));
            for (int k = 0; k < cnt; k++) {
                int   sk = __shfl_sync(0xffffffff, s, k);
                float wk = __shfl_sync(0xffffffff, wgt, k);
                const __half* row = (const __half*)(h2 + (long)sk * RSTR);
                a0 += wk * __half2float(row[j0]);
                if (j1 < F) a1 += wk * __half2float(row[j1]);
            }
        }
        #pragma unroll
        for (int o = 16; o; o >>= 1) myS += __shfl_xor_sync(0xffffffff, myS, o);
        float invS = 1.f / (myS + 1e-16f);
        out[(long)w * F + j0] = tanhf(a0 * invS + bias[j0]);
        if (j1 < F) out[(long)w * F + j1] = tanhf(a1 * invS + bias[j1]);
    }
}

// -------- mask MLP tail (m2..m4) + soft-argmax gating, warp per node ---------
// m1 = tanh(latent @ mw1 + mb1) precomputed by k_tgemm mode 1 into g_xn.
// Gated output is tf32-re-rounded (feeds conv5's GEMM).
__global__ void __launch_bounds__(256) k_mask2(
    float* __restrict__ cur, const float* __restrict__ m1,
    const float* __restrict__ mw2, const float* __restrict__ mb2,
    const float* __restrict__ mw3, const float* __restrict__ mb3,
    const float* __restrict__ mw4, const float* __restrict__ mb4)
{
    __shared__ float w2[64 * 16];
    __shared__ float w3[16 * 16];
    __shared__ float w4[32];
    __shared__ float bb2[16], bb3[16], bb4[2];
    int t = threadIdx.x;
    for (int i = t; i < 64 * 16; i += 256) w2[i] = mw2[i];
    if (t < 256 && t < 16 * 16) w3[t] = mw3[t];
    if (t < 32) w4[t] = mw4[t];
    if (t < 16) { bb2[t] = mb2[t]; bb3[t] = mb3[t]; }
    if (t < 2)  bb4[t] = mb4[t];
    __syncthreads();

    int n = blockIdx.x * 8 + (t >> 5);
    int lane = t & 31;
    if (n >= NN) return;

    float a0 = m1[(long)n * 64 + lane];
    float a1 = m1[(long)n * 64 + lane + 32];

    int l16 = lane & 15;
    float s2 = bb2[l16];
    #pragma unroll
    for (int k = 0; k < 32; k++)
        s2 += __shfl_sync(0xffffffff, a0, k) * w2[k * 16 + l16];
    #pragma unroll
    for (int k = 0; k < 32; k++)
        s2 += __shfl_sync(0xffffffff, a1, k) * w2[(k + 32) * 16 + l16];
    s2 = tanhf(s2);

    float s3 = bb3[l16];
    #pragma unroll
    for (int k = 0; k < 16; k++)
        s3 += __shfl_sync(0xffffffff, s2, k) * w3[k * 16 + l16];
    s3 = tanhf(s3);

    int l2 = lane & 1;
    float o = bb4[l2];
    #pragma unroll
    for (int k = 0; k < 16; k++)
        o += __shfl_sync(0xffffffff, s3, k) * w4[k * 2 + l2];
    float o0 = __shfl_sync(0xffffffff, o, 0);
    float o1 = __shfl_sync(0xffffffff, o, 1);
    float mx = fmaxf(o0, o1);
    float e0 = expf(o0 - mx), e1 = expf(o1 - mx);
    float sa = e1 / (e0 + e1);

    float4* c4 = (float4*)&cur[(long)n * 128];
    float4 v = c4[lane];
    v.x = rnd_tf(v.x * sa); v.y = rnd_tf(v.y * sa);
    v.z = rnd_tf(v.z * sa); v.w = rnd_tf(v.w * sa);
    c4[lane] = v;
}

// ---------------- orchestration ----------------
extern "C" void kernel_launch(void* const* d_in, const int* in_sizes, int n_in,
                              void* d_out, int out_size)
{
    const float* x   = (const float*)d_in[0];
    const int*   ei  = (const int*)  d_in[1];
    const float* W1  = (const float*)d_in[4];
    const float* a1s = (const float*)d_in[5];
    const float* a1d = (const float*)d_in[6];
    const float* b1  = (const float*)d_in[7];
    const float* Wm  = (const float*)d_in[8];
    const float* ams = (const float*)d_in[9];
    const float* amd = (const float*)d_in[10];
    const float* bm  = (const float*)d_in[11];
    const float* W8  = (const float*)d_in[12];
    const float* a8s = (const float*)d_in[13];
    const float* a8d = (const float*)d_in[14];
    const float* b8  = (const float*)d_in[15];
    const float* mw1 = (const float*)d_in[16];
    const float* mb1 = (const float*)d_in[17];
    const float* mw2 = (const float*)d_in[18];
    const float* mb2 = (const float*)d_in[19];
    const float* mw3 = (const float*)d_in[20];
    const float* mb3 = (const float*)d_in[21];
    const float* mw4 = (const float*)d_in[22];
    const float* mb4 = (const float*)d_in[23];
    float* outp = (float*)d_out;

    void *pv;
    cudaGetSymbolAddress(&pv, g_xn);   float*   p_xn  = (float*)pv;
    cudaGetSymbolAddress(&pv, g_h2);   __half2* p_h2  = (__half2*)pv;
    cudaGetSymbolAddress(&pv, g_cur);  float*   p_cur = (float*)pv;
    cudaGetSymbolAddress(&pv, g_wt);   float*   p_wt  = (float*)pv;

    cudaFuncSetAttribute(k_tgemm, cudaFuncAttributeMaxDynamicSharedMemorySize, SMEM_DYN);

    const int EB = (ET + 255) / 256;
    const int GEMM_B = (NN + 127) / 128;       // 391
    const dim3 G2(GEMM_B, 2);                  // N=128 layers
    const dim3 G1(GEMM_B, 1);                  // N<=64 layers
    const int WARP8  = (NN + 7) / 8;
    const int AGG_B  = (NN * 32 + 255) / 256;  // 6250

    // launch order keeps conv1's k_tgemm at index 3 (ncu capture slot)
    k_xn<<<WARP8, 256>>>(x);                                     // 0
    k_count<<<EB, 256>>>(ei);                                    // 1
    k_round<<<(WT_TOT + 255) / 256, 256>>>(W1, Wm, W8, mw1);     // 2
    k_tgemm<<<G2, 256, SMEM_DYN>>>(p_xn, p_wt + W1_OFF, p_h2, a1s, a1d, b1,
                         NN, HIDD, KPAD, FIN, 0);                // 3  <-- profiled
    k_part<<<SCB, 256>>>();                                      // 4
    k_scanb<<<1, 256>>>();                                       // 5
    k_off<<<SCB, 256>>>();                                       // 6
    k_scatter<<<EB, 256>>>(ei);                                  // 7
    k_aggw<HIDD, true><<<AGG_B, 256>>>(p_h2, b1, p_cur);         // 8

    // conv2..conv4
    for (int i = 0; i < 3; i++) {
        k_tgemm<<<G2, 256, SMEM_DYN>>>(p_cur, p_wt + WM_OFF + i * HIDD * HIDD, p_h2,
                             ams + i * HIDD, amd + i * HIDD, bm,
                             NN, HIDD, HIDD, HIDD, 0);
        k_aggw<HIDD, true><<<AGG_B, 256>>>(p_h2, bm + i * HIDD, p_cur);
    }

    // mask MLP: m1 via GEMM (bias+tanh epilogue) into g_xn, then tail + gating
    k_tgemm<<<G1, 256, SMEM_DYN>>>(p_cur, p_wt + MW1_OFF, p_xn, a1s, a1d, mb1,
                         NN, 64, HIDD, HIDD, 1);
    k_mask2<<<(NN + 7) / 8, 256>>>(p_cur, p_xn, mw2, mb2, mw3, mb3, mw4, mb4);

    // conv5..conv7
    for (int i = 3; i < 6; i++) {
        k_tgemm<<<G2, 256, SMEM_DYN>>>(p_cur, p_wt + WM_OFF + i * HIDD * HIDD, p_h2,
                             ams + i * HIDD, amd + i * HIDD, bm,
                             NN, HIDD, HIDD, HIDD, 0);
        k_aggw<HIDD, true><<<AGG_B, 256>>>(p_h2, bm + i * HIDD, p_cur);
    }

    // conv8: 128 -> 42, writes final output (no rounding)
    k_tgemm<<<G1, 256, SMEM_DYN>>>(p_cur, p_wt + W8_OFF, p_h2, a8s, a8d, b8,
                         NN, FIN, HIDD, HIDD, 0);
    k_aggw<FIN, false><<<AGG_B, 256>>>(p_h2, b8, outp);
}